// round 4
// baseline (speedup 1.0000x reference)
#include <cuda_runtime.h>
#include <cuda_fp16.h>
#include <math.h>
#include <stdint.h>

// Problem constants: B=8, n=1024, dQ=dV=512, H=8, d=64, HB=64
#define NSEQ   1024
#define DHEAD  64
#define DVTOT  512
#define NBATCH 8
#define NHB    64

#define SSCALE 0.044194173824159216f   // 1/sqrt(512)
#define LOGMU  (-6.9314615657f)        // log(1/1024 + 1e-8)

// Scratch (device globals; no allocation allowed)
__device__ float  g_Qh [NHB * NSEQ * DHEAD];   // head-major Q_ fp32 (residual)
__device__ __half g_Qh16[NHB * NSEQ * DHEAD];  // head-major Q_ fp16 (mma operand)
__device__ float  g_Oh [NHB * NSEQ * DHEAD];   // head-major O_
__device__ float  g_u  [NHB * NSEQ];
__device__ float  g_v  [NHB * NSEQ];
__device__ float  g_X  [NBATCH * NSEQ * DVTOT];
__device__ float  g_T  [NBATCH * NSEQ * DVTOT];
// P = exp(S/sqrt(512)) stored fp16 in mma-A-fragment order:
// tile(bh, iblk, jt) of 128x128, within tile uint4 index
// ((((mw*2+w2)*2+mt)*4+ntp)*32)+lane, frag = {a0,a1,a2,a3} half2s.
__device__ __align__(16) __half g_P[(size_t)NHB * NSEQ * NSEQ];

// ---------------------------------------------------------------------------
// helpers
// ---------------------------------------------------------------------------
__device__ __forceinline__ void mma16h(float* c, const unsigned* a, const unsigned* b) {
    asm volatile(
        "mma.sync.aligned.m16n8k16.row.col.f32.f16.f16.f32 "
        "{%0,%1,%2,%3},{%4,%5,%6,%7},{%8,%9},{%0,%1,%2,%3};\n"
        : "+f"(c[0]), "+f"(c[1]), "+f"(c[2]), "+f"(c[3])
        : "r"(a[0]), "r"(a[1]), "r"(a[2]), "r"(a[3]), "r"(b[0]), "r"(b[1]));
}
__device__ __forceinline__ unsigned smaddr(const void* p) {
    return (unsigned)__cvta_generic_to_shared(p);
}
__device__ __forceinline__ void ldm_x4(unsigned* r, unsigned a) {
    asm volatile("ldmatrix.sync.aligned.m8n8.x4.shared.b16 {%0,%1,%2,%3},[%4];"
                 : "=r"(r[0]), "=r"(r[1]), "=r"(r[2]), "=r"(r[3]) : "r"(a));
}
__device__ __forceinline__ void ldm_x2(unsigned* r, unsigned a) {
    asm volatile("ldmatrix.sync.aligned.m8n8.x2.shared.b16 {%0,%1},[%2];"
                 : "=r"(r[0]), "=r"(r[1]) : "r"(a));
}
__device__ __forceinline__ void ldm_x2t(unsigned* r, unsigned a) {
    asm volatile("ldmatrix.sync.aligned.m8n8.x2.trans.shared.b16 {%0,%1},[%2];"
                 : "=r"(r[0]), "=r"(r[1]) : "r"(a));
}
__device__ __forceinline__ unsigned fh2(float a, float b) {
    __half2 h = __floats2half2_rn(a, b);
    return *(unsigned*)&h;
}
__device__ __forceinline__ unsigned umul2(unsigned a, unsigned b) {
    __half2 r = __hmul2(*(const __half2*)&a, *(const __half2*)&b);
    return *(unsigned*)&r;
}
__device__ __forceinline__ float h2lo(unsigned a) { return __low2float(*(const __half2*)&a); }
__device__ __forceinline__ float h2hi(unsigned a) { return __high2float(*(const __half2*)&a); }

// ---------------------------------------------------------------------------
// Pass 1: S = Qi Qj^T / sqrt(512) via fp16 mma; P = exp(S) -> g_P (frag order);
//         u_i = LOGMU - log(row-sum of P). grid (8 iblk, 64 bh), 256 thr.
// warps 4(m) x 2(j): warp tile 32 x 64.
// ---------------------------------------------------------------------------
__global__ void __launch_bounds__(256, 2) sink_p1() {
    __shared__ __align__(16) __half Qi[128 * 72];
    __shared__ __align__(16) __half Qj[128 * 72];
    __shared__ float ps[256];

    const int bh = blockIdx.y, iblk = blockIdx.x, i0 = iblk * 128;
    const int tid = threadIdx.x, lane = tid & 31, w = tid >> 5;
    const int mw = w & 3, w2 = w >> 2;
    const int wm = mw * 32, wn = w2 * 64;
    const __half* Qb = g_Qh16 + (size_t)bh * (NSEQ * DHEAD);

#pragma unroll
    for (int r = 0; r < 4; r++) {
        int idx = tid + r * 256;
        int row = idx >> 3, q = (idx & 7) * 8;
        *(float4*)(Qi + row * 72 + q) =
            *(const float4*)(Qb + (size_t)(i0 + row) * DHEAD + q);
    }
    __syncthreads();

    // hoist A fragments (invariant across j-tiles)
    unsigned af[2][4][4];
#pragma unroll
    for (int mt = 0; mt < 2; mt++)
#pragma unroll
        for (int kk = 0; kk < 4; kk++)
            ldm_x4(af[mt][kk],
                   smaddr(Qi + (wm + mt * 16 + (lane & 15)) * 72 + kk * 16 + (lane >> 4) * 8));

    float ls[2][2] = {{0.f, 0.f}, {0.f, 0.f}};

    for (int jt = 0; jt < 8; jt++) {
        __syncthreads();
#pragma unroll
        for (int r = 0; r < 4; r++) {
            int idx = tid + r * 256;
            int row = idx >> 3, q = (idx & 7) * 8;
            *(float4*)(Qj + row * 72 + q) =
                *(const float4*)(Qb + (size_t)(jt * 128 + row) * DHEAD + q);
        }
        __syncthreads();

        float sa[2][8][4];
#pragma unroll
        for (int a = 0; a < 2; a++)
#pragma unroll
            for (int b = 0; b < 8; b++)
#pragma unroll
                for (int c = 0; c < 4; c++) sa[a][b][c] = 0.f;

#pragma unroll
        for (int kk = 0; kk < 4; kk++) {
#pragma unroll
            for (int nt = 0; nt < 8; nt++) {
                unsigned bf[2];
                ldm_x2(bf, smaddr(Qj + (wn + nt * 8 + (lane & 7)) * 72 +
                                  kk * 16 + ((lane >> 3) & 1) * 8));
                mma16h(sa[0][nt], af[0][kk], bf);
                mma16h(sa[1][nt], af[1][kk], bf);
            }
        }

        // exp, row-sum, and store P in fragment order (coalesced 16B/lane)
        uint4* T = (uint4*)(g_P + ((((size_t)bh * 8 + iblk) * 8 + jt) << 14));
#pragma unroll
        for (int mt = 0; mt < 2; mt++)
#pragma unroll
            for (int ntp = 0; ntp < 4; ntp++) {
                float p00 = __expf(sa[mt][2 * ntp][0] * SSCALE);
                float p01 = __expf(sa[mt][2 * ntp][1] * SSCALE);
                float p02 = __expf(sa[mt][2 * ntp][2] * SSCALE);
                float p03 = __expf(sa[mt][2 * ntp][3] * SSCALE);
                float p10 = __expf(sa[mt][2 * ntp + 1][0] * SSCALE);
                float p11 = __expf(sa[mt][2 * ntp + 1][1] * SSCALE);
                float p12 = __expf(sa[mt][2 * ntp + 1][2] * SSCALE);
                float p13 = __expf(sa[mt][2 * ntp + 1][3] * SSCALE);
                ls[mt][0] += p00 + p01 + p10 + p11;   // row r
                ls[mt][1] += p02 + p03 + p12 + p13;   // row r+8
                uint4 fr;
                fr.x = fh2(p00, p01);   // a0: (r,   k0,k0+1)
                fr.y = fh2(p02, p03);   // a1: (r+8, k0,k0+1)
                fr.z = fh2(p10, p11);   // a2: (r,   k0+8,k0+9)
                fr.w = fh2(p12, p13);   // a3: (r+8, k0+8,k0+9)
                T[((((mw * 2 + w2) * 2 + mt) * 4 + ntp) * 32) + lane] = fr;
            }
    }

    // reduce row sums: 4 lanes share a row, then 2 column-warps via smem
#pragma unroll
    for (int mt = 0; mt < 2; mt++)
#pragma unroll
        for (int h = 0; h < 2; h++) {
            float v = ls[mt][h];
            v += __shfl_xor_sync(0xffffffffu, v, 1);
            v += __shfl_xor_sync(0xffffffffu, v, 2);
            if ((lane & 3) == 0)
                ps[w2 * 128 + wm + mt * 16 + (lane >> 2) + h * 8] = v;
        }
    __syncthreads();
    if (tid < 128) {
        float s = ps[tid] + ps[128 + tid];
        g_u[bh * NSEQ + i0 + tid] = LOGMU - __logf(s);
    }
}

// ---------------------------------------------------------------------------
// Pass 2: v_j = LOGMU - log(sum_i e^{u_i} P_ij). Pure streaming over g_P.
// grid (8 jt, 64 bh), 256 threads; warp w: w2=w>>2, ntp=w&3 -> fixed j-set.
// ---------------------------------------------------------------------------
__global__ void __launch_bounds__(256) sink_p2() {
    __shared__ float eu[1024];
    __shared__ float vacc[128];
    const int bh = blockIdx.y, jt = blockIdx.x;
    const int tid = threadIdx.x, lane = tid & 31, w = tid >> 5;
    const int w2 = w >> 2, ntp = w & 3;

#pragma unroll
    for (int k = 0; k < 4; k++) {
        int i = tid + k * 256;
        eu[i] = __expf(g_u[bh * NSEQ + i]);
    }
    __syncthreads();

    float b0 = 0.f, b1 = 0.f, b2 = 0.f, b3 = 0.f;
    for (int iblk = 0; iblk < 8; iblk++) {
        const uint4* T = (const uint4*)g_P + (((size_t)bh * 8 + iblk) * 8 + jt) * 2048;
        const int ib = iblk * 128 + (lane >> 2);
#pragma unroll
        for (int mw = 0; mw < 4; mw++)
#pragma unroll
            for (int mt = 0; mt < 2; mt++) {
                uint4 fr = T[((((mw * 2 + w2) * 2 + mt) * 4 + ntp) * 32) + lane];
                float e0 = eu[ib + mw * 32 + mt * 16];
                float e1 = eu[ib + mw * 32 + mt * 16 + 8];
                b0 += e0 * h2lo(fr.x) + e1 * h2lo(fr.y);
                b1 += e0 * h2hi(fr.x) + e1 * h2hi(fr.y);
                b2 += e0 * h2lo(fr.z) + e1 * h2lo(fr.w);
                b3 += e0 * h2hi(fr.z) + e1 * h2hi(fr.w);
            }
    }
#pragma unroll
    for (int off = 4; off <= 16; off <<= 1) {
        b0 += __shfl_xor_sync(0xffffffffu, b0, off);
        b1 += __shfl_xor_sync(0xffffffffu, b1, off);
        b2 += __shfl_xor_sync(0xffffffffu, b2, off);
        b3 += __shfl_xor_sync(0xffffffffu, b3, off);
    }
    if (lane < 4) {
        int jl = w2 * 64 + ntp * 16 + 2 * lane;
        vacc[jl] = b0; vacc[jl + 1] = b1; vacc[jl + 8] = b2; vacc[jl + 9] = b3;
    }
    __syncthreads();
    if (tid < 128)
        g_v[bh * NSEQ + jt * 128 + tid] = LOGMU - __logf(vacc[tid]);
}

// ---------------------------------------------------------------------------
// Pass 3: O_ = Q_ + (1024 e^u P e^v) @ Q_. A-frags straight from g_P (16B LDG),
// scaled by half2 muls; B via ldmatrix.trans from Qj smem.
// grid (8 iblk, 64 bh), 256 thr, warps 4(m) x 2(d-half).
// ---------------------------------------------------------------------------
__global__ void __launch_bounds__(256) sink_p3() {
    __shared__ __align__(16) __half Qj[128 * 72];
    __shared__ unsigned svh[64];   // half2 pairs e^{v_{2c}}, e^{v_{2c+1}}

    const int bh = blockIdx.y, iblk = blockIdx.x, i0 = iblk * 128;
    const int tid = threadIdx.x, lane = tid & 31, w = tid >> 5;
    const int mw = w & 3, wg = w >> 2;
    const int wm = mw * 32, wn2 = wg * 32;
    const __half* Qb = g_Qh16 + (size_t)bh * (NSEQ * DHEAD);

    // per-thread row scales su = 1024 * e^{u_i} (rows wm+mt*16+(lane>>2)+{0,8})
    unsigned suh[2][2];
#pragma unroll
    for (int mt = 0; mt < 2; mt++)
#pragma unroll
        for (int s = 0; s < 2; s++) {
            float su = 1024.f * __expf(g_u[bh * NSEQ + i0 + wm + mt * 16 + (lane >> 2) + s * 8]);
            suh[mt][s] = fh2(su, su);
        }

    float oa[2][4][4];
#pragma unroll
    for (int a = 0; a < 2; a++)
#pragma unroll
        for (int b = 0; b < 4; b++)
#pragma unroll
            for (int c = 0; c < 4; c++) oa[a][b][c] = 0.f;

    for (int jt = 0; jt < 8; jt++) {
        __syncthreads();
#pragma unroll
        for (int r = 0; r < 4; r++) {
            int idx = tid + r * 256;
            int row = idx >> 3, q = (idx & 7) * 8;
            *(float4*)(Qj + row * 72 + q) =
                *(const float4*)(Qb + (size_t)(jt * 128 + row) * DHEAD + q);
        }
        if (tid < 64) {
            int j = bh * NSEQ + jt * 128 + 2 * tid;
            svh[tid] = fh2(__expf(g_v[j]), __expf(g_v[j + 1]));
        }
        __syncthreads();

        const uint4* T = (const uint4*)g_P + (((size_t)bh * 8 + iblk) * 8 + jt) * 2048;
#pragma unroll
        for (int kk = 0; kk < 8; kk++) {
            const int w2k = kk >> 2, ntpk = kk & 3;
            uint4 f0 = T[((((mw * 2 + w2k) * 2 + 0) * 4 + ntpk) * 32) + lane];
            uint4 f1 = T[((((mw * 2 + w2k) * 2 + 1) * 4 + ntpk) * 32) + lane];
            unsigned svA = svh[8 * kk + (lane & 3)];
            unsigned svB = svh[8 * kk + (lane & 3) + 4];
            unsigned a0[4], a1[4];
            a0[0] = umul2(umul2(f0.x, suh[0][0]), svA);
            a0[1] = umul2(umul2(f0.y, suh[0][1]), svA);
            a0[2] = umul2(umul2(f0.z, suh[0][0]), svB);
            a0[3] = umul2(umul2(f0.w, suh[0][1]), svB);
            a1[0] = umul2(umul2(f1.x, suh[1][0]), svA);
            a1[1] = umul2(umul2(f1.y, suh[1][1]), svA);
            a1[2] = umul2(umul2(f1.z, suh[1][0]), svB);
            a1[3] = umul2(umul2(f1.w, suh[1][1]), svB);
#pragma unroll
            for (int nt = 0; nt < 4; nt++) {
                unsigned bf[2];
                ldm_x2t(bf, smaddr(Qj + (16 * kk + (lane & 15)) * 72 + wn2 + nt * 8));
                mma16h(oa[0][nt], a0, bf);
                mma16h(oa[1][nt], a1, bf);
            }
        }
    }

    const float* Qf = g_Qh + (size_t)bh * (NSEQ * DHEAD);
    float* Ob = g_Oh + (size_t)bh * (NSEQ * DHEAD);
#pragma unroll
    for (int mt = 0; mt < 2; mt++)
#pragma unroll
        for (int nt = 0; nt < 4; nt++)
#pragma unroll
            for (int rg = 0; rg < 4; rg++) {
                int row = i0 + wm + mt * 16 + (lane >> 2) + ((rg & 2) ? 8 : 0);
                int col = wn2 + nt * 8 + 2 * (lane & 3) + (rg & 1);
                Ob[(size_t)row * DHEAD + col] =
                    oa[mt][nt][rg] + Qf[(size_t)row * DHEAD + col];
            }
}

// ---------------------------------------------------------------------------
// fp16 GEMM: C[8192,512] = A[8192,512] * W[512,512]^T (+bias, epilogues)
// MODE 0: A = Q input; scatter head-major into g_Qh (fp32) + g_Qh16 (fp16)
// MODE 1: A = g_X;  g_T = g_X + relu(C + bias)
// tile 128x128, BK=32, warps 4(m) x 2(n)
// ---------------------------------------------------------------------------
template <int MODE>
__global__ void __launch_bounds__(256, 2) gemm512h(const float* __restrict__ Ain,
                                                   const float* __restrict__ W,
                                                   const float* __restrict__ bias) {
    __shared__ __align__(16) __half As[128 * 40];
    __shared__ __align__(16) __half Bs[128 * 40];
    const float* A = (MODE == 0) ? Ain : (const float*)g_X;

    const int m0 = blockIdx.y * 128, n0 = blockIdx.x * 128;
    const int tid = threadIdx.x, lane = tid & 31, w = tid >> 5;
    const int wm = (w & 3) * 32, wn = (w >> 2) * 64;

    float acc[2][8][4];
#pragma unroll
    for (int a = 0; a < 2; a++)
#pragma unroll
        for (int b = 0; b < 8; b++)
#pragma unroll
            for (int c = 0; c < 4; c++) acc[a][b][c] = 0.f;

    for (int k0 = 0; k0 < 512; k0 += 32) {
        __syncthreads();
#pragma unroll
        for (int c = 0; c < 2; c++) {
            int idx = tid + c * 256;
            int row = idx >> 2, q = (idx & 3) * 8;
            float4 v0 = *(const float4*)(A + (size_t)(m0 + row) * 512 + k0 + q);
            float4 v1 = *(const float4*)(A + (size_t)(m0 + row) * 512 + k0 + q + 4);
            uint4 pa;
            pa.x = fh2(v0.x, v0.y); pa.y = fh2(v0.z, v0.w);
            pa.z = fh2(v1.x, v1.y); pa.w = fh2(v1.z, v1.w);
            *(uint4*)(As + row * 40 + q) = pa;
            float4 w0 = *(const float4*)(W + (size_t)(n0 + row) * 512 + k0 + q);
            float4 w1 = *(const float4*)(W + (size_t)(n0 + row) * 512 + k0 + q + 4);
            uint4 pb;
            pb.x = fh2(w0.x, w0.y); pb.y = fh2(w0.z, w0.w);
            pb.z = fh2(w1.x, w1.y); pb.w = fh2(w1.z, w1.w);
            *(uint4*)(Bs + row * 40 + q) = pb;
        }
        __syncthreads();
#pragma unroll
        for (int kk = 0; kk < 2; kk++) {
            unsigned af[2][4];
#pragma unroll
            for (int mt = 0; mt < 2; mt++)
                ldm_x4(af[mt], smaddr(As + (wm + mt * 16 + (lane & 15)) * 40 +
                                      kk * 16 + (lane >> 4) * 8));
#pragma unroll
            for (int nt = 0; nt < 8; nt++) {
                unsigned bf[2];
                ldm_x2(bf, smaddr(Bs + (wn + nt * 8 + (lane & 7)) * 40 +
                                  kk * 16 + ((lane >> 3) & 1) * 8));
                mma16h(acc[0][nt], af[0], bf);
                mma16h(acc[1][nt], af[1], bf);
            }
        }
    }

#pragma unroll
    for (int mt = 0; mt < 2; mt++)
#pragma unroll
        for (int nt = 0; nt < 8; nt++)
#pragma unroll
            for (int rg = 0; rg < 4; rg++) {
                int row = m0 + wm + mt * 16 + (lane >> 2) + ((rg & 2) ? 8 : 0);
                int col = n0 + wn + nt * 8 + 2 * (lane & 3) + (rg & 1);
                float v = acc[mt][nt][rg] + bias[col];
                if (MODE == 0) {
                    int b = row >> 10, i = row & 1023;
                    int h = col >> 6, dc = col & 63;
                    size_t idx = ((size_t)((h << 3) + b) * NSEQ + i) * DHEAD + dc;
                    g_Qh[idx] = v;
                    g_Qh16[idx] = __float2half_rn(v);
                } else {
                    v = fmaxf(v, 0.f) + A[(size_t)row * 512 + col];
                    g_T[(size_t)row * 512 + col] = v;
                }
            }
}

// ---------------------------------------------------------------------------
// LayerNorm. mode 0: merge heads g_Oh -> LN -> g_X ; mode 1: g_T -> LN -> out
// ---------------------------------------------------------------------------
__global__ void __launch_bounds__(512) ln_kernel(const float* __restrict__ gg,
                                                 const float* __restrict__ bb,
                                                 float* __restrict__ out, int mode) {
    int m = blockIdx.x;
    int t = threadIdx.x;
    float val;
    if (mode == 0) {
        int b = m >> 10, i = m & 1023, h = t >> 6, dc = t & 63;
        val = g_Oh[(((h << 3) + b) * NSEQ + i) * DHEAD + dc];
    } else {
        val = g_T[(size_t)m * 512 + t];
    }
    float s = val, q = val * val;
#pragma unroll
    for (int off = 16; off; off >>= 1) {
        s += __shfl_xor_sync(0xffffffffu, s, off);
        q += __shfl_xor_sync(0xffffffffu, q, off);
    }
    __shared__ float ss[16], sq[16];
    int w = t >> 5, lane = t & 31;
    if (!lane) { ss[w] = s; sq[w] = q; }
    __syncthreads();
    float S = 0.f, Q2 = 0.f;
#pragma unroll
    for (int k = 0; k < 16; k++) { S += ss[k]; Q2 += sq[k]; }
    float mean = S * (1.f / 512.f);
    float var = Q2 * (1.f / 512.f) - mean * mean;
    float y = (val - mean) * rsqrtf(var + 1e-5f) * gg[t] + bb[t];
    if (mode == 0) g_X[(size_t)m * 512 + t] = y;
    else           out[(size_t)m * 512 + t] = y;
}

// ---------------------------------------------------------------------------
extern "C" void kernel_launch(void* const* d_in, const int* in_sizes, int n_in,
                              void* d_out, int out_size) {
    (void)in_sizes; (void)n_in; (void)out_size;
    const float* Q  = (const float*)d_in[0];
    // d_in[1] = K, unused by the reference forward
    const float* Wq = (const float*)d_in[2];
    const float* bq = (const float*)d_in[3];
    const float* Wo = (const float*)d_in[4];
    const float* bo = (const float*)d_in[5];
    const float* g0 = (const float*)d_in[6];
    const float* b0 = (const float*)d_in[7];
    const float* g1 = (const float*)d_in[8];
    const float* b1 = (const float*)d_in[9];
    float* out = (float*)d_out;

    dim3 ggrid(4, 64);   // N/128, M/128
    dim3 agrid(8, 64);   // tiles, bh

    gemm512h<0><<<ggrid, 256>>>(Q, Wq, bq);
    sink_p1<<<agrid, 256>>>();
    sink_p2<<<agrid, 256>>>();
    sink_p3<<<agrid, 256>>>();
    ln_kernel<<<8192, 512>>>(g0, b0, nullptr, 0);
    gemm512h<1><<<ggrid, 256>>>(nullptr, Wo, bo);
    ln_kernel<<<8192, 512>>>(g1, b1, out, 1);
}

// round 5
// speedup vs baseline: 1.3569x; 1.3569x over previous
#include <cuda_runtime.h>
#include <cuda_fp16.h>
#include <math.h>
#include <stdint.h>

// Problem constants: B=8, n=1024, dQ=dV=512, H=8, d=64, HB=64
#define NSEQ   1024
#define DHEAD  64
#define DVTOT  512
#define NBATCH 8
#define NHB    64

#define SSCALE 0.044194173824159216f   // 1/sqrt(512)
#define LOGMU  (-6.9314615657f)        // log(1/1024 + 1e-8)

// Scratch (device globals; no allocation allowed)
__device__ float  g_Qh [NHB * NSEQ * DHEAD];   // head-major Q_ fp32 (residual)
__device__ __half g_Qh16[NHB * NSEQ * DHEAD];  // head-major Q_ fp16 (mma operand)
__device__ float  g_Oh [NHB * NSEQ * DHEAD];   // head-major O_
__device__ float  g_u  [NHB * NSEQ];
__device__ float  g_v  [NHB * NSEQ];
__device__ float  g_X  [NBATCH * NSEQ * DVTOT];
__device__ float  g_T  [NBATCH * NSEQ * DVTOT];

// ---------------------------------------------------------------------------
// helpers
// ---------------------------------------------------------------------------
__device__ __forceinline__ void mma16h(float* c, const unsigned* a, const unsigned* b) {
    asm volatile(
        "mma.sync.aligned.m16n8k16.row.col.f32.f16.f16.f32 "
        "{%0,%1,%2,%3},{%4,%5,%6,%7},{%8,%9},{%0,%1,%2,%3};\n"
        : "+f"(c[0]), "+f"(c[1]), "+f"(c[2]), "+f"(c[3])
        : "r"(a[0]), "r"(a[1]), "r"(a[2]), "r"(a[3]), "r"(b[0]), "r"(b[1]));
}
__device__ __forceinline__ unsigned smaddr(const void* p) {
    return (unsigned)__cvta_generic_to_shared(p);
}
__device__ __forceinline__ void ldm_x4(unsigned* r, unsigned a) {
    asm volatile("ldmatrix.sync.aligned.m8n8.x4.shared.b16 {%0,%1,%2,%3},[%4];"
                 : "=r"(r[0]), "=r"(r[1]), "=r"(r[2]), "=r"(r[3]) : "r"(a));
}
__device__ __forceinline__ void ldm_x4t(unsigned* r, unsigned a) {
    asm volatile("ldmatrix.sync.aligned.m8n8.x4.trans.shared.b16 {%0,%1,%2,%3},[%4];"
                 : "=r"(r[0]), "=r"(r[1]), "=r"(r[2]), "=r"(r[3]) : "r"(a));
}
__device__ __forceinline__ void ldm_x2(unsigned* r, unsigned a) {
    asm volatile("ldmatrix.sync.aligned.m8n8.x2.shared.b16 {%0,%1},[%2];"
                 : "=r"(r[0]), "=r"(r[1]) : "r"(a));
}
__device__ __forceinline__ unsigned fh2(float a, float b) {
    __half2 h = __floats2half2_rn(a, b);
    return *(unsigned*)&h;
}
__device__ __forceinline__ void cpa16(unsigned s, const void* g) {
    asm volatile("cp.async.ca.shared.global [%0], [%1], 16;" :: "r"(s), "l"(g) : "memory");
}
__device__ __forceinline__ void cpa_commit() {
    asm volatile("cp.async.commit_group;" ::: "memory");
}
template <int N>
__device__ __forceinline__ void cpa_wait() {
    asm volatile("cp.async.wait_group %0;" :: "n"(N) : "memory");
}

// ---------------------------------------------------------------------------
// Sinkhorn LSE passes, fp16 mma m16n8k16, cp.async double-buffered j-tiles.
// ADDU=false: u_i = log_mu - log(sum_j exp(S_ij))
// ADDU=true : v_j = log_mu - log(sum_i exp(S_ij + u_i))  (S symmetric)
// grid (8, 64), 256 threads, warps 4(m) x 2(j), warp tile 32x64
// ---------------------------------------------------------------------------
template <bool ADDU>
__global__ void __launch_bounds__(256, 2) sink_lse_kernel() {
    __shared__ __align__(16) __half Qi[128 * 72];
    __shared__ __align__(16) __half Qj[2][128 * 72];
    __shared__ float ub[2][128];
    __shared__ float ps[256];

    const int bh = blockIdx.y;
    const int i0 = blockIdx.x * 128;
    const int tid = threadIdx.x, lane = tid & 31, w = tid >> 5;
    const int wm = (w & 3) * 32, wn = (w >> 2) * 64;
    const __half* Qb = g_Qh16 + (size_t)bh * (NSEQ * DHEAD);

    // fill Qi (synchronous; needed for fragment hoist)
#pragma unroll
    for (int r = 0; r < 4; r++) {
        int idx = tid + r * 256;
        int row = idx >> 3, q = (idx & 7) * 8;
        *(float4*)(Qi + row * 72 + q) =
            *(const float4*)(Qb + (size_t)(i0 + row) * DHEAD + q);
    }
    // prefetch Qj tile 0
#pragma unroll
    for (int r = 0; r < 4; r++) {
        int idx = tid + r * 256;
        int row = idx >> 3, q = (idx & 7) * 8;
        cpa16(smaddr(&Qj[0][row * 72 + q]), Qb + (size_t)row * DHEAD + q);
    }
    if (ADDU && tid < 128) ub[0][tid] = g_u[bh * NSEQ + tid];
    cpa_commit();
    __syncthreads();

    // hoist A fragments (loop-invariant across j-tiles)
    unsigned af[2][4][4];
#pragma unroll
    for (int mt = 0; mt < 2; mt++)
#pragma unroll
        for (int kk = 0; kk < 4; kk++)
            ldm_x4(af[mt][kk],
                   smaddr(Qi + (wm + mt * 16 + (lane & 15)) * 72 + kk * 16 + (lane >> 4) * 8));

    float ls[2][2] = {{0.f, 0.f}, {0.f, 0.f}};

    for (int jt = 0; jt < 8; jt++) {
        __syncthreads();                 // all warps done reading buf (jt+1)&1
        if (jt < 7) {
            int j0 = (jt + 1) * 128, buf = (jt + 1) & 1;
#pragma unroll
            for (int r = 0; r < 4; r++) {
                int idx = tid + r * 256;
                int row = idx >> 3, q = (idx & 7) * 8;
                cpa16(smaddr(&Qj[buf][row * 72 + q]),
                      Qb + (size_t)(j0 + row) * DHEAD + q);
            }
            if (ADDU && tid < 128) ub[buf][tid] = g_u[bh * NSEQ + j0 + tid];
            cpa_commit();
            cpa_wait<1>();
        } else {
            cpa_wait<0>();
        }
        __syncthreads();                 // tile jt visible

        const __half* Qc = Qj[jt & 1];
        const float* bb = ub[jt & 1];

        float sa[2][8][4];
#pragma unroll
        for (int a = 0; a < 2; a++)
#pragma unroll
            for (int b = 0; b < 8; b++)
#pragma unroll
                for (int c = 0; c < 4; c++) sa[a][b][c] = 0.f;

#pragma unroll
        for (int kk = 0; kk < 4; kk++) {
#pragma unroll
            for (int nb = 0; nb < 4; nb++) {
                unsigned bq[4];
                ldm_x4(bq, smaddr(Qc + (wn + nb * 16 + ((lane >> 4) & 1) * 8 + (lane & 7)) * 72 +
                                  kk * 16 + ((lane >> 3) & 1) * 8));
                mma16h(sa[0][2 * nb], af[0][kk], bq);
                mma16h(sa[1][2 * nb], af[1][kk], bq);
                mma16h(sa[0][2 * nb + 1], af[0][kk], bq + 2);
                mma16h(sa[1][2 * nb + 1], af[1][kk], bq + 2);
            }
        }
        // accumulate exp sums (no running max: |arg| small)
#pragma unroll
        for (int mt = 0; mt < 2; mt++)
#pragma unroll
            for (int nt = 0; nt < 8; nt++)
#pragma unroll
                for (int rg = 0; rg < 4; rg++) {
                    float v = sa[mt][nt][rg] * SSCALE;
                    if (ADDU) v += bb[wn + nt * 8 + 2 * (lane & 3) + (rg & 1)];
                    ls[mt][rg >> 1] += __expf(v);
                }
    }

#pragma unroll
    for (int mt = 0; mt < 2; mt++)
#pragma unroll
        for (int h = 0; h < 2; h++) {
            float v = ls[mt][h];
            v += __shfl_xor_sync(0xffffffffu, v, 1);
            v += __shfl_xor_sync(0xffffffffu, v, 2);
            if ((lane & 3) == 0)
                ps[(w >> 2) * 128 + wm + mt * 16 + (lane >> 2) + h * 8] = v;
        }
    __syncthreads();
    if (tid < 128) {
        float s = ps[tid] + ps[128 + tid];
        float r = LOGMU - __logf(s);
        if (ADDU) g_v[bh * NSEQ + i0 + tid] = r;
        else      g_u[bh * NSEQ + i0 + tid] = r;
    }
}

// ---------------------------------------------------------------------------
// Pass C: O_ = Q_ + (1024 * exp(S + u_i + v_j)) @ Q_, pipelined j-tiles.
// Phase 1 per j-tile: S via mma (warps 4m x 2j), exp -> Ap (fp16 smem)
// Phase 2: O += Ap @ Qj via mma (warps 4m x 2d)
// ---------------------------------------------------------------------------
__global__ void __launch_bounds__(256, 2) sink_av_kernel() {
    extern __shared__ __align__(16) char smraw[];
    __half* Qi = (__half*)smraw;                 // 128*72
    __half* QjA = Qi + 9216;                     // 128*72 (buf 0)
    __half* QjB = QjA + 9216;                    // 128*72 (buf 1)
    __half* Ap = QjB + 9216;                     // 128*136
    float* ur = (float*)(Ap + 17408);            // 128
    float* vb = ur + 128;                        // 2 x 128

    const int bh = blockIdx.y;
    const int i0 = blockIdx.x * 128;
    const int tid = threadIdx.x, lane = tid & 31, w = tid >> 5;
    const int wm = (w & 3) * 32;
    const int wn = (w >> 2) * 64;    // phase 1 (j cols)
    const int wn2 = (w >> 2) * 32;   // phase 2 (d cols)
    const __half* Qb = g_Qh16 + (size_t)bh * (NSEQ * DHEAD);
    const float* Qf32 = g_Qh + (size_t)bh * (NSEQ * DHEAD);
    float* Obase = g_Oh + (size_t)bh * (NSEQ * DHEAD);
    __half* Qbuf[2] = { QjA, QjB };

#pragma unroll
    for (int r = 0; r < 4; r++) {
        int idx = tid + r * 256;
        int row = idx >> 3, q = (idx & 7) * 8;
        *(float4*)(Qi + row * 72 + q) =
            *(const float4*)(Qb + (size_t)(i0 + row) * DHEAD + q);
    }
#pragma unroll
    for (int r = 0; r < 4; r++) {
        int idx = tid + r * 256;
        int row = idx >> 3, q = (idx & 7) * 8;
        cpa16(smaddr(QjA + row * 72 + q), Qb + (size_t)row * DHEAD + q);
    }
    if (tid < 128) {
        ur[tid] = g_u[bh * NSEQ + i0 + tid];
        vb[tid] = g_v[bh * NSEQ + tid];
    }
    cpa_commit();

    float oa[2][4][4];
#pragma unroll
    for (int a = 0; a < 2; a++)
#pragma unroll
        for (int b = 0; b < 4; b++)
#pragma unroll
            for (int c = 0; c < 4; c++) oa[a][b][c] = 0.f;

    for (int jt = 0; jt < 8; jt++) {
        __syncthreads();                 // all warps done with buf (jt+1)&1 (phase2 of jt-1)
        if (jt < 7) {
            int j0 = (jt + 1) * 128, buf = (jt + 1) & 1;
#pragma unroll
            for (int r = 0; r < 4; r++) {
                int idx = tid + r * 256;
                int row = idx >> 3, q = (idx & 7) * 8;
                cpa16(smaddr(Qbuf[buf] + row * 72 + q),
                      Qb + (size_t)(j0 + row) * DHEAD + q);
            }
            if (tid < 128) vb[buf * 128 + tid] = g_v[bh * NSEQ + j0 + tid];
            cpa_commit();
            cpa_wait<1>();
        } else {
            cpa_wait<0>();
        }
        __syncthreads();

        const __half* Qc = Qbuf[jt & 1];
        const float* vv = vb + (jt & 1) * 128;

        // ---- phase 1: S tile ----
        float sa[2][8][4];
#pragma unroll
        for (int a = 0; a < 2; a++)
#pragma unroll
            for (int b = 0; b < 8; b++)
#pragma unroll
                for (int c = 0; c < 4; c++) sa[a][b][c] = 0.f;

#pragma unroll
        for (int kk = 0; kk < 4; kk++) {
            unsigned a0[4], a1[4];
            {
                int col = kk * 16 + (lane >> 4) * 8;
                ldm_x4(a0, smaddr(Qi + (wm + (lane & 15)) * 72 + col));
                ldm_x4(a1, smaddr(Qi + (wm + 16 + (lane & 15)) * 72 + col));
            }
#pragma unroll
            for (int nb = 0; nb < 4; nb++) {
                unsigned bq[4];
                ldm_x4(bq, smaddr(Qc + (wn + nb * 16 + ((lane >> 4) & 1) * 8 + (lane & 7)) * 72 +
                                  kk * 16 + ((lane >> 3) & 1) * 8));
                mma16h(sa[0][2 * nb], a0, bq);
                mma16h(sa[1][2 * nb], a1, bq);
                mma16h(sa[0][2 * nb + 1], a0, bq + 2);
                mma16h(sa[1][2 * nb + 1], a1, bq + 2);
            }
        }
        // A = 1024 * exp(S*scale + u_i + v_j) -> fp16 tile Ap
#pragma unroll
        for (int mt = 0; mt < 2; mt++)
#pragma unroll
            for (int nt = 0; nt < 8; nt++) {
                int row0 = wm + mt * 16 + (lane >> 2);
                int col = wn + nt * 8 + 2 * (lane & 3);
                float e0 = 1024.f * __expf(sa[mt][nt][0] * SSCALE + ur[row0] + vv[col]);
                float e1 = 1024.f * __expf(sa[mt][nt][1] * SSCALE + ur[row0] + vv[col + 1]);
                *(unsigned*)(Ap + row0 * 136 + col) = fh2(e0, e1);
                int row8 = row0 + 8;
                float e2 = 1024.f * __expf(sa[mt][nt][2] * SSCALE + ur[row8] + vv[col]);
                float e3 = 1024.f * __expf(sa[mt][nt][3] * SSCALE + ur[row8] + vv[col + 1]);
                *(unsigned*)(Ap + row8 * 136 + col) = fh2(e2, e3);
            }
        __syncthreads();

        // ---- phase 2: O += Ap @ Qj ----
#pragma unroll
        for (int kk = 0; kk < 8; kk++) {
            unsigned a0[4], a1[4];
            {
                int col = kk * 16 + (lane >> 4) * 8;
                ldm_x4(a0, smaddr(Ap + (wm + (lane & 15)) * 136 + col));
                ldm_x4(a1, smaddr(Ap + (wm + 16 + (lane & 15)) * 136 + col));
            }
#pragma unroll
            for (int nb = 0; nb < 2; nb++) {
                unsigned bq[4];
                ldm_x4t(bq, smaddr(Qc + (16 * kk + (lane & 15)) * 72 +
                                   wn2 + nb * 16 + ((lane >> 4) & 1) * 8));
                mma16h(oa[0][2 * nb], a0, bq);
                mma16h(oa[1][2 * nb], a1, bq);
                mma16h(oa[0][2 * nb + 1], a0, bq + 2);
                mma16h(oa[1][2 * nb + 1], a1, bq + 2);
            }
        }
    }

    // epilogue: O_ = Q_ + accum (residual in fp32)
#pragma unroll
    for (int mt = 0; mt < 2; mt++)
#pragma unroll
        for (int nt = 0; nt < 4; nt++)
#pragma unroll
            for (int rg = 0; rg < 4; rg++) {
                int row = i0 + wm + mt * 16 + (lane >> 2) + ((rg & 2) ? 8 : 0);
                int col = wn2 + nt * 8 + 2 * (lane & 3) + (rg & 1);
                Obase[row * DHEAD + col] = oa[mt][nt][rg] + Qf32[row * DHEAD + col];
            }
}

// ---------------------------------------------------------------------------
// fp16 GEMM: C[8192,512] = A[8192,512] * W[512,512]^T (+bias, epilogues)
// MODE 0: A = Q input; scatter head-major into g_Qh (fp32) + g_Qh16 (fp16)
// MODE 1: A = g_X;  g_T = g_X + relu(C + bias)
// tile 128x128, BK=32, warps 4(m) x 2(n)
// ---------------------------------------------------------------------------
template <int MODE>
__global__ void __launch_bounds__(256, 2) gemm512h(const float* __restrict__ Ain,
                                                   const float* __restrict__ W,
                                                   const float* __restrict__ bias) {
    __shared__ __align__(16) __half As[128 * 40];
    __shared__ __align__(16) __half Bs[128 * 40];
    const float* A = (MODE == 0) ? Ain : (const float*)g_X;

    const int m0 = blockIdx.y * 128, n0 = blockIdx.x * 128;
    const int tid = threadIdx.x, lane = tid & 31, w = tid >> 5;
    const int wm = (w & 3) * 32, wn = (w >> 2) * 64;

    float acc[2][8][4];
#pragma unroll
    for (int a = 0; a < 2; a++)
#pragma unroll
        for (int b = 0; b < 8; b++)
#pragma unroll
            for (int c = 0; c < 4; c++) acc[a][b][c] = 0.f;

    for (int k0 = 0; k0 < 512; k0 += 32) {
        __syncthreads();
#pragma unroll
        for (int c = 0; c < 2; c++) {
            int idx = tid + c * 256;
            int row = idx >> 2, q = (idx & 3) * 8;
            float4 v0 = *(const float4*)(A + (size_t)(m0 + row) * 512 + k0 + q);
            float4 v1 = *(const float4*)(A + (size_t)(m0 + row) * 512 + k0 + q + 4);
            uint4 pa;
            pa.x = fh2(v0.x, v0.y); pa.y = fh2(v0.z, v0.w);
            pa.z = fh2(v1.x, v1.y); pa.w = fh2(v1.z, v1.w);
            *(uint4*)(As + row * 40 + q) = pa;
            float4 w0 = *(const float4*)(W + (size_t)(n0 + row) * 512 + k0 + q);
            float4 w1 = *(const float4*)(W + (size_t)(n0 + row) * 512 + k0 + q + 4);
            uint4 pb;
            pb.x = fh2(w0.x, w0.y); pb.y = fh2(w0.z, w0.w);
            pb.z = fh2(w1.x, w1.y); pb.w = fh2(w1.z, w1.w);
            *(uint4*)(Bs + row * 40 + q) = pb;
        }
        __syncthreads();
#pragma unroll
        for (int kk = 0; kk < 2; kk++) {
            unsigned af[2][4];
#pragma unroll
            for (int mt = 0; mt < 2; mt++)
                ldm_x4(af[mt], smaddr(As + (wm + mt * 16 + (lane & 15)) * 40 +
                                      kk * 16 + (lane >> 4) * 8));
#pragma unroll
            for (int nb = 0; nb < 4; nb++) {
                unsigned bq[4];
                ldm_x4(bq, smaddr(Bs + (wn + nb * 16 + ((lane >> 4) & 1) * 8 + (lane & 7)) * 40 +
                                  kk * 16 + ((lane >> 3) & 1) * 8));
                mma16h(acc[0][2 * nb], af[0], bq);
                mma16h(acc[1][2 * nb], af[1], bq);
                mma16h(acc[0][2 * nb + 1], af[0], bq + 2);
                mma16h(acc[1][2 * nb + 1], af[1], bq + 2);
            }
        }
    }

#pragma unroll
    for (int mt = 0; mt < 2; mt++)
#pragma unroll
        for (int nt = 0; nt < 8; nt++)
#pragma unroll
            for (int rg = 0; rg < 4; rg++) {
                int row = m0 + wm + mt * 16 + (lane >> 2) + ((rg & 2) ? 8 : 0);
                int col = n0 + wn + nt * 8 + 2 * (lane & 3) + (rg & 1);
                float v = acc[mt][nt][rg] + bias[col];
                if (MODE == 0) {
                    int b = row >> 10, i = row & 1023;
                    int h = col >> 6, dc = col & 63;
                    size_t idx = ((size_t)((h << 3) + b) * NSEQ + i) * DHEAD + dc;
                    g_Qh[idx] = v;
                    g_Qh16[idx] = __float2half_rn(v);
                } else {
                    v = fmaxf(v, 0.f) + A[(size_t)row * 512 + col];
                    g_T[(size_t)row * 512 + col] = v;
                }
            }
}

// ---------------------------------------------------------------------------
// LayerNorm. mode 0: merge heads g_Oh -> LN -> g_X ; mode 1: g_T -> LN -> out
// ---------------------------------------------------------------------------
__global__ void __launch_bounds__(512) ln_kernel(const float* __restrict__ gg,
                                                 const float* __restrict__ bb,
                                                 float* __restrict__ out, int mode) {
    int m = blockIdx.x;
    int t = threadIdx.x;
    float val;
    if (mode == 0) {
        int b = m >> 10, i = m & 1023, h = t >> 6, dc = t & 63;
        val = g_Oh[(((h << 3) + b) * NSEQ + i) * DHEAD + dc];
    } else {
        val = g_T[(size_t)m * 512 + t];
    }
    float s = val, q = val * val;
#pragma unroll
    for (int off = 16; off; off >>= 1) {
        s += __shfl_xor_sync(0xffffffffu, s, off);
        q += __shfl_xor_sync(0xffffffffu, q, off);
    }
    __shared__ float ss[16], sq[16];
    int w = t >> 5, lane = t & 31;
    if (!lane) { ss[w] = s; sq[w] = q; }
    __syncthreads();
    float S = 0.f, Q2 = 0.f;
#pragma unroll
    for (int k = 0; k < 16; k++) { S += ss[k]; Q2 += sq[k]; }
    float mean = S * (1.f / 512.f);
    float var = Q2 * (1.f / 512.f) - mean * mean;
    float y = (val - mean) * rsqrtf(var + 1e-5f) * gg[t] + bb[t];
    if (mode == 0) g_X[(size_t)m * 512 + t] = y;
    else           out[(size_t)m * 512 + t] = y;
}

// ---------------------------------------------------------------------------
extern "C" void kernel_launch(void* const* d_in, const int* in_sizes, int n_in,
                              void* d_out, int out_size) {
    (void)in_sizes; (void)n_in; (void)out_size;
    const float* Q  = (const float*)d_in[0];
    // d_in[1] = K, unused by the reference forward
    const float* Wq = (const float*)d_in[2];
    const float* bq = (const float*)d_in[3];
    const float* Wo = (const float*)d_in[4];
    const float* bo = (const float*)d_in[5];
    const float* g0 = (const float*)d_in[6];
    const float* b0 = (const float*)d_in[7];
    const float* g1 = (const float*)d_in[8];
    const float* b1 = (const float*)d_in[9];
    float* out = (float*)d_out;

    // AV smem: Qi + 2*Qj + Ap halves, + ur/vb floats
    const int SMEM_AV = (9216 * 3 + 17408) * 2 + (128 + 256) * 4;  // 90496 B
    cudaFuncSetAttribute(sink_av_kernel,
                         cudaFuncAttributeMaxDynamicSharedMemorySize, SMEM_AV);

    dim3 ggrid(4, 64);   // N/128, M/128
    dim3 agrid(8, 64);   // row-blocks, bh

    gemm512h<0><<<ggrid, 256>>>(Q, Wq, bq);
    sink_lse_kernel<false><<<agrid, 256>>>();
    sink_lse_kernel<true><<<agrid, 256>>>();
    sink_av_kernel<<<agrid, 256, SMEM_AV>>>();
    ln_kernel<<<8192, 512>>>(g0, b0, nullptr, 0);
    gemm512h<1><<<ggrid, 256>>>(nullptr, Wo, bo);
    ln_kernel<<<8192, 512>>>(g1, b1, out, 1);
}

// round 6
// speedup vs baseline: 1.4235x; 1.0491x over previous
#include <cuda_runtime.h>
#include <cuda_fp16.h>
#include <math.h>
#include <stdint.h>

// Problem constants: B=8, n=1024, dQ=dV=512, H=8, d=64, HB=64
#define NSEQ   1024
#define DHEAD  64
#define DVTOT  512
#define NBATCH 8
#define NHB    64

#define SSCALE 0.044194173824159216f   // 1/sqrt(512)
#define LOGMU  (-6.9314615657f)        // log(1/1024 + 1e-8)

// Scratch (device globals; no allocation allowed)
__device__ float  g_Qh [NHB * NSEQ * DHEAD];   // head-major Q_ fp32 (residual)
__device__ __half g_Qh16[NHB * NSEQ * DHEAD];  // head-major Q_ fp16 (mma operand)
__device__ float  g_Oh [NHB * NSEQ * DHEAD];   // head-major O_
__device__ float  g_u  [NHB * NSEQ];
__device__ float  g_v  [NHB * NSEQ];
__device__ float  g_X  [NBATCH * NSEQ * DVTOT];
__device__ float  g_T  [NBATCH * NSEQ * DVTOT];
// partial sums for symmetric LSE passes: [bh][k=0..7][1024]
__device__ float  g_part[NHB * 8 * NSEQ];

// ---------------------------------------------------------------------------
// helpers
// ---------------------------------------------------------------------------
__device__ __forceinline__ void mma16h(float* c, const unsigned* a, const unsigned* b) {
    asm volatile(
        "mma.sync.aligned.m16n8k16.row.col.f32.f16.f16.f32 "
        "{%0,%1,%2,%3},{%4,%5,%6,%7},{%8,%9},{%0,%1,%2,%3};\n"
        : "+f"(c[0]), "+f"(c[1]), "+f"(c[2]), "+f"(c[3])
        : "r"(a[0]), "r"(a[1]), "r"(a[2]), "r"(a[3]), "r"(b[0]), "r"(b[1]));
}
__device__ __forceinline__ unsigned smaddr(const void* p) {
    return (unsigned)__cvta_generic_to_shared(p);
}
__device__ __forceinline__ void ldm_x4(unsigned* r, unsigned a) {
    asm volatile("ldmatrix.sync.aligned.m8n8.x4.shared.b16 {%0,%1,%2,%3},[%4];"
                 : "=r"(r[0]), "=r"(r[1]), "=r"(r[2]), "=r"(r[3]) : "r"(a));
}
__device__ __forceinline__ void ldm_x4t(unsigned* r, unsigned a) {
    asm volatile("ldmatrix.sync.aligned.m8n8.x4.trans.shared.b16 {%0,%1,%2,%3},[%4];"
                 : "=r"(r[0]), "=r"(r[1]), "=r"(r[2]), "=r"(r[3]) : "r"(a));
}
__device__ __forceinline__ unsigned fh2(float a, float b) {
    __half2 h = __floats2half2_rn(a, b);
    return *(unsigned*)&h;
}
__device__ __forceinline__ void cpa16(unsigned s, const void* g) {
    asm volatile("cp.async.ca.shared.global [%0], [%1], 16;" :: "r"(s), "l"(g) : "memory");
}
__device__ __forceinline__ void cpa_commit() {
    asm volatile("cp.async.commit_group;" ::: "memory");
}
template <int N>
__device__ __forceinline__ void cpa_wait() {
    asm volatile("cp.async.wait_group %0;" :: "n"(N) : "memory");
}

// ---------------------------------------------------------------------------
// Symmetric-tile LSE pass. One CTA per (a,b) tile pair, a<=b (36 pairs x 64 bh).
// MODE 0 (row/col sums of P = exp(S*scale)):
//   rows(a) slot k=b  += rowsum(e);  rows(b) slot k=a += colsum(e)  [a!=b]
// MODE 1 (weighted sums for v; u known):
//   rows(a) slot k=b  += sum_j e^{u_j} e_ij   [a!=b]
//   rows(b) slot k=a  += sum_i e^{u_i} e_ij
// warps 4(m) x 2(n), warp tile 32x64.
// ---------------------------------------------------------------------------
template <int MODE>
__global__ void __launch_bounds__(256, 2) sym_lse() {
    __shared__ __align__(16) __half Qi[128 * 72];
    __shared__ __align__(16) __half Qj[128 * 72];
    __shared__ float csh[4][128];
    __shared__ float ps[256];
    __shared__ float eua[128], eub[128];

    const int bh = blockIdx.y;
    // triangular map: blockIdx.x -> (a, b), a <= b
    int a = 0, tt = blockIdx.x;
    while (tt >= 8 - a) { tt -= 8 - a; a++; }
    const int b = a + tt;

    const int tid = threadIdx.x, lane = tid & 31, w = tid >> 5;
    const int mw = w & 3, w2 = w >> 2;
    const int wm = mw * 32, wn = w2 * 64;
    const __half* Qb = g_Qh16 + (size_t)bh * (NSEQ * DHEAD);

#pragma unroll
    for (int r = 0; r < 4; r++) {
        int idx = tid + r * 256;
        int row = idx >> 3, q = (idx & 7) * 8;
        cpa16(smaddr(Qi + row * 72 + q), Qb + (size_t)(a * 128 + row) * DHEAD + q);
        cpa16(smaddr(Qj + row * 72 + q), Qb + (size_t)(b * 128 + row) * DHEAD + q);
    }
    if (MODE == 1 && tid < 128) {
        eua[tid] = __expf(g_u[bh * NSEQ + a * 128 + tid]);
        eub[tid] = __expf(g_u[bh * NSEQ + b * 128 + tid]);
    }
    cpa_commit();
    cpa_wait<0>();
    __syncthreads();

    float sa[2][8][4];
#pragma unroll
    for (int x = 0; x < 2; x++)
#pragma unroll
        for (int y = 0; y < 8; y++)
#pragma unroll
            for (int z = 0; z < 4; z++) sa[x][y][z] = 0.f;

#pragma unroll
    for (int kk = 0; kk < 4; kk++) {
        unsigned af0[4], af1[4];
        {
            int col = kk * 16 + (lane >> 4) * 8;
            ldm_x4(af0, smaddr(Qi + (wm + (lane & 15)) * 72 + col));
            ldm_x4(af1, smaddr(Qi + (wm + 16 + (lane & 15)) * 72 + col));
        }
#pragma unroll
        for (int nb = 0; nb < 4; nb++) {
            unsigned bq[4];
            ldm_x4(bq, smaddr(Qj + (wn + nb * 16 + ((lane >> 4) & 1) * 8 + (lane & 7)) * 72 +
                              kk * 16 + ((lane >> 3) & 1) * 8));
            mma16h(sa[0][2 * nb], af0, bq);
            mma16h(sa[1][2 * nb], af1, bq);
            mma16h(sa[0][2 * nb + 1], af0, bq + 2);
            mma16h(sa[1][2 * nb + 1], af1, bq + 2);
        }
    }

    // per-thread u weights for own rows (MODE 1)
    float eu4[2][2];
    if (MODE == 1) {
#pragma unroll
        for (int mt = 0; mt < 2; mt++)
#pragma unroll
            for (int h = 0; h < 2; h++)
                eu4[mt][h] = eua[wm + mt * 16 + (lane >> 2) + h * 8];
    }

    float ls[2][2] = {{0.f, 0.f}, {0.f, 0.f}};   // row-sum partials
    float cp[8][2];                              // col-sum partials
#pragma unroll
    for (int nt = 0; nt < 8; nt++) { cp[nt][0] = 0.f; cp[nt][1] = 0.f; }

#pragma unroll
    for (int mt = 0; mt < 2; mt++)
#pragma unroll
        for (int nt = 0; nt < 8; nt++) {
            int colb = wn + nt * 8 + 2 * (lane & 3);
#pragma unroll
            for (int rg = 0; rg < 4; rg++) {
                float e = __expf(sa[mt][nt][rg] * SSCALE);
                int h = rg >> 1, d = rg & 1;
                if (MODE == 0) {
                    ls[mt][h] += e;
                    cp[nt][d] += e;
                } else {
                    ls[mt][h] += eub[colb + d] * e;
                    cp[nt][d] += eu4[mt][h] * e;
                }
            }
        }

    // ---- row-sum reduction (4 lanes share a row, then two n-warps) ----
#pragma unroll
    for (int mt = 0; mt < 2; mt++)
#pragma unroll
        for (int h = 0; h < 2; h++) {
            float v = ls[mt][h];
            v += __shfl_xor_sync(0xffffffffu, v, 1);
            v += __shfl_xor_sync(0xffffffffu, v, 2);
            if ((lane & 3) == 0)
                ps[w2 * 128 + wm + mt * 16 + (lane >> 2) + h * 8] = v;
        }

    // ---- col-sum reduction (8 row-groups within warp) ----
#pragma unroll
    for (int nt = 0; nt < 8; nt++)
#pragma unroll
        for (int d = 0; d < 2; d++) {
            float v = cp[nt][d];
            v += __shfl_xor_sync(0xffffffffu, v, 4);
            v += __shfl_xor_sync(0xffffffffu, v, 8);
            v += __shfl_xor_sync(0xffffffffu, v, 16);
            cp[nt][d] = v;
        }
    if (lane < 4) {
#pragma unroll
        for (int nt = 0; nt < 8; nt++) {
            csh[mw][wn + nt * 8 + 2 * lane + 0] = cp[nt][0];
            csh[mw][wn + nt * 8 + 2 * lane + 1] = cp[nt][1];
        }
    }
    __syncthreads();

    if (tid < 128) {
        // rowsum -> block a, slot k=b   (skip on diagonal for MODE 1)
        if (MODE == 0 || a != b) {
            float rs = ps[tid] + ps[128 + tid];
            g_part[((size_t)bh * 8 + b) * NSEQ + a * 128 + tid] = rs;
        }
        // colsum -> block b, slot k=a   (skip on diagonal for MODE 0)
        if (MODE == 1 || a != b) {
            float cs = csh[0][tid] + csh[1][tid] + csh[2][tid] + csh[3][tid];
            g_part[((size_t)bh * 8 + a) * NSEQ + b * 128 + tid] = cs;
        }
    }
}

// finalize: sum the 8 partial slots, take LOGMU - log. M=0 -> g_u, M=1 -> g_v
template <int M>
__global__ void __launch_bounds__(1024) fin_kernel() {
    int bh = blockIdx.x, pos = threadIdx.x;
    float s = 0.f;
#pragma unroll
    for (int k = 0; k < 8; k++)
        s += g_part[((size_t)bh * 8 + k) * NSEQ + pos];
    float r = LOGMU - __logf(s);
    if (M == 0) g_u[bh * NSEQ + pos] = r;
    else        g_v[bh * NSEQ + pos] = r;
}

// ---------------------------------------------------------------------------
// Pass C: O_ = Q_ + (1024 * exp(S + u_i + v_j)) @ Q_, pipelined j-tiles.
// (unchanged from R5 best)
// ---------------------------------------------------------------------------
__global__ void __launch_bounds__(256, 2) sink_av_kernel() {
    extern __shared__ __align__(16) char smraw[];
    __half* Qi = (__half*)smraw;                 // 128*72
    __half* QjA = Qi + 9216;                     // 128*72 (buf 0)
    __half* QjB = QjA + 9216;                    // 128*72 (buf 1)
    __half* Ap = QjB + 9216;                     // 128*136
    float* ur = (float*)(Ap + 17408);            // 128
    float* vb = ur + 128;                        // 2 x 128

    const int bh = blockIdx.y;
    const int i0 = blockIdx.x * 128;
    const int tid = threadIdx.x, lane = tid & 31, w = tid >> 5;
    const int wm = (w & 3) * 32;
    const int wn = (w >> 2) * 64;    // phase 1 (j cols)
    const int wn2 = (w >> 2) * 32;   // phase 2 (d cols)
    const __half* Qb = g_Qh16 + (size_t)bh * (NSEQ * DHEAD);
    const float* Qf32 = g_Qh + (size_t)bh * (NSEQ * DHEAD);
    float* Obase = g_Oh + (size_t)bh * (NSEQ * DHEAD);
    __half* Qbuf[2] = { QjA, QjB };

#pragma unroll
    for (int r = 0; r < 4; r++) {
        int idx = tid + r * 256;
        int row = idx >> 3, q = (idx & 7) * 8;
        *(float4*)(Qi + row * 72 + q) =
            *(const float4*)(Qb + (size_t)(i0 + row) * DHEAD + q);
    }
#pragma unroll
    for (int r = 0; r < 4; r++) {
        int idx = tid + r * 256;
        int row = idx >> 3, q = (idx & 7) * 8;
        cpa16(smaddr(QjA + row * 72 + q), Qb + (size_t)row * DHEAD + q);
    }
    if (tid < 128) {
        ur[tid] = g_u[bh * NSEQ + i0 + tid];
        vb[tid] = g_v[bh * NSEQ + tid];
    }
    cpa_commit();

    float oa[2][4][4];
#pragma unroll
    for (int x = 0; x < 2; x++)
#pragma unroll
        for (int y = 0; y < 4; y++)
#pragma unroll
            for (int z = 0; z < 4; z++) oa[x][y][z] = 0.f;

    for (int jt = 0; jt < 8; jt++) {
        __syncthreads();
        if (jt < 7) {
            int j0 = (jt + 1) * 128, buf = (jt + 1) & 1;
#pragma unroll
            for (int r = 0; r < 4; r++) {
                int idx = tid + r * 256;
                int row = idx >> 3, q = (idx & 7) * 8;
                cpa16(smaddr(Qbuf[buf] + row * 72 + q),
                      Qb + (size_t)(j0 + row) * DHEAD + q);
            }
            if (tid < 128) vb[buf * 128 + tid] = g_v[bh * NSEQ + j0 + tid];
            cpa_commit();
            cpa_wait<1>();
        } else {
            cpa_wait<0>();
        }
        __syncthreads();

        const __half* Qc = Qbuf[jt & 1];
        const float* vv = vb + (jt & 1) * 128;

        // ---- phase 1: S tile ----
        float sa[2][8][4];
#pragma unroll
        for (int x = 0; x < 2; x++)
#pragma unroll
            for (int y = 0; y < 8; y++)
#pragma unroll
                for (int z = 0; z < 4; z++) sa[x][y][z] = 0.f;

#pragma unroll
        for (int kk = 0; kk < 4; kk++) {
            unsigned a0[4], a1[4];
            {
                int col = kk * 16 + (lane >> 4) * 8;
                ldm_x4(a0, smaddr(Qi + (wm + (lane & 15)) * 72 + col));
                ldm_x4(a1, smaddr(Qi + (wm + 16 + (lane & 15)) * 72 + col));
            }
#pragma unroll
            for (int nb = 0; nb < 4; nb++) {
                unsigned bq[4];
                ldm_x4(bq, smaddr(Qc + (wn + nb * 16 + ((lane >> 4) & 1) * 8 + (lane & 7)) * 72 +
                                  kk * 16 + ((lane >> 3) & 1) * 8));
                mma16h(sa[0][2 * nb], a0, bq);
                mma16h(sa[1][2 * nb], a1, bq);
                mma16h(sa[0][2 * nb + 1], a0, bq + 2);
                mma16h(sa[1][2 * nb + 1], a1, bq + 2);
            }
        }
        // A = 1024 * exp(S*scale + u_i + v_j) -> fp16 tile Ap
#pragma unroll
        for (int mt = 0; mt < 2; mt++)
#pragma unroll
            for (int nt = 0; nt < 8; nt++) {
                int row0 = wm + mt * 16 + (lane >> 2);
                int col = wn + nt * 8 + 2 * (lane & 3);
                float e0 = 1024.f * __expf(sa[mt][nt][0] * SSCALE + ur[row0] + vv[col]);
                float e1 = 1024.f * __expf(sa[mt][nt][1] * SSCALE + ur[row0] + vv[col + 1]);
                *(unsigned*)(Ap + row0 * 136 + col) = fh2(e0, e1);
                int row8 = row0 + 8;
                float e2 = 1024.f * __expf(sa[mt][nt][2] * SSCALE + ur[row8] + vv[col]);
                float e3 = 1024.f * __expf(sa[mt][nt][3] * SSCALE + ur[row8] + vv[col + 1]);
                *(unsigned*)(Ap + row8 * 136 + col) = fh2(e2, e3);
            }
        __syncthreads();

        // ---- phase 2: O += Ap @ Qj ----
#pragma unroll
        for (int kk = 0; kk < 8; kk++) {
            unsigned a0[4], a1[4];
            {
                int col = kk * 16 + (lane >> 4) * 8;
                ldm_x4(a0, smaddr(Ap + (wm + (lane & 15)) * 136 + col));
                ldm_x4(a1, smaddr(Ap + (wm + 16 + (lane & 15)) * 136 + col));
            }
#pragma unroll
            for (int nb = 0; nb < 2; nb++) {
                unsigned bq[4];
                ldm_x4t(bq, smaddr(Qc + (16 * kk + (lane & 15)) * 72 +
                                   wn2 + nb * 16 + ((lane >> 4) & 1) * 8));
                mma16h(oa[0][2 * nb], a0, bq);
                mma16h(oa[1][2 * nb], a1, bq);
                mma16h(oa[0][2 * nb + 1], a0, bq + 2);
                mma16h(oa[1][2 * nb + 1], a1, bq + 2);
            }
        }
    }

    // epilogue: O_ = Q_ + accum (residual in fp32)
#pragma unroll
    for (int mt = 0; mt < 2; mt++)
#pragma unroll
        for (int nt = 0; nt < 4; nt++)
#pragma unroll
            for (int rg = 0; rg < 4; rg++) {
                int row = i0 + wm + mt * 16 + (lane >> 2) + ((rg & 2) ? 8 : 0);
                int col = wn2 + nt * 8 + 2 * (lane & 3) + (rg & 1);
                Obase[row * DHEAD + col] = oa[mt][nt][rg] + Qf32[row * DHEAD + col];
            }
}

// ---------------------------------------------------------------------------
// fp16 GEMM: C[8192,512] = A[8192,512] * W[512,512]^T (+bias, epilogues)
// MODE 0: A = Q input; scatter head-major into g_Qh (fp32) + g_Qh16 (fp16)
// MODE 1: A = g_X;  g_T = g_X + relu(C + bias)
// ---------------------------------------------------------------------------
template <int MODE>
__global__ void __launch_bounds__(256, 2) gemm512h(const float* __restrict__ Ain,
                                                   const float* __restrict__ W,
                                                   const float* __restrict__ bias) {
    __shared__ __align__(16) __half As[128 * 40];
    __shared__ __align__(16) __half Bs[128 * 40];
    const float* A = (MODE == 0) ? Ain : (const float*)g_X;

    const int m0 = blockIdx.y * 128, n0 = blockIdx.x * 128;
    const int tid = threadIdx.x, lane = tid & 31, w = tid >> 5;
    const int wm = (w & 3) * 32, wn = (w >> 2) * 64;

    float acc[2][8][4];
#pragma unroll
    for (int x = 0; x < 2; x++)
#pragma unroll
        for (int y = 0; y < 8; y++)
#pragma unroll
            for (int z = 0; z < 4; z++) acc[x][y][z] = 0.f;

    for (int k0 = 0; k0 < 512; k0 += 32) {
        __syncthreads();
#pragma unroll
        for (int c = 0; c < 2; c++) {
            int idx = tid + c * 256;
            int row = idx >> 2, q = (idx & 3) * 8;
            float4 v0 = *(const float4*)(A + (size_t)(m0 + row) * 512 + k0 + q);
            float4 v1 = *(const float4*)(A + (size_t)(m0 + row) * 512 + k0 + q + 4);
            uint4 pa;
            pa.x = fh2(v0.x, v0.y); pa.y = fh2(v0.z, v0.w);
            pa.z = fh2(v1.x, v1.y); pa.w = fh2(v1.z, v1.w);
            *(uint4*)(As + row * 40 + q) = pa;
            float4 w0 = *(const float4*)(W + (size_t)(n0 + row) * 512 + k0 + q);
            float4 w1 = *(const float4*)(W + (size_t)(n0 + row) * 512 + k0 + q + 4);
            uint4 pb;
            pb.x = fh2(w0.x, w0.y); pb.y = fh2(w0.z, w0.w);
            pb.z = fh2(w1.x, w1.y); pb.w = fh2(w1.z, w1.w);
            *(uint4*)(Bs + row * 40 + q) = pb;
        }
        __syncthreads();
#pragma unroll
        for (int kk = 0; kk < 2; kk++) {
            unsigned af[2][4];
#pragma unroll
            for (int mt = 0; mt < 2; mt++)
                ldm_x4(af[mt], smaddr(As + (wm + mt * 16 + (lane & 15)) * 40 +
                                      kk * 16 + (lane >> 4) * 8));
#pragma unroll
            for (int nb = 0; nb < 4; nb++) {
                unsigned bq[4];
                ldm_x4(bq, smaddr(Bs + (wn + nb * 16 + ((lane >> 4) & 1) * 8 + (lane & 7)) * 40 +
                                  kk * 16 + ((lane >> 3) & 1) * 8));
                mma16h(acc[0][2 * nb], af[0], bq);
                mma16h(acc[1][2 * nb], af[1], bq);
                mma16h(acc[0][2 * nb + 1], af[0], bq + 2);
                mma16h(acc[1][2 * nb + 1], af[1], bq + 2);
            }
        }
    }

#pragma unroll
    for (int mt = 0; mt < 2; mt++)
#pragma unroll
        for (int nt = 0; nt < 8; nt++)
#pragma unroll
            for (int rg = 0; rg < 4; rg++) {
                int row = m0 + wm + mt * 16 + (lane >> 2) + ((rg & 2) ? 8 : 0);
                int col = n0 + wn + nt * 8 + 2 * (lane & 3) + (rg & 1);
                float v = acc[mt][nt][rg] + bias[col];
                if (MODE == 0) {
                    int b = row >> 10, i = row & 1023;
                    int h = col >> 6, dc = col & 63;
                    size_t idx = ((size_t)((h << 3) + b) * NSEQ + i) * DHEAD + dc;
                    g_Qh[idx] = v;
                    g_Qh16[idx] = __float2half_rn(v);
                } else {
                    v = fmaxf(v, 0.f) + A[(size_t)row * 512 + col];
                    g_T[(size_t)row * 512 + col] = v;
                }
            }
}

// ---------------------------------------------------------------------------
// LayerNorm. mode 0: merge heads g_Oh -> LN -> g_X ; mode 1: g_T -> LN -> out
// ---------------------------------------------------------------------------
__global__ void __launch_bounds__(512) ln_kernel(const float* __restrict__ gg,
                                                 const float* __restrict__ bb,
                                                 float* __restrict__ out, int mode) {
    int m = blockIdx.x;
    int t = threadIdx.x;
    float val;
    if (mode == 0) {
        int b = m >> 10, i = m & 1023, h = t >> 6, dc = t & 63;
        val = g_Oh[(((h << 3) + b) * NSEQ + i) * DHEAD + dc];
    } else {
        val = g_T[(size_t)m * 512 + t];
    }
    float s = val, q = val * val;
#pragma unroll
    for (int off = 16; off; off >>= 1) {
        s += __shfl_xor_sync(0xffffffffu, s, off);
        q += __shfl_xor_sync(0xffffffffu, q, off);
    }
    __shared__ float ss[16], sq[16];
    int w = t >> 5, lane = t & 31;
    if (!lane) { ss[w] = s; sq[w] = q; }
    __syncthreads();
    float S = 0.f, Q2 = 0.f;
#pragma unroll
    for (int k = 0; k < 16; k++) { S += ss[k]; Q2 += sq[k]; }
    float mean = S * (1.f / 512.f);
    float var = Q2 * (1.f / 512.f) - mean * mean;
    float y = (val - mean) * rsqrtf(var + 1e-5f) * gg[t] + bb[t];
    if (mode == 0) g_X[(size_t)m * 512 + t] = y;
    else           out[(size_t)m * 512 + t] = y;
}

// ---------------------------------------------------------------------------
extern "C" void kernel_launch(void* const* d_in, const int* in_sizes, int n_in,
                              void* d_out, int out_size) {
    (void)in_sizes; (void)n_in; (void)out_size;
    const float* Q  = (const float*)d_in[0];
    // d_in[1] = K, unused by the reference forward
    const float* Wq = (const float*)d_in[2];
    const float* bq = (const float*)d_in[3];
    const float* Wo = (const float*)d_in[4];
    const float* bo = (const float*)d_in[5];
    const float* g0 = (const float*)d_in[6];
    const float* b0 = (const float*)d_in[7];
    const float* g1 = (const float*)d_in[8];
    const float* b1 = (const float*)d_in[9];
    float* out = (float*)d_out;

    const int SMEM_AV = (9216 * 3 + 17408) * 2 + (128 + 256) * 4;  // 90496 B
    cudaFuncSetAttribute(sink_av_kernel,
                         cudaFuncAttributeMaxDynamicSharedMemorySize, SMEM_AV);

    dim3 ggrid(4, 64);    // N/128, M/128
    dim3 sgrid(36, 64);   // triangular tile pairs, bh
    dim3 agrid(8, 64);    // row-blocks, bh

    gemm512h<0><<<ggrid, 256>>>(Q, Wq, bq);
    sym_lse<0><<<sgrid, 256>>>();
    fin_kernel<0><<<64, 1024>>>();
    sym_lse<1><<<sgrid, 256>>>();
    fin_kernel<1><<<64, 1024>>>();
    sink_av_kernel<<<agrid, 256, SMEM_AV>>>();
    ln_kernel<<<8192, 512>>>(g0, b0, nullptr, 0);
    gemm512h<1><<<ggrid, 256>>>(nullptr, Wo, bo);
    ln_kernel<<<8192, 512>>>(g1, b1, out, 1);
}

// round 7
// speedup vs baseline: 1.5354x; 1.0786x over previous
#include <cuda_runtime.h>
#include <cuda_fp16.h>
#include <math.h>
#include <stdint.h>

// Problem constants: B=8, n=1024, dQ=dV=512, H=8, d=64, HB=64
#define NSEQ   1024
#define DHEAD  64
#define DVTOT  512
#define NBATCH 8
#define NHB    64

#define SSCALE 0.044194173824159216f   // 1/sqrt(512)
#define LOGMU  (-6.9314615657f)        // log(1/1024 + 1e-8)

// Scratch (device globals; no allocation allowed)
__device__ float  g_Qh [NHB * NSEQ * DHEAD];   // head-major Q_ fp32 (residual)
__device__ __half g_Qh16[NHB * NSEQ * DHEAD];  // head-major Q_ fp16 (mma operand)
__device__ float  g_Oh [NHB * NSEQ * DHEAD];   // head-major O_
__device__ float  g_u  [NHB * NSEQ];
__device__ float  g_v  [NHB * NSEQ];
__device__ float  g_X  [NBATCH * NSEQ * DVTOT];
__device__ float  g_T  [NBATCH * NSEQ * DVTOT];
// partial sums for symmetric LSE passes: [bh][k=0..7][1024]
__device__ float  g_part[NHB * 8 * NSEQ];

// ---------------------------------------------------------------------------
// helpers
// ---------------------------------------------------------------------------
__device__ __forceinline__ void mma16h(float* c, const unsigned* a, const unsigned* b) {
    asm volatile(
        "mma.sync.aligned.m16n8k16.row.col.f32.f16.f16.f32 "
        "{%0,%1,%2,%3},{%4,%5,%6,%7},{%8,%9},{%0,%1,%2,%3};\n"
        : "+f"(c[0]), "+f"(c[1]), "+f"(c[2]), "+f"(c[3])
        : "r"(a[0]), "r"(a[1]), "r"(a[2]), "r"(a[3]), "r"(b[0]), "r"(b[1]));
}
__device__ __forceinline__ unsigned smaddr(const void* p) {
    return (unsigned)__cvta_generic_to_shared(p);
}
__device__ __forceinline__ void ldm_x4(unsigned* r, unsigned a) {
    asm volatile("ldmatrix.sync.aligned.m8n8.x4.shared.b16 {%0,%1,%2,%3},[%4];"
                 : "=r"(r[0]), "=r"(r[1]), "=r"(r[2]), "=r"(r[3]) : "r"(a));
}
__device__ __forceinline__ void ldm_x4t(unsigned* r, unsigned a) {
    asm volatile("ldmatrix.sync.aligned.m8n8.x4.trans.shared.b16 {%0,%1,%2,%3},[%4];"
                 : "=r"(r[0]), "=r"(r[1]), "=r"(r[2]), "=r"(r[3]) : "r"(a));
}
__device__ __forceinline__ unsigned fh2(float a, float b) {
    __half2 h = __floats2half2_rn(a, b);
    return *(unsigned*)&h;
}
__device__ __forceinline__ void cpa16(unsigned s, const void* g) {
    asm volatile("cp.async.ca.shared.global [%0], [%1], 16;" :: "r"(s), "l"(g) : "memory");
}
__device__ __forceinline__ void cpa_commit() {
    asm volatile("cp.async.commit_group;" ::: "memory");
}
template <int N>
__device__ __forceinline__ void cpa_wait() {
    asm volatile("cp.async.wait_group %0;" :: "n"(N) : "memory");
}

// ---------------------------------------------------------------------------
// Symmetric-tile LSE pass (unchanged from R6). One CTA per (a,b), a<=b.
// ---------------------------------------------------------------------------
template <int MODE>
__global__ void __launch_bounds__(256, 2) sym_lse() {
    __shared__ __align__(16) __half Qi[128 * 72];
    __shared__ __align__(16) __half Qj[128 * 72];
    __shared__ float csh[4][128];
    __shared__ float ps[256];
    __shared__ float eua[128], eub[128];

    const int bh = blockIdx.y;
    int a = 0, tt = blockIdx.x;
    while (tt >= 8 - a) { tt -= 8 - a; a++; }
    const int b = a + tt;

    const int tid = threadIdx.x, lane = tid & 31, w = tid >> 5;
    const int mw = w & 3, w2 = w >> 2;
    const int wm = mw * 32, wn = w2 * 64;
    const __half* Qb = g_Qh16 + (size_t)bh * (NSEQ * DHEAD);

#pragma unroll
    for (int r = 0; r < 4; r++) {
        int idx = tid + r * 256;
        int row = idx >> 3, q = (idx & 7) * 8;
        cpa16(smaddr(Qi + row * 72 + q), Qb + (size_t)(a * 128 + row) * DHEAD + q);
        cpa16(smaddr(Qj + row * 72 + q), Qb + (size_t)(b * 128 + row) * DHEAD + q);
    }
    if (MODE == 1 && tid < 128) {
        eua[tid] = __expf(g_u[bh * NSEQ + a * 128 + tid]);
        eub[tid] = __expf(g_u[bh * NSEQ + b * 128 + tid]);
    }
    cpa_commit();
    cpa_wait<0>();
    __syncthreads();

    float sa[2][8][4];
#pragma unroll
    for (int x = 0; x < 2; x++)
#pragma unroll
        for (int y = 0; y < 8; y++)
#pragma unroll
            for (int z = 0; z < 4; z++) sa[x][y][z] = 0.f;

#pragma unroll
    for (int kk = 0; kk < 4; kk++) {
        unsigned af0[4], af1[4];
        {
            int col = kk * 16 + (lane >> 4) * 8;
            ldm_x4(af0, smaddr(Qi + (wm + (lane & 15)) * 72 + col));
            ldm_x4(af1, smaddr(Qi + (wm + 16 + (lane & 15)) * 72 + col));
        }
#pragma unroll
        for (int nb = 0; nb < 4; nb++) {
            unsigned bq[4];
            ldm_x4(bq, smaddr(Qj + (wn + nb * 16 + ((lane >> 4) & 1) * 8 + (lane & 7)) * 72 +
                              kk * 16 + ((lane >> 3) & 1) * 8));
            mma16h(sa[0][2 * nb], af0, bq);
            mma16h(sa[1][2 * nb], af1, bq);
            mma16h(sa[0][2 * nb + 1], af0, bq + 2);
            mma16h(sa[1][2 * nb + 1], af1, bq + 2);
        }
    }

    float eu4[2][2];
    if (MODE == 1) {
#pragma unroll
        for (int mt = 0; mt < 2; mt++)
#pragma unroll
            for (int h = 0; h < 2; h++)
                eu4[mt][h] = eua[wm + mt * 16 + (lane >> 2) + h * 8];
    }

    float ls[2][2] = {{0.f, 0.f}, {0.f, 0.f}};
    float cp[8][2];
#pragma unroll
    for (int nt = 0; nt < 8; nt++) { cp[nt][0] = 0.f; cp[nt][1] = 0.f; }

#pragma unroll
    for (int mt = 0; mt < 2; mt++)
#pragma unroll
        for (int nt = 0; nt < 8; nt++) {
            int colb = wn + nt * 8 + 2 * (lane & 3);
#pragma unroll
            for (int rg = 0; rg < 4; rg++) {
                float e = __expf(sa[mt][nt][rg] * SSCALE);
                int h = rg >> 1, d = rg & 1;
                if (MODE == 0) {
                    ls[mt][h] += e;
                    cp[nt][d] += e;
                } else {
                    ls[mt][h] += eub[colb + d] * e;
                    cp[nt][d] += eu4[mt][h] * e;
                }
            }
        }

#pragma unroll
    for (int mt = 0; mt < 2; mt++)
#pragma unroll
        for (int h = 0; h < 2; h++) {
            float v = ls[mt][h];
            v += __shfl_xor_sync(0xffffffffu, v, 1);
            v += __shfl_xor_sync(0xffffffffu, v, 2);
            if ((lane & 3) == 0)
                ps[w2 * 128 + wm + mt * 16 + (lane >> 2) + h * 8] = v;
        }

#pragma unroll
    for (int nt = 0; nt < 8; nt++)
#pragma unroll
        for (int d = 0; d < 2; d++) {
            float v = cp[nt][d];
            v += __shfl_xor_sync(0xffffffffu, v, 4);
            v += __shfl_xor_sync(0xffffffffu, v, 8);
            v += __shfl_xor_sync(0xffffffffu, v, 16);
            cp[nt][d] = v;
        }
    if (lane < 4) {
#pragma unroll
        for (int nt = 0; nt < 8; nt++) {
            csh[mw][wn + nt * 8 + 2 * lane + 0] = cp[nt][0];
            csh[mw][wn + nt * 8 + 2 * lane + 1] = cp[nt][1];
        }
    }
    __syncthreads();

    if (tid < 128) {
        if (MODE == 0 || a != b) {
            float rs = ps[tid] + ps[128 + tid];
            g_part[((size_t)bh * 8 + b) * NSEQ + a * 128 + tid] = rs;
        }
        if (MODE == 1 || a != b) {
            float cs = csh[0][tid] + csh[1][tid] + csh[2][tid] + csh[3][tid];
            g_part[((size_t)bh * 8 + a) * NSEQ + b * 128 + tid] = cs;
        }
    }
}

// finalize: sum the 8 partial slots, take LOGMU - log. M=0 -> g_u, M=1 -> g_v
template <int M>
__global__ void __launch_bounds__(1024) fin_kernel() {
    int bh = blockIdx.x, pos = threadIdx.x;
    float s = 0.f;
#pragma unroll
    for (int k = 0; k < 8; k++)
        s += g_part[((size_t)bh * 8 + k) * NSEQ + pos];
    float r = LOGMU - __logf(s);
    if (M == 0) g_u[bh * NSEQ + pos] = r;
    else        g_v[bh * NSEQ + pos] = r;
}

// ---------------------------------------------------------------------------
// Pass C: O_ = Q_ + (1024 * exp(S + u_i + v_j)) @ Q_.
// NEW: 8 warps x 16 rows each; phase-1 C-fragments are exp'ed/scaled/packed in
// registers and used DIRECTLY as phase-2 A-fragments (no Ap smem tile).
// Each j-tile processed in two 64-column halves to bound register pressure.
// ---------------------------------------------------------------------------
__global__ void __launch_bounds__(256, 2) sink_av_kernel() {
    extern __shared__ __align__(16) char smraw[];
    __half* Qi = (__half*)smraw;                 // 128*72
    __half* QjA = Qi + 9216;                     // 128*72 (buf 0)
    __half* QjB = QjA + 9216;                    // 128*72 (buf 1)
    float* vb = (float*)(QjB + 9216);            // 2 x 128

    const int bh = blockIdx.y;
    const int i0 = blockIdx.x * 128;
    const int tid = threadIdx.x, lane = tid & 31, w = tid >> 5;
    const int wm = w * 16;                        // warp's 16-row block
    const __half* Qb = g_Qh16 + (size_t)bh * (NSEQ * DHEAD);
    const float* Qf32 = g_Qh + (size_t)bh * (NSEQ * DHEAD);
    float* Obase = g_Oh + (size_t)bh * (NSEQ * DHEAD);
    __half* Qbuf[2] = { QjA, QjB };

#pragma unroll
    for (int r = 0; r < 4; r++) {
        int idx = tid + r * 256;
        int row = idx >> 3, q = (idx & 7) * 8;
        *(float4*)(Qi + row * 72 + q) =
            *(const float4*)(Qb + (size_t)(i0 + row) * DHEAD + q);
    }
#pragma unroll
    for (int r = 0; r < 4; r++) {
        int idx = tid + r * 256;
        int row = idx >> 3, q = (idx & 7) * 8;
        cpa16(smaddr(QjA + row * 72 + q), Qb + (size_t)row * DHEAD + q);
    }
    if (tid < 128) vb[tid] = g_v[bh * NSEQ + tid];
    cpa_commit();

    // per-thread row scales: u for rows wm + (lane>>2) and +8
    const float u0 = g_u[bh * NSEQ + i0 + wm + (lane >> 2)];
    const float u1 = g_u[bh * NSEQ + i0 + wm + (lane >> 2) + 8];
    __syncthreads();

    // hoisted A fragments of Qi (warp's 16 rows, all 64 k)
    unsigned af[4][4];
#pragma unroll
    for (int kk = 0; kk < 4; kk++)
        ldm_x4(af[kk], smaddr(Qi + (wm + (lane & 15)) * 72 + kk * 16 + (lane >> 4) * 8));

    float oa[8][4];
#pragma unroll
    for (int y = 0; y < 8; y++)
#pragma unroll
        for (int z = 0; z < 4; z++) oa[y][z] = 0.f;

    for (int jt = 0; jt < 8; jt++) {
        __syncthreads();
        if (jt < 7) {
            int j0 = (jt + 1) * 128, buf = (jt + 1) & 1;
#pragma unroll
            for (int r = 0; r < 4; r++) {
                int idx = tid + r * 256;
                int row = idx >> 3, q = (idx & 7) * 8;
                cpa16(smaddr(Qbuf[buf] + row * 72 + q),
                      Qb + (size_t)(j0 + row) * DHEAD + q);
            }
            if (tid < 128) vb[((jt + 1) & 1) * 128 + tid] = g_v[bh * NSEQ + j0 + tid];
            cpa_commit();
            cpa_wait<1>();
        } else {
            cpa_wait<0>();
        }
        __syncthreads();

        const __half* Qc = Qbuf[jt & 1];
        const float* vv = vb + (jt & 1) * 128;

#pragma unroll
        for (int h = 0; h < 2; h++) {
            const int jb = h * 64;
            // ---- phase 1: S for warp's 16 rows x 64 j-cols ----
            float sa[8][4];
#pragma unroll
            for (int y = 0; y < 8; y++)
#pragma unroll
                for (int z = 0; z < 4; z++) sa[y][z] = 0.f;

#pragma unroll
            for (int kk = 0; kk < 4; kk++) {
#pragma unroll
                for (int nb = 0; nb < 4; nb++) {
                    unsigned bq[4];
                    ldm_x4(bq, smaddr(Qc + (jb + nb * 16 + ((lane >> 4) & 1) * 8 + (lane & 7)) * 72 +
                                      kk * 16 + ((lane >> 3) & 1) * 8));
                    mma16h(sa[2 * nb], af[kk], bq);
                    mma16h(sa[2 * nb + 1], af[kk], bq + 2);
                }
            }

            // ---- exp + scale + pack straight into phase-2 A fragments ----
            unsigned ak[4][4];
#pragma unroll
            for (int s2 = 0; s2 < 4; s2++) {
                const float* s0 = sa[2 * s2];
                const float* s1 = sa[2 * s2 + 1];
                int c0 = jb + s2 * 16 + 2 * (lane & 3);
                int c8 = c0 + 8;
                ak[s2][0] = fh2(1024.f * __expf(s0[0] * SSCALE + u0 + vv[c0]),
                                1024.f * __expf(s0[1] * SSCALE + u0 + vv[c0 + 1]));
                ak[s2][1] = fh2(1024.f * __expf(s0[2] * SSCALE + u1 + vv[c0]),
                                1024.f * __expf(s0[3] * SSCALE + u1 + vv[c0 + 1]));
                ak[s2][2] = fh2(1024.f * __expf(s1[0] * SSCALE + u0 + vv[c8]),
                                1024.f * __expf(s1[1] * SSCALE + u0 + vv[c8 + 1]));
                ak[s2][3] = fh2(1024.f * __expf(s1[2] * SSCALE + u1 + vv[c8]),
                                1024.f * __expf(s1[3] * SSCALE + u1 + vv[c8 + 1]));
            }

            // ---- phase 2: O(warp 16 rows x 64 d) += A @ Qj (K = these 64 j) ----
#pragma unroll
            for (int s2 = 0; s2 < 4; s2++) {
#pragma unroll
                for (int nb = 0; nb < 4; nb++) {
                    unsigned bq[4];
                    ldm_x4t(bq, smaddr(Qc + (jb + s2 * 16 + (lane & 15)) * 72 +
                                       nb * 16 + ((lane >> 4) & 1) * 8));
                    mma16h(oa[2 * nb], ak[s2], bq);
                    mma16h(oa[2 * nb + 1], ak[s2], bq + 2);
                }
            }
        }
    }

    // epilogue: O_ = Q_ + accum (residual in fp32)
#pragma unroll
    for (int nt = 0; nt < 8; nt++)
#pragma unroll
        for (int rg = 0; rg < 4; rg++) {
            int row = i0 + wm + (lane >> 2) + ((rg & 2) ? 8 : 0);
            int col = nt * 8 + 2 * (lane & 3) + (rg & 1);
            Obase[(size_t)row * DHEAD + col] = oa[nt][rg] + Qf32[(size_t)row * DHEAD + col];
        }
}

// ---------------------------------------------------------------------------
// fp16 GEMM: C[8192,512] = A[8192,512] * W[512,512]^T (+bias, epilogues)
// ---------------------------------------------------------------------------
template <int MODE>
__global__ void __launch_bounds__(256, 2) gemm512h(const float* __restrict__ Ain,
                                                   const float* __restrict__ W,
                                                   const float* __restrict__ bias) {
    __shared__ __align__(16) __half As[128 * 40];
    __shared__ __align__(16) __half Bs[128 * 40];
    const float* A = (MODE == 0) ? Ain : (const float*)g_X;

    const int m0 = blockIdx.y * 128, n0 = blockIdx.x * 128;
    const int tid = threadIdx.x, lane = tid & 31, w = tid >> 5;
    const int wm = (w & 3) * 32, wn = (w >> 2) * 64;

    float acc[2][8][4];
#pragma unroll
    for (int x = 0; x < 2; x++)
#pragma unroll
        for (int y = 0; y < 8; y++)
#pragma unroll
            for (int z = 0; z < 4; z++) acc[x][y][z] = 0.f;

    for (int k0 = 0; k0 < 512; k0 += 32) {
        __syncthreads();
#pragma unroll
        for (int c = 0; c < 2; c++) {
            int idx = tid + c * 256;
            int row = idx >> 2, q = (idx & 3) * 8;
            float4 v0 = *(const float4*)(A + (size_t)(m0 + row) * 512 + k0 + q);
            float4 v1 = *(const float4*)(A + (size_t)(m0 + row) * 512 + k0 + q + 4);
            uint4 pa;
            pa.x = fh2(v0.x, v0.y); pa.y = fh2(v0.z, v0.w);
            pa.z = fh2(v1.x, v1.y); pa.w = fh2(v1.z, v1.w);
            *(uint4*)(As + row * 40 + q) = pa;
            float4 w0 = *(const float4*)(W + (size_t)(n0 + row) * 512 + k0 + q);
            float4 w1 = *(const float4*)(W + (size_t)(n0 + row) * 512 + k0 + q + 4);
            uint4 pb;
            pb.x = fh2(w0.x, w0.y); pb.y = fh2(w0.z, w0.w);
            pb.z = fh2(w1.x, w1.y); pb.w = fh2(w1.z, w1.w);
            *(uint4*)(Bs + row * 40 + q) = pb;
        }
        __syncthreads();
#pragma unroll
        for (int kk = 0; kk < 2; kk++) {
            unsigned af[2][4];
#pragma unroll
            for (int mt = 0; mt < 2; mt++)
                ldm_x4(af[mt], smaddr(As + (wm + mt * 16 + (lane & 15)) * 40 +
                                      kk * 16 + (lane >> 4) * 8));
#pragma unroll
            for (int nb = 0; nb < 4; nb++) {
                unsigned bq[4];
                ldm_x4(bq, smaddr(Bs + (wn + nb * 16 + ((lane >> 4) & 1) * 8 + (lane & 7)) * 40 +
                                  kk * 16 + ((lane >> 3) & 1) * 8));
                mma16h(acc[0][2 * nb], af[0], bq);
                mma16h(acc[1][2 * nb], af[1], bq);
                mma16h(acc[0][2 * nb + 1], af[0], bq + 2);
                mma16h(acc[1][2 * nb + 1], af[1], bq + 2);
            }
        }
    }

#pragma unroll
    for (int mt = 0; mt < 2; mt++)
#pragma unroll
        for (int nt = 0; nt < 8; nt++)
#pragma unroll
            for (int rg = 0; rg < 4; rg++) {
                int row = m0 + wm + mt * 16 + (lane >> 2) + ((rg & 2) ? 8 : 0);
                int col = n0 + wn + nt * 8 + 2 * (lane & 3) + (rg & 1);
                float v = acc[mt][nt][rg] + bias[col];
                if (MODE == 0) {
                    int b = row >> 10, i = row & 1023;
                    int h = col >> 6, dc = col & 63;
                    size_t idx = ((size_t)((h << 3) + b) * NSEQ + i) * DHEAD + dc;
                    g_Qh[idx] = v;
                    g_Qh16[idx] = __float2half_rn(v);
                } else {
                    v = fmaxf(v, 0.f) + A[(size_t)row * 512 + col];
                    g_T[(size_t)row * 512 + col] = v;
                }
            }
}

// ---------------------------------------------------------------------------
// LayerNorm. mode 0: merge heads g_Oh -> LN -> g_X ; mode 1: g_T -> LN -> out
// ---------------------------------------------------------------------------
__global__ void __launch_bounds__(512) ln_kernel(const float* __restrict__ gg,
                                                 const float* __restrict__ bb,
                                                 float* __restrict__ out, int mode) {
    int m = blockIdx.x;
    int t = threadIdx.x;
    float val;
    if (mode == 0) {
        int b = m >> 10, i = m & 1023, h = t >> 6, dc = t & 63;
        val = g_Oh[(((h << 3) + b) * NSEQ + i) * DHEAD + dc];
    } else {
        val = g_T[(size_t)m * 512 + t];
    }
    float s = val, q = val * val;
#pragma unroll
    for (int off = 16; off; off >>= 1) {
        s += __shfl_xor_sync(0xffffffffu, s, off);
        q += __shfl_xor_sync(0xffffffffu, q, off);
    }
    __shared__ float ss[16], sq[16];
    int w = t >> 5, lane = t & 31;
    if (!lane) { ss[w] = s; sq[w] = q; }
    __syncthreads();
    float S = 0.f, Q2 = 0.f;
#pragma unroll
    for (int k = 0; k < 16; k++) { S += ss[k]; Q2 += sq[k]; }
    float mean = S * (1.f / 512.f);
    float var = Q2 * (1.f / 512.f) - mean * mean;
    float y = (val - mean) * rsqrtf(var + 1e-5f) * gg[t] + bb[t];
    if (mode == 0) g_X[(size_t)m * 512 + t] = y;
    else           out[(size_t)m * 512 + t] = y;
}

// ---------------------------------------------------------------------------
extern "C" void kernel_launch(void* const* d_in, const int* in_sizes, int n_in,
                              void* d_out, int out_size) {
    (void)in_sizes; (void)n_in; (void)out_size;
    const float* Q  = (const float*)d_in[0];
    // d_in[1] = K, unused by the reference forward
    const float* Wq = (const float*)d_in[2];
    const float* bq = (const float*)d_in[3];
    const float* Wo = (const float*)d_in[4];
    const float* bo = (const float*)d_in[5];
    const float* g0 = (const float*)d_in[6];
    const float* b0 = (const float*)d_in[7];
    const float* g1 = (const float*)d_in[8];
    const float* b1 = (const float*)d_in[9];
    float* out = (float*)d_out;

    const int SMEM_AV = 9216 * 3 * 2 + 256 * 4;  // 56320 B
    cudaFuncSetAttribute(sink_av_kernel,
                         cudaFuncAttributeMaxDynamicSharedMemorySize, SMEM_AV);

    dim3 ggrid(4, 64);    // N/128, M/128
    dim3 sgrid(36, 64);   // triangular tile pairs, bh
    dim3 agrid(8, 64);    // row-blocks, bh

    gemm512h<0><<<ggrid, 256>>>(Q, Wq, bq);
    sym_lse<0><<<sgrid, 256>>>();
    fin_kernel<0><<<64, 1024>>>();
    sym_lse<1><<<sgrid, 256>>>();
    fin_kernel<1><<<64, 1024>>>();
    sink_av_kernel<<<agrid, 256, SMEM_AV>>>();
    ln_kernel<<<8192, 512>>>(g0, b0, nullptr, 0);
    gemm512h<1><<<ggrid, 256>>>(nullptr, Wo, bo);
    ln_kernel<<<8192, 512>>>(g1, b1, out, 1);
}

// round 8
// speedup vs baseline: 1.5903x; 1.0357x over previous
#include <cuda_runtime.h>
#include <cuda_fp16.h>
#include <math.h>
#include <stdint.h>

// Problem constants: B=8, n=1024, dQ=dV=512, H=8, d=64, HB=64
#define NSEQ   1024
#define DHEAD  64
#define DVTOT  512
#define NBATCH 8
#define NHB    64

#define SSCALE 0.044194173824159216f   // 1/sqrt(512)
#define LOGMU  (-6.9314615657f)        // log(1/1024 + 1e-8)
#define MUVAL  (0.0009765725f)         // 1/1024 + 1e-8

// Scratch (device globals; no allocation allowed)
__device__ float  g_Qh [NHB * NSEQ * DHEAD];   // head-major Q_ fp32 (residual)
__device__ __half g_Qh16[NHB * NSEQ * DHEAD];  // head-major Q_ fp16 (mma operand)
__device__ float  g_Oh [NHB * NSEQ * DHEAD];   // head-major O_
__device__ float  g_X  [NBATCH * NSEQ * DVTOT];
__device__ __half g_X16[NBATCH * NSEQ * DVTOT];
__device__ float  g_T  [NBATCH * NSEQ * DVTOT];
__device__ __half g_A16[NBATCH * NSEQ * DVTOT];  // fp16 Q input
__device__ __half g_W16q[DVTOT * DVTOT];
__device__ __half g_W16o[DVTOT * DVTOT];
// partial sums: g_part (pass 0, row/col sums of P) ; g_part2 (pass 1, for v)
__device__ float  g_part [NHB * 8 * NSEQ];
__device__ float  g_part2[NHB * 8 * NSEQ];

// ---------------------------------------------------------------------------
// helpers
// ---------------------------------------------------------------------------
__device__ __forceinline__ void mma16h(float* c, const unsigned* a, const unsigned* b) {
    asm volatile(
        "mma.sync.aligned.m16n8k16.row.col.f32.f16.f16.f32 "
        "{%0,%1,%2,%3},{%4,%5,%6,%7},{%8,%9},{%0,%1,%2,%3};\n"
        : "+f"(c[0]), "+f"(c[1]), "+f"(c[2]), "+f"(c[3])
        : "r"(a[0]), "r"(a[1]), "r"(a[2]), "r"(a[3]), "r"(b[0]), "r"(b[1]));
}
__device__ __forceinline__ unsigned smaddr(const void* p) {
    return (unsigned)__cvta_generic_to_shared(p);
}
__device__ __forceinline__ void ldm_x4(unsigned* r, unsigned a) {
    asm volatile("ldmatrix.sync.aligned.m8n8.x4.shared.b16 {%0,%1,%2,%3},[%4];"
                 : "=r"(r[0]), "=r"(r[1]), "=r"(r[2]), "=r"(r[3]) : "r"(a));
}
__device__ __forceinline__ void ldm_x4t(unsigned* r, unsigned a) {
    asm volatile("ldmatrix.sync.aligned.m8n8.x4.trans.shared.b16 {%0,%1,%2,%3},[%4];"
                 : "=r"(r[0]), "=r"(r[1]), "=r"(r[2]), "=r"(r[3]) : "r"(a));
}
__device__ __forceinline__ unsigned fh2(float a, float b) {
    __half2 h = __floats2half2_rn(a, b);
    return *(unsigned*)&h;
}
__device__ __forceinline__ void cpa16(unsigned s, const void* g) {
    asm volatile("cp.async.ca.shared.global [%0], [%1], 16;" :: "r"(s), "l"(g) : "memory");
}
__device__ __forceinline__ void cpa_commit() {
    asm volatile("cp.async.commit_group;" ::: "memory");
}
template <int N>
__device__ __forceinline__ void cpa_wait() {
    asm volatile("cp.async.wait_group %0;" :: "n"(N) : "memory");
}

// ---------------------------------------------------------------------------
// fp32 -> fp16 conversion for GEMM operands (Q, Wq, Wo). One launch.
// 4718592 floats / 8 per thread = 589824 threads = 2304 blocks x 256.
// ---------------------------------------------------------------------------
__global__ void __launch_bounds__(256) cvt_kernel(const float* __restrict__ Q,
                                                  const float* __restrict__ Wq,
                                                  const float* __restrict__ Wo) {
    size_t t = ((size_t)blockIdx.x * 256 + threadIdx.x) * 8;
    const float* src;
    __half* dst;
    size_t off;
    if (t < 4194304) { src = Q;  dst = g_A16;  off = t; }
    else if (t < 4456448) { src = Wq; dst = g_W16q; off = t - 4194304; }
    else { src = Wo; dst = g_W16o; off = t - 4456448; }
    float4 a = *(const float4*)(src + off);
    float4 b = *(const float4*)(src + off + 4);
    uint4 p;
    p.x = fh2(a.x, a.y); p.y = fh2(a.z, a.w);
    p.z = fh2(b.x, b.y); p.w = fh2(b.z, b.w);
    *(uint4*)(dst + off) = p;
}

// ---------------------------------------------------------------------------
// Symmetric-tile LSE pass. One CTA per (a,b), a<=b (36 pairs x 64 bh).
// MODE 0: partials of rowsum/colsum of P = exp(S*scale) -> g_part
// MODE 1: e^u derived from g_part (e^u = MUVAL / rowsum); weighted partials
//         for v -> g_part2
// ---------------------------------------------------------------------------
template <int MODE>
__global__ void __launch_bounds__(256, 2) sym_lse() {
    __shared__ __align__(16) __half Qi[128 * 72];
    __shared__ __align__(16) __half Qj[128 * 72];
    __shared__ float csh[4][128];
    __shared__ float ps[256];
    __shared__ float eua[128], eub[128];

    const int bh = blockIdx.y;
    int a = 0, tt = blockIdx.x;
    while (tt >= 8 - a) { tt -= 8 - a; a++; }
    const int b = a + tt;

    const int tid = threadIdx.x, lane = tid & 31, w = tid >> 5;
    const int mw = w & 3, w2 = w >> 2;
    const int wm = mw * 32, wn = w2 * 64;
    const __half* Qb = g_Qh16 + (size_t)bh * (NSEQ * DHEAD);

#pragma unroll
    for (int r = 0; r < 4; r++) {
        int idx = tid + r * 256;
        int row = idx >> 3, q = (idx & 7) * 8;
        cpa16(smaddr(Qi + row * 72 + q), Qb + (size_t)(a * 128 + row) * DHEAD + q);
        cpa16(smaddr(Qj + row * 72 + q), Qb + (size_t)(b * 128 + row) * DHEAD + q);
    }
    if (MODE == 1 && tid < 128) {
        float sa_ = 0.f, sb_ = 0.f;
#pragma unroll
        for (int k = 0; k < 8; k++) {
            sa_ += g_part[((size_t)bh * 8 + k) * NSEQ + a * 128 + tid];
            sb_ += g_part[((size_t)bh * 8 + k) * NSEQ + b * 128 + tid];
        }
        eua[tid] = MUVAL / sa_;
        eub[tid] = MUVAL / sb_;
    }
    cpa_commit();
    cpa_wait<0>();
    __syncthreads();

    float sa[2][8][4];
#pragma unroll
    for (int x = 0; x < 2; x++)
#pragma unroll
        for (int y = 0; y < 8; y++)
#pragma unroll
            for (int z = 0; z < 4; z++) sa[x][y][z] = 0.f;

#pragma unroll
    for (int kk = 0; kk < 4; kk++) {
        unsigned af0[4], af1[4];
        {
            int col = kk * 16 + (lane >> 4) * 8;
            ldm_x4(af0, smaddr(Qi + (wm + (lane & 15)) * 72 + col));
            ldm_x4(af1, smaddr(Qi + (wm + 16 + (lane & 15)) * 72 + col));
        }
#pragma unroll
        for (int nb = 0; nb < 4; nb++) {
            unsigned bq[4];
            ldm_x4(bq, smaddr(Qj + (wn + nb * 16 + ((lane >> 4) & 1) * 8 + (lane & 7)) * 72 +
                              kk * 16 + ((lane >> 3) & 1) * 8));
            mma16h(sa[0][2 * nb], af0, bq);
            mma16h(sa[1][2 * nb], af1, bq);
            mma16h(sa[0][2 * nb + 1], af0, bq + 2);
            mma16h(sa[1][2 * nb + 1], af1, bq + 2);
        }
    }

    float eu4[2][2];
    if (MODE == 1) {
#pragma unroll
        for (int mt = 0; mt < 2; mt++)
#pragma unroll
            for (int h = 0; h < 2; h++)
                eu4[mt][h] = eua[wm + mt * 16 + (lane >> 2) + h * 8];
    }

    float ls[2][2] = {{0.f, 0.f}, {0.f, 0.f}};
    float cp[8][2];
#pragma unroll
    for (int nt = 0; nt < 8; nt++) { cp[nt][0] = 0.f; cp[nt][1] = 0.f; }

#pragma unroll
    for (int mt = 0; mt < 2; mt++)
#pragma unroll
        for (int nt = 0; nt < 8; nt++) {
            int colb = wn + nt * 8 + 2 * (lane & 3);
#pragma unroll
            for (int rg = 0; rg < 4; rg++) {
                float e = __expf(sa[mt][nt][rg] * SSCALE);
                int h = rg >> 1, d = rg & 1;
                if (MODE == 0) {
                    ls[mt][h] += e;
                    cp[nt][d] += e;
                } else {
                    ls[mt][h] += eub[colb + d] * e;
                    cp[nt][d] += eu4[mt][h] * e;
                }
            }
        }

#pragma unroll
    for (int mt = 0; mt < 2; mt++)
#pragma unroll
        for (int h = 0; h < 2; h++) {
            float v = ls[mt][h];
            v += __shfl_xor_sync(0xffffffffu, v, 1);
            v += __shfl_xor_sync(0xffffffffu, v, 2);
            if ((lane & 3) == 0)
                ps[w2 * 128 + wm + mt * 16 + (lane >> 2) + h * 8] = v;
        }

#pragma unroll
    for (int nt = 0; nt < 8; nt++)
#pragma unroll
        for (int d = 0; d < 2; d++) {
            float v = cp[nt][d];
            v += __shfl_xor_sync(0xffffffffu, v, 4);
            v += __shfl_xor_sync(0xffffffffu, v, 8);
            v += __shfl_xor_sync(0xffffffffu, v, 16);
            cp[nt][d] = v;
        }
    if (lane < 4) {
#pragma unroll
        for (int nt = 0; nt < 8; nt++) {
            csh[mw][wn + nt * 8 + 2 * lane + 0] = cp[nt][0];
            csh[mw][wn + nt * 8 + 2 * lane + 1] = cp[nt][1];
        }
    }
    __syncthreads();

    float* dst = (MODE == 0) ? g_part : g_part2;
    if (tid < 128) {
        if (MODE == 0 || a != b) {
            float rs = ps[tid] + ps[128 + tid];
            dst[((size_t)bh * 8 + b) * NSEQ + a * 128 + tid] = rs;
        }
        if (MODE == 1 || a != b) {
            float cs = csh[0][tid] + csh[1][tid] + csh[2][tid] + csh[3][tid];
            dst[((size_t)bh * 8 + a) * NSEQ + b * 128 + tid] = cs;
        }
    }
}

// ---------------------------------------------------------------------------
// Pass C: O_ = Q_ + (1024 * exp(S + u_i + v_j)) @ Q_.
// u, v derived inline from g_part / g_part2 (LOGMU - log(sum of 8 slots)).
// 8 warps x 16 rows; phase-1 C-fragments exp'ed/scaled/packed in registers
// and used directly as phase-2 A-fragments.
// ---------------------------------------------------------------------------
__global__ void __launch_bounds__(256, 2) sink_av_kernel() {
    extern __shared__ __align__(16) char smraw[];
    __half* Qi = (__half*)smraw;                 // 128*72
    __half* QjA = Qi + 9216;                     // 128*72 (buf 0)
    __half* QjB = QjA + 9216;                    // 128*72 (buf 1)
    float* vb = (float*)(QjB + 9216);            // 2 x 128

    const int bh = blockIdx.y;
    const int i0 = blockIdx.x * 128;
    const int tid = threadIdx.x, lane = tid & 31, w = tid >> 5;
    const int wm = w * 16;
    const __half* Qb = g_Qh16 + (size_t)bh * (NSEQ * DHEAD);
    const float* Qf32 = g_Qh + (size_t)bh * (NSEQ * DHEAD);
    float* Obase = g_Oh + (size_t)bh * (NSEQ * DHEAD);
    __half* Qbuf[2] = { QjA, QjB };

#pragma unroll
    for (int r = 0; r < 4; r++) {
        int idx = tid + r * 256;
        int row = idx >> 3, q = (idx & 7) * 8;
        *(float4*)(Qi + row * 72 + q) =
            *(const float4*)(Qb + (size_t)(i0 + row) * DHEAD + q);
    }
#pragma unroll
    for (int r = 0; r < 4; r++) {
        int idx = tid + r * 256;
        int row = idx >> 3, q = (idx & 7) * 8;
        cpa16(smaddr(QjA + row * 72 + q), Qb + (size_t)row * DHEAD + q);
    }
    if (tid < 128) {
        float s = 0.f;
#pragma unroll
        for (int k = 0; k < 8; k++)
            s += g_part2[((size_t)bh * 8 + k) * NSEQ + tid];
        vb[tid] = LOGMU - __logf(s);
    }
    cpa_commit();

    // per-thread row biases u (rows wm + (lane>>2) and +8)
    float r0s = 0.f, r1s = 0.f;
#pragma unroll
    for (int k = 0; k < 8; k++) {
        r0s += g_part[((size_t)bh * 8 + k) * NSEQ + i0 + wm + (lane >> 2)];
        r1s += g_part[((size_t)bh * 8 + k) * NSEQ + i0 + wm + (lane >> 2) + 8];
    }
    const float u0 = LOGMU - __logf(r0s);
    const float u1 = LOGMU - __logf(r1s);
    __syncthreads();

    unsigned af[4][4];
#pragma unroll
    for (int kk = 0; kk < 4; kk++)
        ldm_x4(af[kk], smaddr(Qi + (wm + (lane & 15)) * 72 + kk * 16 + (lane >> 4) * 8));

    float oa[8][4];
#pragma unroll
    for (int y = 0; y < 8; y++)
#pragma unroll
        for (int z = 0; z < 4; z++) oa[y][z] = 0.f;

    for (int jt = 0; jt < 8; jt++) {
        __syncthreads();
        if (jt < 7) {
            int j0 = (jt + 1) * 128, buf = (jt + 1) & 1;
#pragma unroll
            for (int r = 0; r < 4; r++) {
                int idx = tid + r * 256;
                int row = idx >> 3, q = (idx & 7) * 8;
                cpa16(smaddr(Qbuf[buf] + row * 72 + q),
                      Qb + (size_t)(j0 + row) * DHEAD + q);
            }
            if (tid < 128) {
                float s = 0.f;
#pragma unroll
                for (int k = 0; k < 8; k++)
                    s += g_part2[((size_t)bh * 8 + k) * NSEQ + j0 + tid];
                vb[buf * 128 + tid] = LOGMU - __logf(s);
            }
            cpa_commit();
            cpa_wait<1>();
        } else {
            cpa_wait<0>();
        }
        __syncthreads();

        const __half* Qc = Qbuf[jt & 1];
        const float* vv = vb + (jt & 1) * 128;

#pragma unroll
        for (int h = 0; h < 2; h++) {
            const int jb = h * 64;
            float sa[8][4];
#pragma unroll
            for (int y = 0; y < 8; y++)
#pragma unroll
                for (int z = 0; z < 4; z++) sa[y][z] = 0.f;

#pragma unroll
            for (int kk = 0; kk < 4; kk++) {
#pragma unroll
                for (int nb = 0; nb < 4; nb++) {
                    unsigned bq[4];
                    ldm_x4(bq, smaddr(Qc + (jb + nb * 16 + ((lane >> 4) & 1) * 8 + (lane & 7)) * 72 +
                                      kk * 16 + ((lane >> 3) & 1) * 8));
                    mma16h(sa[2 * nb], af[kk], bq);
                    mma16h(sa[2 * nb + 1], af[kk], bq + 2);
                }
            }

            unsigned ak[4][4];
#pragma unroll
            for (int s2 = 0; s2 < 4; s2++) {
                const float* s0 = sa[2 * s2];
                const float* s1 = sa[2 * s2 + 1];
                int c0 = jb + s2 * 16 + 2 * (lane & 3);
                int c8 = c0 + 8;
                ak[s2][0] = fh2(1024.f * __expf(s0[0] * SSCALE + u0 + vv[c0]),
                                1024.f * __expf(s0[1] * SSCALE + u0 + vv[c0 + 1]));
                ak[s2][1] = fh2(1024.f * __expf(s0[2] * SSCALE + u1 + vv[c0]),
                                1024.f * __expf(s0[3] * SSCALE + u1 + vv[c0 + 1]));
                ak[s2][2] = fh2(1024.f * __expf(s1[0] * SSCALE + u0 + vv[c8]),
                                1024.f * __expf(s1[1] * SSCALE + u0 + vv[c8 + 1]));
                ak[s2][3] = fh2(1024.f * __expf(s1[2] * SSCALE + u1 + vv[c8]),
                                1024.f * __expf(s1[3] * SSCALE + u1 + vv[c8 + 1]));
            }

#pragma unroll
            for (int s2 = 0; s2 < 4; s2++) {
#pragma unroll
                for (int nb = 0; nb < 4; nb++) {
                    unsigned bq[4];
                    ldm_x4t(bq, smaddr(Qc + (jb + s2 * 16 + (lane & 15)) * 72 +
                                       nb * 16 + ((lane >> 4) & 1) * 8));
                    mma16h(oa[2 * nb], ak[s2], bq);
                    mma16h(oa[2 * nb + 1], ak[s2], bq + 2);
                }
            }
        }
    }

#pragma unroll
    for (int nt = 0; nt < 8; nt++)
#pragma unroll
        for (int rg = 0; rg < 4; rg++) {
            int row = i0 + wm + (lane >> 2) + ((rg & 2) ? 8 : 0);
            int col = nt * 8 + 2 * (lane & 3) + (rg & 1);
            Obase[(size_t)row * DHEAD + col] = oa[nt][rg] + Qf32[(size_t)row * DHEAD + col];
        }
}

// ---------------------------------------------------------------------------
// fp16 GEMM, cp.async double-buffered: C[8192,512] = A * W^T (+bias, epilogue)
// MODE 0: A = g_A16 (converted Q); scatter head-major into g_Qh + g_Qh16
// MODE 1: A = g_X16; g_T = g_X + relu(C + bias)
// ---------------------------------------------------------------------------
template <int MODE>
__global__ void __launch_bounds__(256, 2) gemm512h(const float* __restrict__ bias) {
    __shared__ __align__(16) __half As[2][128 * 40];
    __shared__ __align__(16) __half Bs[2][128 * 40];
    const __half* A16 = MODE ? g_X16 : g_A16;
    const __half* W16 = MODE ? g_W16o : g_W16q;

    const int m0 = blockIdx.y * 128, n0 = blockIdx.x * 128;
    const int tid = threadIdx.x, lane = tid & 31, w = tid >> 5;
    const int wm = (w & 3) * 32, wn = (w >> 2) * 64;

    float acc[2][8][4];
#pragma unroll
    for (int x = 0; x < 2; x++)
#pragma unroll
        for (int y = 0; y < 8; y++)
#pragma unroll
            for (int z = 0; z < 4; z++) acc[x][y][z] = 0.f;

    // preload stage 0
#pragma unroll
    for (int c = 0; c < 2; c++) {
        int idx = tid + c * 256;
        int row = idx >> 2, ch = (idx & 3) * 8;
        cpa16(smaddr(&As[0][row * 40 + ch]), A16 + (size_t)(m0 + row) * 512 + ch);
        cpa16(smaddr(&Bs[0][row * 40 + ch]), W16 + (size_t)(n0 + row) * 512 + ch);
    }
    cpa_commit();

    for (int kt = 0; kt < 16; kt++) {
        __syncthreads();     // previous compute done before overwriting buffer
        if (kt < 15) {
            int s = (kt + 1) & 1, k0 = (kt + 1) * 32;
#pragma unroll
            for (int c = 0; c < 2; c++) {
                int idx = tid + c * 256;
                int row = idx >> 2, ch = (idx & 3) * 8;
                cpa16(smaddr(&As[s][row * 40 + ch]), A16 + (size_t)(m0 + row) * 512 + k0 + ch);
                cpa16(smaddr(&Bs[s][row * 40 + ch]), W16 + (size_t)(n0 + row) * 512 + k0 + ch);
            }
            cpa_commit();
            cpa_wait<1>();
        } else {
            cpa_wait<0>();
        }
        __syncthreads();

        const __half* as = As[kt & 1];
        const __half* bs = Bs[kt & 1];
#pragma unroll
        for (int kk = 0; kk < 2; kk++) {
            unsigned af[2][4];
#pragma unroll
            for (int mt = 0; mt < 2; mt++)
                ldm_x4(af[mt], smaddr(as + (wm + mt * 16 + (lane & 15)) * 40 +
                                      kk * 16 + (lane >> 4) * 8));
#pragma unroll
            for (int nb = 0; nb < 4; nb++) {
                unsigned bq[4];
                ldm_x4(bq, smaddr(bs + (wn + nb * 16 + ((lane >> 4) & 1) * 8 + (lane & 7)) * 40 +
                                  kk * 16 + ((lane >> 3) & 1) * 8));
                mma16h(acc[0][2 * nb], af[0], bq);
                mma16h(acc[1][2 * nb], af[1], bq);
                mma16h(acc[0][2 * nb + 1], af[0], bq + 2);
                mma16h(acc[1][2 * nb + 1], af[1], bq + 2);
            }
        }
    }

#pragma unroll
    for (int mt = 0; mt < 2; mt++)
#pragma unroll
        for (int nt = 0; nt < 8; nt++)
#pragma unroll
            for (int rg = 0; rg < 4; rg++) {
                int row = m0 + wm + mt * 16 + (lane >> 2) + ((rg & 2) ? 8 : 0);
                int col = n0 + wn + nt * 8 + 2 * (lane & 3) + (rg & 1);
                float v = acc[mt][nt][rg] + bias[col];
                if (MODE == 0) {
                    int b = row >> 10, i = row & 1023;
                    int h = col >> 6, dc = col & 63;
                    size_t idx = ((size_t)((h << 3) + b) * NSEQ + i) * DHEAD + dc;
                    g_Qh[idx] = v;
                    g_Qh16[idx] = __float2half_rn(v);
                } else {
                    v = fmaxf(v, 0.f) + g_X[(size_t)row * 512 + col];
                    g_T[(size_t)row * 512 + col] = v;
                }
            }
}

// ---------------------------------------------------------------------------
// LayerNorm. mode 0: merge heads g_Oh -> LN -> g_X (+ g_X16)
//            mode 1: g_T -> LN -> out
// ---------------------------------------------------------------------------
__global__ void __launch_bounds__(512) ln_kernel(const float* __restrict__ gg,
                                                 const float* __restrict__ bb,
                                                 float* __restrict__ out, int mode) {
    int m = blockIdx.x;
    int t = threadIdx.x;
    float val;
    if (mode == 0) {
        int b = m >> 10, i = m & 1023, h = t >> 6, dc = t & 63;
        val = g_Oh[(((h << 3) + b) * NSEQ + i) * DHEAD + dc];
    } else {
        val = g_T[(size_t)m * 512 + t];
    }
    float s = val, q = val * val;
#pragma unroll
    for (int off = 16; off; off >>= 1) {
        s += __shfl_xor_sync(0xffffffffu, s, off);
        q += __shfl_xor_sync(0xffffffffu, q, off);
    }
    __shared__ float ss[16], sq[16];
    int w = t >> 5, lane = t & 31;
    if (!lane) { ss[w] = s; sq[w] = q; }
    __syncthreads();
    float S = 0.f, Q2 = 0.f;
#pragma unroll
    for (int k = 0; k < 16; k++) { S += ss[k]; Q2 += sq[k]; }
    float mean = S * (1.f / 512.f);
    float var = Q2 * (1.f / 512.f) - mean * mean;
    float y = (val - mean) * rsqrtf(var + 1e-5f) * gg[t] + bb[t];
    if (mode == 0) {
        g_X[(size_t)m * 512 + t] = y;
        g_X16[(size_t)m * 512 + t] = __float2half_rn(y);
    } else {
        out[(size_t)m * 512 + t] = y;
    }
}

// ---------------------------------------------------------------------------
extern "C" void kernel_launch(void* const* d_in, const int* in_sizes, int n_in,
                              void* d_out, int out_size) {
    (void)in_sizes; (void)n_in; (void)out_size;
    const float* Q  = (const float*)d_in[0];
    // d_in[1] = K, unused by the reference forward
    const float* Wq = (const float*)d_in[2];
    const float* bq = (const float*)d_in[3];
    const float* Wo = (const float*)d_in[4];
    const float* bo = (const float*)d_in[5];
    const float* g0 = (const float*)d_in[6];
    const float* b0 = (const float*)d_in[7];
    const float* g1 = (const float*)d_in[8];
    const float* b1 = (const float*)d_in[9];
    float* out = (float*)d_out;

    const int SMEM_AV = 9216 * 3 * 2 + 256 * 4;  // 56320 B
    cudaFuncSetAttribute(sink_av_kernel,
                         cudaFuncAttributeMaxDynamicSharedMemorySize, SMEM_AV);

    dim3 ggrid(4, 64);    // N/128, M/128
    dim3 sgrid(36, 64);   // triangular tile pairs, bh
    dim3 agrid(8, 64);    // row-blocks, bh

    cvt_kernel<<<2304, 256>>>(Q, Wq, Wo);
    gemm512h<0><<<ggrid, 256>>>(bq);
    sym_lse<0><<<sgrid, 256>>>();
    sym_lse<1><<<sgrid, 256>>>();
    sink_av_kernel<<<agrid, 256, SMEM_AV>>>();
    ln_kernel<<<8192, 512>>>(g0, b0, nullptr, 0);
    gemm512h<1><<<ggrid, 256>>>(bo);
    ln_kernel<<<8192, 512>>>(g1, b1, out, 1);
}

// round 9
// speedup vs baseline: 1.8452x; 1.1603x over previous
#include <cuda_runtime.h>
#include <cuda_fp16.h>
#include <math.h>
#include <stdint.h>

// Problem constants: B=8, n=1024, dQ=dV=512, H=8, d=64, HB=64
#define NSEQ   1024
#define DHEAD  64
#define DVTOT  512
#define NBATCH 8
#define NHB    64

#define SSCALE 0.044194173824159216f   // 1/sqrt(512)
#define LOG2E  1.4426950408889634f
#define SS2    (SSCALE * LOG2E)        // exp(s*SSCALE) = ex2(s*SS2)
#define LOGMU  (-6.9314615657f)        // log(1/1024 + 1e-8)
#define MUVAL  (0.0009765725f)         // 1/1024 + 1e-8

// Scratch (device globals; no allocation allowed)
__device__ float  g_Qh [NHB * NSEQ * DHEAD];   // head-major Q_ fp32 (residual)
__device__ __half g_Qh16[NHB * NSEQ * DHEAD];  // head-major Q_ fp16 (mma operand)
__device__ float  g_Oh [NHB * NSEQ * DHEAD];   // head-major O_
__device__ float  g_X  [NBATCH * NSEQ * DVTOT];
__device__ __half g_X16[NBATCH * NSEQ * DVTOT];
__device__ float  g_T  [NBATCH * NSEQ * DVTOT];
__device__ __half g_A16[NBATCH * NSEQ * DVTOT];  // fp16 Q input
__device__ __half g_W16q[DVTOT * DVTOT];
__device__ __half g_W16o[DVTOT * DVTOT];
// partial sums: g_part (pass 0, row/col sums of P) ; g_part2 (pass 1, for v)
__device__ float  g_part [NHB * 8 * NSEQ];
__device__ float  g_part2[NHB * 8 * NSEQ];

// ---------------------------------------------------------------------------
// helpers
// ---------------------------------------------------------------------------
__device__ __forceinline__ void mma16h(float* c, const unsigned* a, const unsigned* b) {
    asm volatile(
        "mma.sync.aligned.m16n8k16.row.col.f32.f16.f16.f32 "
        "{%0,%1,%2,%3},{%4,%5,%6,%7},{%8,%9},{%0,%1,%2,%3};\n"
        : "+f"(c[0]), "+f"(c[1]), "+f"(c[2]), "+f"(c[3])
        : "r"(a[0]), "r"(a[1]), "r"(a[2]), "r"(a[3]), "r"(b[0]), "r"(b[1]));
}
__device__ __forceinline__ unsigned smaddr(const void* p) {
    return (unsigned)__cvta_generic_to_shared(p);
}
__device__ __forceinline__ void ldm_x4(unsigned* r, unsigned a) {
    asm volatile("ldmatrix.sync.aligned.m8n8.x4.shared.b16 {%0,%1,%2,%3},[%4];"
                 : "=r"(r[0]), "=r"(r[1]), "=r"(r[2]), "=r"(r[3]) : "r"(a));
}
__device__ __forceinline__ void ldm_x4t(unsigned* r, unsigned a) {
    asm volatile("ldmatrix.sync.aligned.m8n8.x4.trans.shared.b16 {%0,%1,%2,%3},[%4];"
                 : "=r"(r[0]), "=r"(r[1]), "=r"(r[2]), "=r"(r[3]) : "r"(a));
}
__device__ __forceinline__ unsigned fh2(float a, float b) {
    __half2 h = __floats2half2_rn(a, b);
    return *(unsigned*)&h;
}
__device__ __forceinline__ float ex2(float x) {
    float r;
    asm("ex2.approx.ftz.f32 %0, %1;" : "=f"(r) : "f"(x));
    return r;
}
__device__ __forceinline__ void cpa16(unsigned s, const void* g) {
    asm volatile("cp.async.ca.shared.global [%0], [%1], 16;" :: "r"(s), "l"(g) : "memory");
}
__device__ __forceinline__ void cpa_commit() {
    asm volatile("cp.async.commit_group;" ::: "memory");
}
template <int N>
__device__ __forceinline__ void cpa_wait() {
    asm volatile("cp.async.wait_group %0;" :: "n"(N) : "memory");
}

// ---------------------------------------------------------------------------
// fp32 -> fp16 conversion for GEMM operands (Q, Wq, Wo). One launch.
// ---------------------------------------------------------------------------
__global__ void __launch_bounds__(256) cvt_kernel(const float* __restrict__ Q,
                                                  const float* __restrict__ Wq,
                                                  const float* __restrict__ Wo) {
    size_t t = ((size_t)blockIdx.x * 256 + threadIdx.x) * 8;
    const float* src;
    __half* dst;
    size_t off;
    if (t < 4194304) { src = Q;  dst = g_A16;  off = t; }
    else if (t < 4456448) { src = Wq; dst = g_W16q; off = t - 4194304; }
    else { src = Wo; dst = g_W16o; off = t - 4456448; }
    float4 a = *(const float4*)(src + off);
    float4 b = *(const float4*)(src + off + 4);
    uint4 p;
    p.x = fh2(a.x, a.y); p.y = fh2(a.z, a.w);
    p.z = fh2(b.x, b.y); p.w = fh2(b.z, b.w);
    *(uint4*)(dst + off) = p;
}

// ---------------------------------------------------------------------------
// Symmetric-tile LSE pass. One CTA per (a,b), a<=b (36 pairs x 64 bh).
// MODE 0: partials of rowsum/colsum of P = exp(S*scale) -> g_part
// MODE 1: e^u derived from g_part; weighted partials for v -> g_part2
// ---------------------------------------------------------------------------
template <int MODE>
__global__ void __launch_bounds__(256, 2) sym_lse() {
    __shared__ __align__(16) __half Qi[128 * 72];
    __shared__ __align__(16) __half Qj[128 * 72];
    __shared__ float csh[4][128];
    __shared__ float ps[256];
    __shared__ float eua[128], eub[128];

    const int bh = blockIdx.y;
    int a = 0, tt = blockIdx.x;
    while (tt >= 8 - a) { tt -= 8 - a; a++; }
    const int b = a + tt;

    const int tid = threadIdx.x, lane = tid & 31, w = tid >> 5;
    const int mw = w & 3, w2 = w >> 2;
    const int wm = mw * 32, wn = w2 * 64;
    const __half* Qb = g_Qh16 + (size_t)bh * (NSEQ * DHEAD);

#pragma unroll
    for (int r = 0; r < 4; r++) {
        int idx = tid + r * 256;
        int row = idx >> 3, q = (idx & 7) * 8;
        cpa16(smaddr(Qi + row * 72 + q), Qb + (size_t)(a * 128 + row) * DHEAD + q);
        cpa16(smaddr(Qj + row * 72 + q), Qb + (size_t)(b * 128 + row) * DHEAD + q);
    }
    if (MODE == 1 && tid < 128) {
        float sa_ = 0.f, sb_ = 0.f;
#pragma unroll
        for (int k = 0; k < 8; k++) {
            sa_ += g_part[((size_t)bh * 8 + k) * NSEQ + a * 128 + tid];
            sb_ += g_part[((size_t)bh * 8 + k) * NSEQ + b * 128 + tid];
        }
        eua[tid] = MUVAL / sa_;
        eub[tid] = MUVAL / sb_;
    }
    cpa_commit();
    cpa_wait<0>();
    __syncthreads();

    float sa[2][8][4];
#pragma unroll
    for (int x = 0; x < 2; x++)
#pragma unroll
        for (int y = 0; y < 8; y++)
#pragma unroll
            for (int z = 0; z < 4; z++) sa[x][y][z] = 0.f;

#pragma unroll
    for (int kk = 0; kk < 4; kk++) {
        unsigned af0[4], af1[4];
        {
            int col = kk * 16 + (lane >> 4) * 8;
            ldm_x4(af0, smaddr(Qi + (wm + (lane & 15)) * 72 + col));
            ldm_x4(af1, smaddr(Qi + (wm + 16 + (lane & 15)) * 72 + col));
        }
#pragma unroll
        for (int nb = 0; nb < 4; nb++) {
            unsigned bq[4];
            ldm_x4(bq, smaddr(Qj + (wn + nb * 16 + ((lane >> 4) & 1) * 8 + (lane & 7)) * 72 +
                              kk * 16 + ((lane >> 3) & 1) * 8));
            mma16h(sa[0][2 * nb], af0, bq);
            mma16h(sa[1][2 * nb], af1, bq);
            mma16h(sa[0][2 * nb + 1], af0, bq + 2);
            mma16h(sa[1][2 * nb + 1], af1, bq + 2);
        }
    }

    float eu4[2][2];
    if (MODE == 1) {
#pragma unroll
        for (int mt = 0; mt < 2; mt++)
#pragma unroll
            for (int h = 0; h < 2; h++)
                eu4[mt][h] = eua[wm + mt * 16 + (lane >> 2) + h * 8];
    }

    float ls[2][2] = {{0.f, 0.f}, {0.f, 0.f}};
    float cp[8][2];
#pragma unroll
    for (int nt = 0; nt < 8; nt++) { cp[nt][0] = 0.f; cp[nt][1] = 0.f; }

#pragma unroll
    for (int mt = 0; mt < 2; mt++)
#pragma unroll
        for (int nt = 0; nt < 8; nt++) {
            int colb = wn + nt * 8 + 2 * (lane & 3);
#pragma unroll
            for (int rg = 0; rg < 4; rg++) {
                float e = ex2(sa[mt][nt][rg] * SS2);
                int h = rg >> 1, d = rg & 1;
                if (MODE == 0) {
                    ls[mt][h] += e;
                    cp[nt][d] += e;
                } else {
                    ls[mt][h] += eub[colb + d] * e;
                    cp[nt][d] += eu4[mt][h] * e;
                }
            }
        }

#pragma unroll
    for (int mt = 0; mt < 2; mt++)
#pragma unroll
        for (int h = 0; h < 2; h++) {
            float v = ls[mt][h];
            v += __shfl_xor_sync(0xffffffffu, v, 1);
            v += __shfl_xor_sync(0xffffffffu, v, 2);
            if ((lane & 3) == 0)
                ps[w2 * 128 + wm + mt * 16 + (lane >> 2) + h * 8] = v;
        }

#pragma unroll
    for (int nt = 0; nt < 8; nt++)
#pragma unroll
        for (int d = 0; d < 2; d++) {
            float v = cp[nt][d];
            v += __shfl_xor_sync(0xffffffffu, v, 4);
            v += __shfl_xor_sync(0xffffffffu, v, 8);
            v += __shfl_xor_sync(0xffffffffu, v, 16);
            cp[nt][d] = v;
        }
    if (lane < 4) {
#pragma unroll
        for (int nt = 0; nt < 8; nt++) {
            csh[mw][wn + nt * 8 + 2 * lane + 0] = cp[nt][0];
            csh[mw][wn + nt * 8 + 2 * lane + 1] = cp[nt][1];
        }
    }
    __syncthreads();

    float* dst = (MODE == 0) ? g_part : g_part2;
    if (tid < 128) {
        if (MODE == 0 || a != b) {
            float rs = ps[tid] + ps[128 + tid];
            dst[((size_t)bh * 8 + b) * NSEQ + a * 128 + tid] = rs;
        }
        if (MODE == 1 || a != b) {
            float cs = csh[0][tid] + csh[1][tid] + csh[2][tid] + csh[3][tid];
            dst[((size_t)bh * 8 + a) * NSEQ + b * 128 + tid] = cs;
        }
    }
}

// ---------------------------------------------------------------------------
// Pass C: O_ = Q_ + (1024 * exp(S + u_i + v_j)) @ Q_.
// u, v derived inline from g_part/g_part2 and carried in log2 units with the
// 1024 = 2^10 factor folded into u. 8 warps x 16 rows; phase-1 C-fragments
// exp'ed/packed in registers as phase-2 A-fragments.
// ---------------------------------------------------------------------------
__global__ void __launch_bounds__(256, 2) sink_av_kernel() {
    extern __shared__ __align__(16) char smraw[];
    __half* Qi = (__half*)smraw;                 // 128*72
    __half* QjA = Qi + 9216;                     // 128*72 (buf 0)
    __half* QjB = QjA + 9216;                    // 128*72 (buf 1)
    float* vb = (float*)(QjB + 9216);            // 2 x 128 (log2 units)

    const int bh = blockIdx.y;
    const int i0 = blockIdx.x * 128;
    const int tid = threadIdx.x, lane = tid & 31, w = tid >> 5;
    const int wm = w * 16;
    const __half* Qb = g_Qh16 + (size_t)bh * (NSEQ * DHEAD);
    const float* Qf32 = g_Qh + (size_t)bh * (NSEQ * DHEAD);
    float* Obase = g_Oh + (size_t)bh * (NSEQ * DHEAD);
    __half* Qbuf[2] = { QjA, QjB };

#pragma unroll
    for (int r = 0; r < 4; r++) {
        int idx = tid + r * 256;
        int row = idx >> 3, q = (idx & 7) * 8;
        *(float4*)(Qi + row * 72 + q) =
            *(const float4*)(Qb + (size_t)(i0 + row) * DHEAD + q);
    }
#pragma unroll
    for (int r = 0; r < 4; r++) {
        int idx = tid + r * 256;
        int row = idx >> 3, q = (idx & 7) * 8;
        cpa16(smaddr(QjA + row * 72 + q), Qb + (size_t)row * DHEAD + q);
    }
    if (tid < 128) {
        float s = 0.f;
#pragma unroll
        for (int k = 0; k < 8; k++)
            s += g_part2[((size_t)bh * 8 + k) * NSEQ + tid];
        vb[tid] = (LOGMU - __logf(s)) * LOG2E;
    }
    cpa_commit();

    // per-thread row biases in log2 units, 1024 folded in (+10)
    float r0s = 0.f, r1s = 0.f;
#pragma unroll
    for (int k = 0; k < 8; k++) {
        r0s += g_part[((size_t)bh * 8 + k) * NSEQ + i0 + wm + (lane >> 2)];
        r1s += g_part[((size_t)bh * 8 + k) * NSEQ + i0 + wm + (lane >> 2) + 8];
    }
    const float u0 = (LOGMU - __logf(r0s)) * LOG2E + 10.f;
    const float u1 = (LOGMU - __logf(r1s)) * LOG2E + 10.f;
    __syncthreads();

    unsigned af[4][4];
#pragma unroll
    for (int kk = 0; kk < 4; kk++)
        ldm_x4(af[kk], smaddr(Qi + (wm + (lane & 15)) * 72 + kk * 16 + (lane >> 4) * 8));

    float oa[8][4];
#pragma unroll
    for (int y = 0; y < 8; y++)
#pragma unroll
        for (int z = 0; z < 4; z++) oa[y][z] = 0.f;

    for (int jt = 0; jt < 8; jt++) {
        __syncthreads();
        if (jt < 7) {
            int j0 = (jt + 1) * 128, buf = (jt + 1) & 1;
#pragma unroll
            for (int r = 0; r < 4; r++) {
                int idx = tid + r * 256;
                int row = idx >> 3, q = (idx & 7) * 8;
                cpa16(smaddr(Qbuf[buf] + row * 72 + q),
                      Qb + (size_t)(j0 + row) * DHEAD + q);
            }
            if (tid < 128) {
                float s = 0.f;
#pragma unroll
                for (int k = 0; k < 8; k++)
                    s += g_part2[((size_t)bh * 8 + k) * NSEQ + j0 + tid];
                vb[buf * 128 + tid] = (LOGMU - __logf(s)) * LOG2E;
            }
            cpa_commit();
            cpa_wait<1>();
        } else {
            cpa_wait<0>();
        }
        __syncthreads();

        const __half* Qc = Qbuf[jt & 1];
        const float* vv = vb + (jt & 1) * 128;

#pragma unroll
        for (int h = 0; h < 2; h++) {
            const int jb = h * 64;
            float sa[8][4];
#pragma unroll
            for (int y = 0; y < 8; y++)
#pragma unroll
                for (int z = 0; z < 4; z++) sa[y][z] = 0.f;

#pragma unroll
            for (int kk = 0; kk < 4; kk++) {
#pragma unroll
                for (int nb = 0; nb < 4; nb++) {
                    unsigned bq[4];
                    ldm_x4(bq, smaddr(Qc + (jb + nb * 16 + ((lane >> 4) & 1) * 8 + (lane & 7)) * 72 +
                                      kk * 16 + ((lane >> 3) & 1) * 8));
                    mma16h(sa[2 * nb], af[kk], bq);
                    mma16h(sa[2 * nb + 1], af[kk], bq + 2);
                }
            }

            unsigned ak[4][4];
#pragma unroll
            for (int s2 = 0; s2 < 4; s2++) {
                const float* s0 = sa[2 * s2];
                const float* s1 = sa[2 * s2 + 1];
                int c0 = jb + s2 * 16 + 2 * (lane & 3);
                int c8 = c0 + 8;
                ak[s2][0] = fh2(ex2(s0[0] * SS2 + u0 + vv[c0]),
                                ex2(s0[1] * SS2 + u0 + vv[c0 + 1]));
                ak[s2][1] = fh2(ex2(s0[2] * SS2 + u1 + vv[c0]),
                                ex2(s0[3] * SS2 + u1 + vv[c0 + 1]));
                ak[s2][2] = fh2(ex2(s1[0] * SS2 + u0 + vv[c8]),
                                ex2(s1[1] * SS2 + u0 + vv[c8 + 1]));
                ak[s2][3] = fh2(ex2(s1[2] * SS2 + u1 + vv[c8]),
                                ex2(s1[3] * SS2 + u1 + vv[c8 + 1]));
            }

#pragma unroll
            for (int s2 = 0; s2 < 4; s2++) {
#pragma unroll
                for (int nb = 0; nb < 4; nb++) {
                    unsigned bq[4];
                    ldm_x4t(bq, smaddr(Qc + (jb + s2 * 16 + (lane & 15)) * 72 +
                                       nb * 16 + ((lane >> 4) & 1) * 8));
                    mma16h(oa[2 * nb], ak[s2], bq);
                    mma16h(oa[2 * nb + 1], ak[s2], bq + 2);
                }
            }
        }
    }

    // epilogue: O_ = Q_ + accum, vectorized float2 loads/stores
#pragma unroll
    for (int nt = 0; nt < 8; nt++) {
        int row = i0 + wm + (lane >> 2);
        int col = nt * 8 + 2 * (lane & 3);
        float2 q0 = *(const float2*)(Qf32 + (size_t)row * DHEAD + col);
        float2 o0 = { oa[nt][0] + q0.x, oa[nt][1] + q0.y };
        *(float2*)(Obase + (size_t)row * DHEAD + col) = o0;
        int row8 = row + 8;
        float2 q1 = *(const float2*)(Qf32 + (size_t)row8 * DHEAD + col);
        float2 o1 = { oa[nt][2] + q1.x, oa[nt][3] + q1.y };
        *(float2*)(Obase + (size_t)row8 * DHEAD + col) = o1;
    }
}

// ---------------------------------------------------------------------------
// fp16 GEMM, cp.async double-buffered, BK=64: C[8192,512] = A * W^T (+bias)
// MODE 0: A = g_A16; scatter head-major into g_Qh + g_Qh16 (vectorized)
// MODE 1: A = g_X16; g_T = g_X + relu(C + bias) (vectorized)
// ---------------------------------------------------------------------------
template <int MODE>
__global__ void __launch_bounds__(256, 2) gemm512h(const float* __restrict__ bias) {
    __shared__ __align__(16) __half As[2][128 * 72];
    __shared__ __align__(16) __half Bs[2][128 * 72];
    const __half* A16 = MODE ? g_X16 : g_A16;
    const __half* W16 = MODE ? g_W16o : g_W16q;

    const int m0 = blockIdx.y * 128, n0 = blockIdx.x * 128;
    const int tid = threadIdx.x, lane = tid & 31, w = tid >> 5;
    const int wm = (w & 3) * 32, wn = (w >> 2) * 64;

    float acc[2][8][4];
#pragma unroll
    for (int x = 0; x < 2; x++)
#pragma unroll
        for (int y = 0; y < 8; y++)
#pragma unroll
            for (int z = 0; z < 4; z++) acc[x][y][z] = 0.f;

    // preload stage 0 (BK=64: 128 rows x 64 halves per matrix)
#pragma unroll
    for (int c = 0; c < 4; c++) {
        int idx = tid + c * 256;
        int row = idx >> 3, ch = (idx & 7) * 8;
        cpa16(smaddr(&As[0][row * 72 + ch]), A16 + (size_t)(m0 + row) * 512 + ch);
        cpa16(smaddr(&Bs[0][row * 72 + ch]), W16 + (size_t)(n0 + row) * 512 + ch);
    }
    cpa_commit();

    for (int kt = 0; kt < 8; kt++) {
        __syncthreads();
        if (kt < 7) {
            int s = (kt + 1) & 1, k0 = (kt + 1) * 64;
#pragma unroll
            for (int c = 0; c < 4; c++) {
                int idx = tid + c * 256;
                int row = idx >> 3, ch = (idx & 7) * 8;
                cpa16(smaddr(&As[s][row * 72 + ch]), A16 + (size_t)(m0 + row) * 512 + k0 + ch);
                cpa16(smaddr(&Bs[s][row * 72 + ch]), W16 + (size_t)(n0 + row) * 512 + k0 + ch);
            }
            cpa_commit();
            cpa_wait<1>();
        } else {
            cpa_wait<0>();
        }
        __syncthreads();

        const __half* as = As[kt & 1];
        const __half* bs = Bs[kt & 1];
#pragma unroll
        for (int kk = 0; kk < 4; kk++) {
            unsigned af[2][4];
#pragma unroll
            for (int mt = 0; mt < 2; mt++)
                ldm_x4(af[mt], smaddr(as + (wm + mt * 16 + (lane & 15)) * 72 +
                                      kk * 16 + (lane >> 4) * 8));
#pragma unroll
            for (int nb = 0; nb < 4; nb++) {
                unsigned bq[4];
                ldm_x4(bq, smaddr(bs + (wn + nb * 16 + ((lane >> 4) & 1) * 8 + (lane & 7)) * 72 +
                                  kk * 16 + ((lane >> 3) & 1) * 8));
                mma16h(acc[0][2 * nb], af[0], bq);
                mma16h(acc[1][2 * nb], af[1], bq);
                mma16h(acc[0][2 * nb + 1], af[0], bq + 2);
                mma16h(acc[1][2 * nb + 1], af[1], bq + 2);
            }
        }
    }

    // vectorized epilogue
#pragma unroll
    for (int mt = 0; mt < 2; mt++)
#pragma unroll
        for (int nt = 0; nt < 8; nt++) {
            int row = m0 + wm + mt * 16 + (lane >> 2);
            int col = n0 + wn + nt * 8 + 2 * (lane & 3);
            float b0 = bias[col], b1 = bias[col + 1];
#pragma unroll
            for (int hh = 0; hh < 2; hh++) {
                int rr = row + hh * 8;
                float v0 = acc[mt][nt][2 * hh] + b0;
                float v1 = acc[mt][nt][2 * hh + 1] + b1;
                if (MODE == 0) {
                    int b = rr >> 10, i = rr & 1023;
                    int h = col >> 6, dc = col & 63;
                    size_t idx = ((size_t)((h << 3) + b) * NSEQ + i) * DHEAD + dc;
                    *(float2*)(g_Qh + idx) = make_float2(v0, v1);
                    *(unsigned*)((__half*)g_Qh16 + idx) = fh2(v0, v1);
                } else {
                    float2 x = *(const float2*)(g_X + (size_t)rr * 512 + col);
                    float2 t = { fmaxf(v0, 0.f) + x.x, fmaxf(v1, 0.f) + x.y };
                    *(float2*)(g_T + (size_t)rr * 512 + col) = t;
                }
            }
        }
}

// ---------------------------------------------------------------------------
// LayerNorm. mode 0: merge heads g_Oh -> LN -> g_X (+ g_X16)
//            mode 1: g_T -> LN -> out
// ---------------------------------------------------------------------------
__global__ void __launch_bounds__(512) ln_kernel(const float* __restrict__ gg,
                                                 const float* __restrict__ bb,
                                                 float* __restrict__ out, int mode) {
    int m = blockIdx.x;
    int t = threadIdx.x;
    float val;
    if (mode == 0) {
        int b = m >> 10, i = m & 1023, h = t >> 6, dc = t & 63;
        val = g_Oh[(((h << 3) + b) * NSEQ + i) * DHEAD + dc];
    } else {
        val = g_T[(size_t)m * 512 + t];
    }
    float s = val, q = val * val;
#pragma unroll
    for (int off = 16; off; off >>= 1) {
        s += __shfl_xor_sync(0xffffffffu, s, off);
        q += __shfl_xor_sync(0xffffffffu, q, off);
    }
    __shared__ float ss[16], sq[16];
    int w = t >> 5, lane = t & 31;
    if (!lane) { ss[w] = s; sq[w] = q; }
    __syncthreads();
    float S = 0.f, Q2 = 0.f;
#pragma unroll
    for (int k = 0; k < 16; k++) { S += ss[k]; Q2 += sq[k]; }
    float mean = S * (1.f / 512.f);
    float var = Q2 * (1.f / 512.f) - mean * mean;
    float y = (val - mean) * rsqrtf(var + 1e-5f) * gg[t] + bb[t];
    if (mode == 0) {
        g_X[(size_t)m * 512 + t] = y;
        g_X16[(size_t)m * 512 + t] = __float2half_rn(y);
    } else {
        out[(size_t)m * 512 + t] = y;
    }
}

// ---------------------------------------------------------------------------
extern "C" void kernel_launch(void* const* d_in, const int* in_sizes, int n_in,
                              void* d_out, int out_size) {
    (void)in_sizes; (void)n_in; (void)out_size;
    const float* Q  = (const float*)d_in[0];
    // d_in[1] = K, unused by the reference forward
    const float* Wq = (const float*)d_in[2];
    const float* bq = (const float*)d_in[3];
    const float* Wo = (const float*)d_in[4];
    const float* bo = (const float*)d_in[5];
    const float* g0 = (const float*)d_in[6];
    const float* b0 = (const float*)d_in[7];
    const float* g1 = (const float*)d_in[8];
    const float* b1 = (const float*)d_in[9];
    float* out = (float*)d_out;

    const int SMEM_AV = 9216 * 3 * 2 + 256 * 4;  // 56320 B
    cudaFuncSetAttribute(sink_av_kernel,
                         cudaFuncAttributeMaxDynamicSharedMemorySize, SMEM_AV);

    dim3 ggrid(4, 64);    // N/128, M/128
    dim3 sgrid(36, 64);   // triangular tile pairs, bh
    dim3 agrid(8, 64);    // row-blocks, bh

    cvt_kernel<<<2304, 256>>>(Q, Wq, Wo);
    gemm512h<0><<<ggrid, 256>>>(bq);
    sym_lse<0><<<sgrid, 256>>>();
    sym_lse<1><<<sgrid, 256>>>();
    sink_av_kernel<<<agrid, 256, SMEM_AV>>>();
    ln_kernel<<<8192, 512>>>(g0, b0, nullptr, 0);
    gemm512h<1><<<ggrid, 256>>>(bo);
    ln_kernel<<<8192, 512>>>(g1, b1, out, 1);
}

// round 10
// speedup vs baseline: 1.8634x; 1.0099x over previous
#include <cuda_runtime.h>
#include <cuda_fp16.h>
#include <math.h>
#include <stdint.h>

// Problem constants: B=8, n=1024, dQ=dV=512, H=8, d=64, HB=64
#define NSEQ   1024
#define DHEAD  64
#define DVTOT  512
#define NBATCH 8
#define NHB    64

#define SSCALE 0.044194173824159216f   // 1/sqrt(512)
#define LOG2E  1.4426950408889634f
#define SS2    (SSCALE * LOG2E)        // exp(s*SSCALE) = ex2(s*SS2)
#define LOGMU  (-6.9314615657f)        // log(1/1024 + 1e-8)
#define MUVAL  (0.0009765725f)         // 1/1024 + 1e-8

// Scratch (device globals; no allocation allowed)
__device__ float  g_Qh [NHB * NSEQ * DHEAD];   // head-major Q_ fp32 (residual)
__device__ __half g_Qh16[NHB * NSEQ * DHEAD];  // head-major Q_ fp16 (mma operand)
__device__ float  g_Oh [NHB * NSEQ * DHEAD];   // head-major O_
__device__ float  g_X  [NBATCH * NSEQ * DVTOT];
__device__ __half g_X16[NBATCH * NSEQ * DVTOT];
__device__ float  g_T  [NBATCH * NSEQ * DVTOT];
__device__ __half g_A16[NBATCH * NSEQ * DVTOT];  // fp16 Q input
__device__ __half g_W16q[DVTOT * DVTOT];
__device__ __half g_W16o[DVTOT * DVTOT];
// partial sums: g_part (pass 0, row/col sums of P) ; g_part2 (pass 1, for v)
__device__ float  g_part [NHB * 8 * NSEQ];
__device__ float  g_part2[NHB * 8 * NSEQ];

// ---------------------------------------------------------------------------
// helpers
// ---------------------------------------------------------------------------
__device__ __forceinline__ void mma16h(float* c, const unsigned* a, const unsigned* b) {
    asm volatile(
        "mma.sync.aligned.m16n8k16.row.col.f32.f16.f16.f32 "
        "{%0,%1,%2,%3},{%4,%5,%6,%7},{%8,%9},{%0,%1,%2,%3};\n"
        : "+f"(c[0]), "+f"(c[1]), "+f"(c[2]), "+f"(c[3])
        : "r"(a[0]), "r"(a[1]), "r"(a[2]), "r"(a[3]), "r"(b[0]), "r"(b[1]));
}
__device__ __forceinline__ unsigned smaddr(const void* p) {
    return (unsigned)__cvta_generic_to_shared(p);
}
__device__ __forceinline__ void ldm_x4(unsigned* r, unsigned a) {
    asm volatile("ldmatrix.sync.aligned.m8n8.x4.shared.b16 {%0,%1,%2,%3},[%4];"
                 : "=r"(r[0]), "=r"(r[1]), "=r"(r[2]), "=r"(r[3]) : "r"(a));
}
__device__ __forceinline__ void ldm_x4t(unsigned* r, unsigned a) {
    asm volatile("ldmatrix.sync.aligned.m8n8.x4.trans.shared.b16 {%0,%1,%2,%3},[%4];"
                 : "=r"(r[0]), "=r"(r[1]), "=r"(r[2]), "=r"(r[3]) : "r"(a));
}
__device__ __forceinline__ unsigned fh2(float a, float b) {
    __half2 h = __floats2half2_rn(a, b);
    return *(unsigned*)&h;
}
__device__ __forceinline__ unsigned hmul2u(unsigned a, unsigned b) {
    __half2 r = __hmul2(*(const __half2*)&a, *(const __half2*)&b);
    return *(unsigned*)&r;
}
__device__ __forceinline__ unsigned hadd2u(unsigned a, unsigned b) {
    __half2 r = __hadd2(*(const __half2*)&a, *(const __half2*)&b);
    return *(unsigned*)&r;
}
__device__ __forceinline__ float ex2(float x) {
    float r;
    asm("ex2.approx.ftz.f32 %0, %1;" : "=f"(r) : "f"(x));
    return r;
}
__device__ __forceinline__ unsigned h2ex2(unsigned x) {
    unsigned r;
    asm("ex2.approx.f16x2 %0, %1;" : "=r"(r) : "r"(x));
    return r;
}
__device__ __forceinline__ void cpa16(unsigned s, const void* g) {
    asm volatile("cp.async.ca.shared.global [%0], [%1], 16;" :: "r"(s), "l"(g) : "memory");
}
__device__ __forceinline__ void cpa_commit() {
    asm volatile("cp.async.commit_group;" ::: "memory");
}
template <int N>
__device__ __forceinline__ void cpa_wait() {
    asm volatile("cp.async.wait_group %0;" :: "n"(N) : "memory");
}

// ---------------------------------------------------------------------------
// fp32 -> fp16 conversion for GEMM operands (Q, Wq, Wo). One launch.
// ---------------------------------------------------------------------------
__global__ void __launch_bounds__(256) cvt_kernel(const float* __restrict__ Q,
                                                  const float* __restrict__ Wq,
                                                  const float* __restrict__ Wo) {
    size_t t = ((size_t)blockIdx.x * 256 + threadIdx.x) * 8;
    const float* src;
    __half* dst;
    size_t off;
    if (t < 4194304) { src = Q;  dst = g_A16;  off = t; }
    else if (t < 4456448) { src = Wq; dst = g_W16q; off = t - 4194304; }
    else { src = Wo; dst = g_W16o; off = t - 4456448; }
    float4 a = *(const float4*)(src + off);
    float4 b = *(const float4*)(src + off + 4);
    uint4 p;
    p.x = fh2(a.x, a.y); p.y = fh2(a.z, a.w);
    p.z = fh2(b.x, b.y); p.w = fh2(b.z, b.w);
    *(uint4*)(dst + off) = p;
}

// ---------------------------------------------------------------------------
// Symmetric-tile LSE pass. One CTA per (a,b), a<=b (36 pairs x 64 bh).
// Qi fragments prescaled by SS2 so epilogue is a bare ex2.
// MODE 0: partials of rowsum/colsum of P -> g_part
// MODE 1: e^u from g_part; weighted partials for v -> g_part2
// ---------------------------------------------------------------------------
template <int MODE>
__global__ void __launch_bounds__(256, 2) sym_lse() {
    __shared__ __align__(16) __half Qi[128 * 72];
    __shared__ __align__(16) __half Qj[128 * 72];
    __shared__ float csh[4][128];
    __shared__ float ps[256];
    __shared__ float eua[128], eub[128];

    const int bh = blockIdx.y;
    int a = 0, tt = blockIdx.x;
    while (tt >= 8 - a) { tt -= 8 - a; a++; }
    const int b = a + tt;

    const int tid = threadIdx.x, lane = tid & 31, w = tid >> 5;
    const int mw = w & 3, w2 = w >> 2;
    const int wm = mw * 32, wn = w2 * 64;
    const __half* Qb = g_Qh16 + (size_t)bh * (NSEQ * DHEAD);
    const unsigned HSS2 = fh2(SS2, SS2);

#pragma unroll
    for (int r = 0; r < 4; r++) {
        int idx = tid + r * 256;
        int row = idx >> 3, q = (idx & 7) * 8;
        cpa16(smaddr(Qi + row * 72 + q), Qb + (size_t)(a * 128 + row) * DHEAD + q);
        cpa16(smaddr(Qj + row * 72 + q), Qb + (size_t)(b * 128 + row) * DHEAD + q);
    }
    if (MODE == 1 && tid < 128) {
        float sa_ = 0.f, sb_ = 0.f;
#pragma unroll
        for (int k = 0; k < 8; k++) {
            sa_ += g_part[((size_t)bh * 8 + k) * NSEQ + a * 128 + tid];
            sb_ += g_part[((size_t)bh * 8 + k) * NSEQ + b * 128 + tid];
        }
        eua[tid] = MUVAL / sa_;
        eub[tid] = MUVAL / sb_;
    }
    cpa_commit();
    cpa_wait<0>();
    __syncthreads();

    float sa[2][8][4];
#pragma unroll
    for (int x = 0; x < 2; x++)
#pragma unroll
        for (int y = 0; y < 8; y++)
#pragma unroll
            for (int z = 0; z < 4; z++) sa[x][y][z] = 0.f;

#pragma unroll
    for (int kk = 0; kk < 4; kk++) {
        unsigned af0[4], af1[4];
        {
            int col = kk * 16 + (lane >> 4) * 8;
            ldm_x4(af0, smaddr(Qi + (wm + (lane & 15)) * 72 + col));
            ldm_x4(af1, smaddr(Qi + (wm + 16 + (lane & 15)) * 72 + col));
#pragma unroll
            for (int r = 0; r < 4; r++) {
                af0[r] = hmul2u(af0[r], HSS2);
                af1[r] = hmul2u(af1[r], HSS2);
            }
        }
#pragma unroll
        for (int nb = 0; nb < 4; nb++) {
            unsigned bq[4];
            ldm_x4(bq, smaddr(Qj + (wn + nb * 16 + ((lane >> 4) & 1) * 8 + (lane & 7)) * 72 +
                              kk * 16 + ((lane >> 3) & 1) * 8));
            mma16h(sa[0][2 * nb], af0, bq);
            mma16h(sa[1][2 * nb], af1, bq);
            mma16h(sa[0][2 * nb + 1], af0, bq + 2);
            mma16h(sa[1][2 * nb + 1], af1, bq + 2);
        }
    }

    float eu4[2][2];
    if (MODE == 1) {
#pragma unroll
        for (int mt = 0; mt < 2; mt++)
#pragma unroll
            for (int h = 0; h < 2; h++)
                eu4[mt][h] = eua[wm + mt * 16 + (lane >> 2) + h * 8];
    }

    float ls[2][2] = {{0.f, 0.f}, {0.f, 0.f}};
    float cp[8][2];
#pragma unroll
    for (int nt = 0; nt < 8; nt++) { cp[nt][0] = 0.f; cp[nt][1] = 0.f; }

#pragma unroll
    for (int mt = 0; mt < 2; mt++)
#pragma unroll
        for (int nt = 0; nt < 8; nt++) {
            int colb = wn + nt * 8 + 2 * (lane & 3);
#pragma unroll
            for (int rg = 0; rg < 4; rg++) {
                float e = ex2(sa[mt][nt][rg]);   // SS2 folded into A operand
                int h = rg >> 1, d = rg & 1;
                if (MODE == 0) {
                    ls[mt][h] += e;
                    cp[nt][d] += e;
                } else {
                    ls[mt][h] += eub[colb + d] * e;
                    cp[nt][d] += eu4[mt][h] * e;
                }
            }
        }

#pragma unroll
    for (int mt = 0; mt < 2; mt++)
#pragma unroll
        for (int h = 0; h < 2; h++) {
            float v = ls[mt][h];
            v += __shfl_xor_sync(0xffffffffu, v, 1);
            v += __shfl_xor_sync(0xffffffffu, v, 2);
            if ((lane & 3) == 0)
                ps[w2 * 128 + wm + mt * 16 + (lane >> 2) + h * 8] = v;
        }

#pragma unroll
    for (int nt = 0; nt < 8; nt++)
#pragma unroll
        for (int d = 0; d < 2; d++) {
            float v = cp[nt][d];
            v += __shfl_xor_sync(0xffffffffu, v, 4);
            v += __shfl_xor_sync(0xffffffffu, v, 8);
            v += __shfl_xor_sync(0xffffffffu, v, 16);
            cp[nt][d] = v;
        }
    if (lane < 4) {
#pragma unroll
        for (int nt = 0; nt < 8; nt++) {
            csh[mw][wn + nt * 8 + 2 * lane + 0] = cp[nt][0];
            csh[mw][wn + nt * 8 + 2 * lane + 1] = cp[nt][1];
        }
    }
    __syncthreads();

    float* dst = (MODE == 0) ? g_part : g_part2;
    if (tid < 128) {
        if (MODE == 0 || a != b) {
            float rs = ps[tid] + ps[128 + tid];
            dst[((size_t)bh * 8 + b) * NSEQ + a * 128 + tid] = rs;
        }
        if (MODE == 1 || a != b) {
            float cs = csh[0][tid] + csh[1][tid] + csh[2][tid] + csh[3][tid];
            dst[((size_t)bh * 8 + a) * NSEQ + b * 128 + tid] = cs;
        }
    }
}

// ---------------------------------------------------------------------------
// Pass C: O_ = Q_ + (1024 * exp(S + u_i + v_j)) @ Q_.
// u kept in fp32 (row-coherent); v rounded fp16 (column errors average out);
// ex2.approx.f16x2 halves MUFU. 8 warps x 16 rows; phase-1 C-fragments
// packed in registers as phase-2 A-fragments.
// ---------------------------------------------------------------------------
__global__ void __launch_bounds__(256, 2) sink_av_kernel() {
    extern __shared__ __align__(16) char smraw[];
    __half* Qi = (__half*)smraw;                 // 128*72
    __half* QjA = Qi + 9216;                     // 128*72 (buf 0)
    __half* QjB = QjA + 9216;                    // 128*72 (buf 1)
    float* vb = (float*)(QjB + 9216);            // 2 x 128 (log2 units)

    const int bh = blockIdx.y;
    const int i0 = blockIdx.x * 128;
    const int tid = threadIdx.x, lane = tid & 31, w = tid >> 5;
    const int wm = w * 16;
    const __half* Qb = g_Qh16 + (size_t)bh * (NSEQ * DHEAD);
    const float* Qf32 = g_Qh + (size_t)bh * (NSEQ * DHEAD);
    float* Obase = g_Oh + (size_t)bh * (NSEQ * DHEAD);
    __half* Qbuf[2] = { QjA, QjB };

#pragma unroll
    for (int r = 0; r < 4; r++) {
        int idx = tid + r * 256;
        int row = idx >> 3, q = (idx & 7) * 8;
        *(float4*)(Qi + row * 72 + q) =
            *(const float4*)(Qb + (size_t)(i0 + row) * DHEAD + q);
    }
#pragma unroll
    for (int r = 0; r < 4; r++) {
        int idx = tid + r * 256;
        int row = idx >> 3, q = (idx & 7) * 8;
        cpa16(smaddr(QjA + row * 72 + q), Qb + (size_t)row * DHEAD + q);
    }
    if (tid < 128) {
        float s = 0.f;
#pragma unroll
        for (int k = 0; k < 8; k++)
            s += g_part2[((size_t)bh * 8 + k) * NSEQ + tid];
        vb[tid] = (LOGMU - __logf(s)) * LOG2E;
    }
    cpa_commit();

    // per-thread row biases in log2 units, 1024 folded in (+10), fp32
    float r0s = 0.f, r1s = 0.f;
#pragma unroll
    for (int k = 0; k < 8; k++) {
        r0s += g_part[((size_t)bh * 8 + k) * NSEQ + i0 + wm + (lane >> 2)];
        r1s += g_part[((size_t)bh * 8 + k) * NSEQ + i0 + wm + (lane >> 2) + 8];
    }
    const float u0 = (LOGMU - __logf(r0s)) * LOG2E + 10.f;
    const float u1 = (LOGMU - __logf(r1s)) * LOG2E + 10.f;
    __syncthreads();

    unsigned af[4][4];
#pragma unroll
    for (int kk = 0; kk < 4; kk++)
        ldm_x4(af[kk], smaddr(Qi + (wm + (lane & 15)) * 72 + kk * 16 + (lane >> 4) * 8));

    float oa[8][4];
#pragma unroll
    for (int y = 0; y < 8; y++)
#pragma unroll
        for (int z = 0; z < 4; z++) oa[y][z] = 0.f;

    for (int jt = 0; jt < 8; jt++) {
        __syncthreads();
        if (jt < 7) {
            int j0 = (jt + 1) * 128, buf = (jt + 1) & 1;
#pragma unroll
            for (int r = 0; r < 4; r++) {
                int idx = tid + r * 256;
                int row = idx >> 3, q = (idx & 7) * 8;
                cpa16(smaddr(Qbuf[buf] + row * 72 + q),
                      Qb + (size_t)(j0 + row) * DHEAD + q);
            }
            if (tid < 128) {
                float s = 0.f;
#pragma unroll
                for (int k = 0; k < 8; k++)
                    s += g_part2[((size_t)bh * 8 + k) * NSEQ + j0 + tid];
                vb[buf * 128 + tid] = (LOGMU - __logf(s)) * LOG2E;
            }
            cpa_commit();
            cpa_wait<1>();
        } else {
            cpa_wait<0>();
        }
        __syncthreads();

        const __half* Qc = Qbuf[jt & 1];
        const float* vv = vb + (jt & 1) * 128;

#pragma unroll
        for (int h = 0; h < 2; h++) {
            const int jb = h * 64;
            float sa[8][4];
#pragma unroll
            for (int y = 0; y < 8; y++)
#pragma unroll
                for (int z = 0; z < 4; z++) sa[y][z] = 0.f;

#pragma unroll
            for (int kk = 0; kk < 4; kk++) {
#pragma unroll
                for (int nb = 0; nb < 4; nb++) {
                    unsigned bq[4];
                    ldm_x4(bq, smaddr(Qc + (jb + nb * 16 + ((lane >> 4) & 1) * 8 + (lane & 7)) * 72 +
                                      kk * 16 + ((lane >> 3) & 1) * 8));
                    mma16h(sa[2 * nb], af[kk], bq);
                    mma16h(sa[2 * nb + 1], af[kk], bq + 2);
                }
            }

            unsigned ak[4][4];
#pragma unroll
            for (int s2 = 0; s2 < 4; s2++) {
                const float* s0 = sa[2 * s2];
                const float* s1 = sa[2 * s2 + 1];
                int c0 = jb + s2 * 16 + 2 * (lane & 3);
                int c8 = c0 + 8;
                float2 v0p = *(const float2*)(vv + c0);
                float2 v8p = *(const float2*)(vv + c8);
                unsigned vh0 = fh2(v0p.x, v0p.y);
                unsigned vh8 = fh2(v8p.x, v8p.y);
                unsigned p00 = fh2(s0[0] * SS2 + u0, s0[1] * SS2 + u0);
                unsigned p01 = fh2(s0[2] * SS2 + u1, s0[3] * SS2 + u1);
                unsigned p80 = fh2(s1[0] * SS2 + u0, s1[1] * SS2 + u0);
                unsigned p81 = fh2(s1[2] * SS2 + u1, s1[3] * SS2 + u1);
                ak[s2][0] = h2ex2(hadd2u(p00, vh0));
                ak[s2][1] = h2ex2(hadd2u(p01, vh0));
                ak[s2][2] = h2ex2(hadd2u(p80, vh8));
                ak[s2][3] = h2ex2(hadd2u(p81, vh8));
            }

#pragma unroll
            for (int s2 = 0; s2 < 4; s2++) {
#pragma unroll
                for (int nb = 0; nb < 4; nb++) {
                    unsigned bq[4];
                    ldm_x4t(bq, smaddr(Qc + (jb + s2 * 16 + (lane & 15)) * 72 +
                                       nb * 16 + ((lane >> 4) & 1) * 8));
                    mma16h(oa[2 * nb], ak[s2], bq);
                    mma16h(oa[2 * nb + 1], ak[s2], bq + 2);
                }
            }
        }
    }

    // epilogue: O_ = Q_ + accum, vectorized float2 loads/stores
#pragma unroll
    for (int nt = 0; nt < 8; nt++) {
        int row = i0 + wm + (lane >> 2);
        int col = nt * 8 + 2 * (lane & 3);
        float2 q0 = *(const float2*)(Qf32 + (size_t)row * DHEAD + col);
        float2 o0 = { oa[nt][0] + q0.x, oa[nt][1] + q0.y };
        *(float2*)(Obase + (size_t)row * DHEAD + col) = o0;
        int row8 = row + 8;
        float2 q1 = *(const float2*)(Qf32 + (size_t)row8 * DHEAD + col);
        float2 o1 = { oa[nt][2] + q1.x, oa[nt][3] + q1.y };
        *(float2*)(Obase + (size_t)row8 * DHEAD + col) = o1;
    }
}

// ---------------------------------------------------------------------------
// fp16 GEMM, cp.async double-buffered, BK=64: C[8192,512] = A * W^T (+bias)
// MODE 0: A = g_A16; scatter head-major into g_Qh + g_Qh16 (vectorized)
// MODE 1: A = g_X16; g_T = g_X + relu(C + bias) (vectorized)
// ---------------------------------------------------------------------------
template <int MODE>
__global__ void __launch_bounds__(256, 2) gemm512h(const float* __restrict__ bias) {
    __shared__ __align__(16) __half As[2][128 * 72];
    __shared__ __align__(16) __half Bs[2][128 * 72];
    const __half* A16 = MODE ? g_X16 : g_A16;
    const __half* W16 = MODE ? g_W16o : g_W16q;

    const int m0 = blockIdx.y * 128, n0 = blockIdx.x * 128;
    const int tid = threadIdx.x, lane = tid & 31, w = tid >> 5;
    const int wm = (w & 3) * 32, wn = (w >> 2) * 64;

    float acc[2][8][4];
#pragma unroll
    for (int x = 0; x < 2; x++)
#pragma unroll
        for (int y = 0; y < 8; y++)
#pragma unroll
            for (int z = 0; z < 4; z++) acc[x][y][z] = 0.f;

#pragma unroll
    for (int c = 0; c < 4; c++) {
        int idx = tid + c * 256;
        int row = idx >> 3, ch = (idx & 7) * 8;
        cpa16(smaddr(&As[0][row * 72 + ch]), A16 + (size_t)(m0 + row) * 512 + ch);
        cpa16(smaddr(&Bs[0][row * 72 + ch]), W16 + (size_t)(n0 + row) * 512 + ch);
    }
    cpa_commit();

    for (int kt = 0; kt < 8; kt++) {
        __syncthreads();
        if (kt < 7) {
            int s = (kt + 1) & 1, k0 = (kt + 1) * 64;
#pragma unroll
            for (int c = 0; c < 4; c++) {
                int idx = tid + c * 256;
                int row = idx >> 3, ch = (idx & 7) * 8;
                cpa16(smaddr(&As[s][row * 72 + ch]), A16 + (size_t)(m0 + row) * 512 + k0 + ch);
                cpa16(smaddr(&Bs[s][row * 72 + ch]), W16 + (size_t)(n0 + row) * 512 + k0 + ch);
            }
            cpa_commit();
            cpa_wait<1>();
        } else {
            cpa_wait<0>();
        }
        __syncthreads();

        const __half* as = As[kt & 1];
        const __half* bs = Bs[kt & 1];
#pragma unroll
        for (int kk = 0; kk < 4; kk++) {
            unsigned af[2][4];
#pragma unroll
            for (int mt = 0; mt < 2; mt++)
                ldm_x4(af[mt], smaddr(as + (wm + mt * 16 + (lane & 15)) * 72 +
                                      kk * 16 + (lane >> 4) * 8));
#pragma unroll
            for (int nb = 0; nb < 4; nb++) {
                unsigned bq[4];
                ldm_x4(bq, smaddr(bs + (wn + nb * 16 + ((lane >> 4) & 1) * 8 + (lane & 7)) * 72 +
                                  kk * 16 + ((lane >> 3) & 1) * 8));
                mma16h(acc[0][2 * nb], af[0], bq);
                mma16h(acc[1][2 * nb], af[1], bq);
                mma16h(acc[0][2 * nb + 1], af[0], bq + 2);
                mma16h(acc[1][2 * nb + 1], af[1], bq + 2);
            }
        }
    }

#pragma unroll
    for (int mt = 0; mt < 2; mt++)
#pragma unroll
        for (int nt = 0; nt < 8; nt++) {
            int row = m0 + wm + mt * 16 + (lane >> 2);
            int col = n0 + wn + nt * 8 + 2 * (lane & 3);
            float b0 = bias[col], b1 = bias[col + 1];
#pragma unroll
            for (int hh = 0; hh < 2; hh++) {
                int rr = row + hh * 8;
                float v0 = acc[mt][nt][2 * hh] + b0;
                float v1 = acc[mt][nt][2 * hh + 1] + b1;
                if (MODE == 0) {
                    int b = rr >> 10, i = rr & 1023;
                    int h = col >> 6, dc = col & 63;
                    size_t idx = ((size_t)((h << 3) + b) * NSEQ + i) * DHEAD + dc;
                    *(float2*)(g_Qh + idx) = make_float2(v0, v1);
                    *(unsigned*)((__half*)g_Qh16 + idx) = fh2(v0, v1);
                } else {
                    float2 x = *(const float2*)(g_X + (size_t)rr * 512 + col);
                    float2 t = { fmaxf(v0, 0.f) + x.x, fmaxf(v1, 0.f) + x.y };
                    *(float2*)(g_T + (size_t)rr * 512 + col) = t;
                }
            }
        }
}

// ---------------------------------------------------------------------------
// LayerNorm. mode 0: merge heads g_Oh -> LN -> g_X (+ g_X16)
//            mode 1: g_T -> LN -> out
// ---------------------------------------------------------------------------
__global__ void __launch_bounds__(512) ln_kernel(const float* __restrict__ gg,
                                                 const float* __restrict__ bb,
                                                 float* __restrict__ out, int mode) {
    int m = blockIdx.x;
    int t = threadIdx.x;
    float val;
    if (mode == 0) {
        int b = m >> 10, i = m & 1023, h = t >> 6, dc = t & 63;
        val = g_Oh[(((h << 3) + b) * NSEQ + i) * DHEAD + dc];
    } else {
        val = g_T[(size_t)m * 512 + t];
    }
    float s = val, q = val * val;
#pragma unroll
    for (int off = 16; off; off >>= 1) {
        s += __shfl_xor_sync(0xffffffffu, s, off);
        q += __shfl_xor_sync(0xffffffffu, q, off);
    }
    __shared__ float ss[16], sq[16];
    int w = t >> 5, lane = t & 31;
    if (!lane) { ss[w] = s; sq[w] = q; }
    __syncthreads();
    float S = 0.f, Q2 = 0.f;
#pragma unroll
    for (int k = 0; k < 16; k++) { S += ss[k]; Q2 += sq[k]; }
    float mean = S * (1.f / 512.f);
    float var = Q2 * (1.f / 512.f) - mean * mean;
    float y = (val - mean) * rsqrtf(var + 1e-5f) * gg[t] + bb[t];
    if (mode == 0) {
        g_X[(size_t)m * 512 + t] = y;
        g_X16[(size_t)m * 512 + t] = __float2half_rn(y);
    } else {
        out[(size_t)m * 512 + t] = y;
    }
}

// ---------------------------------------------------------------------------
extern "C" void kernel_launch(void* const* d_in, const int* in_sizes, int n_in,
                              void* d_out, int out_size) {
    (void)in_sizes; (void)n_in; (void)out_size;
    const float* Q  = (const float*)d_in[0];
    // d_in[1] = K, unused by the reference forward
    const float* Wq = (const float*)d_in[2];
    const float* bq = (const float*)d_in[3];
    const float* Wo = (const float*)d_in[4];
    const float* bo = (const float*)d_in[5];
    const float* g0 = (const float*)d_in[6];
    const float* b0 = (const float*)d_in[7];
    const float* g1 = (const float*)d_in[8];
    const float* b1 = (const float*)d_in[9];
    float* out = (float*)d_out;

    const int SMEM_AV = 9216 * 3 * 2 + 256 * 4;  // 56320 B
    cudaFuncSetAttribute(sink_av_kernel,
                         cudaFuncAttributeMaxDynamicSharedMemorySize, SMEM_AV);

    dim3 ggrid(4, 64);    // N/128, M/128
    dim3 sgrid(36, 64);   // triangular tile pairs, bh
    dim3 agrid(8, 64);    // row-blocks, bh

    cvt_kernel<<<2304, 256>>>(Q, Wq, Wo);
    gemm512h<0><<<ggrid, 256>>>(bq);
    sym_lse<0><<<sgrid, 256>>>();
    sym_lse<1><<<sgrid, 256>>>();
    sink_av_kernel<<<agrid, 256, SMEM_AV>>>();
    ln_kernel<<<8192, 512>>>(g0, b0, nullptr, 0);
    gemm512h<1><<<ggrid, 256>>>(bo);
    ln_kernel<<<8192, 512>>>(g1, b1, out, 1);
}

// round 11
// speedup vs baseline: 2.2058x; 1.1837x over previous
#include <cuda_runtime.h>
#include <cuda_fp16.h>
#include <math.h>
#include <stdint.h>

// Problem constants: B=8, n=1024, dQ=dV=512, H=8, d=64, HB=64
#define NSEQ   1024
#define DHEAD  64
#define DVTOT  512
#define NBATCH 8
#define NHB    64

#define SSCALE 0.044194173824159216f   // 1/sqrt(512)
#define LOG2E  1.4426950408889634f
#define SS2    (SSCALE * LOG2E)        // exp(s*SSCALE) = ex2(s*SS2)
#define LOGMU  (-6.9314615657f)        // log(1/1024 + 1e-8)
#define MUVAL  (0.0009765725f)         // 1/1024 + 1e-8

// Scratch (device globals; no allocation allowed)
__device__ float  g_Qh [NHB * NSEQ * DHEAD];   // head-major Q_ fp32 (residual)
__device__ __half g_Qh16[NHB * NSEQ * DHEAD];  // head-major Q_ fp16 (mma operand)
__device__ float  g_Oh [NBATCH * NSEQ * DVTOT]; // O_ in merged (b,i,512) layout
__device__ float  g_X  [NBATCH * NSEQ * DVTOT];
__device__ __half g_X16[NBATCH * NSEQ * DVTOT];
__device__ float  g_T  [NBATCH * NSEQ * DVTOT];
__device__ __half g_A16[NBATCH * NSEQ * DVTOT];  // fp16 Q input
__device__ __half g_W16q[DVTOT * DVTOT];
__device__ __half g_W16o[DVTOT * DVTOT];
// partial sums: g_part (pass 0, row/col sums of P) ; g_part2 (pass 1, for v)
__device__ float  g_part [NHB * 8 * NSEQ];
__device__ float  g_part2[NHB * 8 * NSEQ];

// ---------------------------------------------------------------------------
// helpers
// ---------------------------------------------------------------------------
__device__ __forceinline__ void mma16h(float* c, const unsigned* a, const unsigned* b) {
    asm volatile(
        "mma.sync.aligned.m16n8k16.row.col.f32.f16.f16.f32 "
        "{%0,%1,%2,%3},{%4,%5,%6,%7},{%8,%9},{%0,%1,%2,%3};\n"
        : "+f"(c[0]), "+f"(c[1]), "+f"(c[2]), "+f"(c[3])
        : "r"(a[0]), "r"(a[1]), "r"(a[2]), "r"(a[3]), "r"(b[0]), "r"(b[1]));
}
__device__ __forceinline__ unsigned smaddr(const void* p) {
    return (unsigned)__cvta_generic_to_shared(p);
}
__device__ __forceinline__ void ldm_x4(unsigned* r, unsigned a) {
    asm volatile("ldmatrix.sync.aligned.m8n8.x4.shared.b16 {%0,%1,%2,%3},[%4];"
                 : "=r"(r[0]), "=r"(r[1]), "=r"(r[2]), "=r"(r[3]) : "r"(a));
}
__device__ __forceinline__ void ldm_x4t(unsigned* r, unsigned a) {
    asm volatile("ldmatrix.sync.aligned.m8n8.x4.trans.shared.b16 {%0,%1,%2,%3},[%4];"
                 : "=r"(r[0]), "=r"(r[1]), "=r"(r[2]), "=r"(r[3]) : "r"(a));
}
__device__ __forceinline__ unsigned fh2(float a, float b) {
    __half2 h = __floats2half2_rn(a, b);
    return *(unsigned*)&h;
}
__device__ __forceinline__ unsigned hmul2u(unsigned a, unsigned b) {
    __half2 r = __hmul2(*(const __half2*)&a, *(const __half2*)&b);
    return *(unsigned*)&r;
}
__device__ __forceinline__ unsigned hadd2u(unsigned a, unsigned b) {
    __half2 r = __hadd2(*(const __half2*)&a, *(const __half2*)&b);
    return *(unsigned*)&r;
}
__device__ __forceinline__ float ex2(float x) {
    float r;
    asm("ex2.approx.ftz.f32 %0, %1;" : "=f"(r) : "f"(x));
    return r;
}
__device__ __forceinline__ unsigned h2ex2(unsigned x) {
    unsigned r;
    asm("ex2.approx.f16x2 %0, %1;" : "=r"(r) : "r"(x));
    return r;
}
__device__ __forceinline__ void cpa16(unsigned s, const void* g) {
    asm volatile("cp.async.ca.shared.global [%0], [%1], 16;" :: "r"(s), "l"(g) : "memory");
}
__device__ __forceinline__ void cpa_commit() {
    asm volatile("cp.async.commit_group;" ::: "memory");
}
template <int N>
__device__ __forceinline__ void cpa_wait() {
    asm volatile("cp.async.wait_group %0;" :: "n"(N) : "memory");
}

// ---------------------------------------------------------------------------
// fp32 -> fp16 conversion for GEMM operands (Q, Wq, Wo). One launch.
// ---------------------------------------------------------------------------
__global__ void __launch_bounds__(256) cvt_kernel(const float* __restrict__ Q,
                                                  const float* __restrict__ Wq,
                                                  const float* __restrict__ Wo) {
    size_t t = ((size_t)blockIdx.x * 256 + threadIdx.x) * 8;
    const float* src;
    __half* dst;
    size_t off;
    if (t < 4194304) { src = Q;  dst = g_A16;  off = t; }
    else if (t < 4456448) { src = Wq; dst = g_W16q; off = t - 4194304; }
    else { src = Wo; dst = g_W16o; off = t - 4456448; }
    float4 a = *(const float4*)(src + off);
    float4 b = *(const float4*)(src + off + 4);
    uint4 p;
    p.x = fh2(a.x, a.y); p.y = fh2(a.z, a.w);
    p.z = fh2(b.x, b.y); p.w = fh2(b.z, b.w);
    *(uint4*)(dst + off) = p;
}

// ---------------------------------------------------------------------------
// Symmetric-tile LSE pass. One CTA per (a,b), a<=b (36 pairs x 64 bh).
// Restructured for 3 CTAs/SM: warp tile processed in two 32-col halves,
// cutting live registers (sa 64->32, cp 16->8). Qi frags prescaled by SS2.
// MODE 0: partials of rowsum/colsum of P -> g_part
// MODE 1: e^u from g_part; weighted partials for v -> g_part2
// ---------------------------------------------------------------------------
template <int MODE>
__global__ void __launch_bounds__(256, 3) sym_lse() {
    __shared__ __align__(16) __half Qi[128 * 72];
    __shared__ __align__(16) __half Qj[128 * 72];
    __shared__ float csh[4][128];
    __shared__ float ps[256];
    __shared__ float eua[128], eub[128];

    const int bh = blockIdx.y;
    int a = 0, tt = blockIdx.x;
    while (tt >= 8 - a) { tt -= 8 - a; a++; }
    const int b = a + tt;

    const int tid = threadIdx.x, lane = tid & 31, w = tid >> 5;
    const int mw = w & 3, w2 = w >> 2;
    const int wm = mw * 32, wn = w2 * 64;
    const __half* Qb = g_Qh16 + (size_t)bh * (NSEQ * DHEAD);
    const unsigned HSS2 = fh2(SS2, SS2);

#pragma unroll
    for (int r = 0; r < 4; r++) {
        int idx = tid + r * 256;
        int row = idx >> 3, q = (idx & 7) * 8;
        cpa16(smaddr(Qi + row * 72 + q), Qb + (size_t)(a * 128 + row) * DHEAD + q);
        cpa16(smaddr(Qj + row * 72 + q), Qb + (size_t)(b * 128 + row) * DHEAD + q);
    }
    if (MODE == 1 && tid < 128) {
        float sa_ = 0.f, sb_ = 0.f;
#pragma unroll
        for (int k = 0; k < 8; k++) {
            sa_ += g_part[((size_t)bh * 8 + k) * NSEQ + a * 128 + tid];
            sb_ += g_part[((size_t)bh * 8 + k) * NSEQ + b * 128 + tid];
        }
        eua[tid] = MUVAL / sa_;
        eub[tid] = MUVAL / sb_;
    }
    cpa_commit();
    cpa_wait<0>();
    __syncthreads();

    float eu4[2][2];
    if (MODE == 1) {
#pragma unroll
        for (int mt = 0; mt < 2; mt++)
#pragma unroll
            for (int h = 0; h < 2; h++)
                eu4[mt][h] = eua[wm + mt * 16 + (lane >> 2) + h * 8];
    }

    float ls[2][2] = {{0.f, 0.f}, {0.f, 0.f}};

#pragma unroll
    for (int nh = 0; nh < 2; nh++) {
        const int wnh = wn + nh * 32;

        float sa[2][4][4];
#pragma unroll
        for (int x = 0; x < 2; x++)
#pragma unroll
            for (int y = 0; y < 4; y++)
#pragma unroll
                for (int z = 0; z < 4; z++) sa[x][y][z] = 0.f;

#pragma unroll
        for (int kk = 0; kk < 4; kk++) {
            unsigned af0[4], af1[4];
            {
                int col = kk * 16 + (lane >> 4) * 8;
                ldm_x4(af0, smaddr(Qi + (wm + (lane & 15)) * 72 + col));
                ldm_x4(af1, smaddr(Qi + (wm + 16 + (lane & 15)) * 72 + col));
#pragma unroll
                for (int r = 0; r < 4; r++) {
                    af0[r] = hmul2u(af0[r], HSS2);
                    af1[r] = hmul2u(af1[r], HSS2);
                }
            }
#pragma unroll
            for (int nb = 0; nb < 2; nb++) {
                unsigned bq[4];
                ldm_x4(bq, smaddr(Qj + (wnh + nb * 16 + ((lane >> 4) & 1) * 8 + (lane & 7)) * 72 +
                                  kk * 16 + ((lane >> 3) & 1) * 8));
                mma16h(sa[0][2 * nb], af0, bq);
                mma16h(sa[1][2 * nb], af1, bq);
                mma16h(sa[0][2 * nb + 1], af0, bq + 2);
                mma16h(sa[1][2 * nb + 1], af1, bq + 2);
            }
        }

        float cp[4][2];
#pragma unroll
        for (int nt = 0; nt < 4; nt++) { cp[nt][0] = 0.f; cp[nt][1] = 0.f; }

#pragma unroll
        for (int mt = 0; mt < 2; mt++)
#pragma unroll
            for (int nt = 0; nt < 4; nt++) {
                int colb = wnh + nt * 8 + 2 * (lane & 3);
#pragma unroll
                for (int rg = 0; rg < 4; rg++) {
                    float e = ex2(sa[mt][nt][rg]);   // SS2 folded into A
                    int h = rg >> 1, d = rg & 1;
                    if (MODE == 0) {
                        ls[mt][h] += e;
                        cp[nt][d] += e;
                    } else {
                        ls[mt][h] += eub[colb + d] * e;
                        cp[nt][d] += eu4[mt][h] * e;
                    }
                }
            }

        // col-sum reduction for this half
#pragma unroll
        for (int nt = 0; nt < 4; nt++)
#pragma unroll
            for (int d = 0; d < 2; d++) {
                float v = cp[nt][d];
                v += __shfl_xor_sync(0xffffffffu, v, 4);
                v += __shfl_xor_sync(0xffffffffu, v, 8);
                v += __shfl_xor_sync(0xffffffffu, v, 16);
                cp[nt][d] = v;
            }
        if (lane < 4) {
#pragma unroll
            for (int nt = 0; nt < 4; nt++) {
                csh[mw][wnh + nt * 8 + 2 * lane + 0] = cp[nt][0];
                csh[mw][wnh + nt * 8 + 2 * lane + 1] = cp[nt][1];
            }
        }
    }

    // row-sum reduction
#pragma unroll
    for (int mt = 0; mt < 2; mt++)
#pragma unroll
        for (int h = 0; h < 2; h++) {
            float v = ls[mt][h];
            v += __shfl_xor_sync(0xffffffffu, v, 1);
            v += __shfl_xor_sync(0xffffffffu, v, 2);
            if ((lane & 3) == 0)
                ps[w2 * 128 + wm + mt * 16 + (lane >> 2) + h * 8] = v;
        }
    __syncthreads();

    float* dst = (MODE == 0) ? g_part : g_part2;
    if (tid < 128) {
        if (MODE == 0 || a != b) {
            float rs = ps[tid] + ps[128 + tid];
            dst[((size_t)bh * 8 + b) * NSEQ + a * 128 + tid] = rs;
        }
        if (MODE == 1 || a != b) {
            float cs = csh[0][tid] + csh[1][tid] + csh[2][tid] + csh[3][tid];
            dst[((size_t)bh * 8 + a) * NSEQ + b * 128 + tid] = cs;
        }
    }
}

// ---------------------------------------------------------------------------
// Pass C: O_ = Q_ + (1024 * exp(S + u_i + v_j)) @ Q_.
// u fp32 (row-coherent); v fp16 (column errors average); ex2.f16x2.
// O written in merged (b, i, h*64+d) layout for coalesced LN.
// ---------------------------------------------------------------------------
__global__ void __launch_bounds__(256, 2) sink_av_kernel() {
    extern __shared__ __align__(16) char smraw[];
    __half* Qi = (__half*)smraw;                 // 128*72
    __half* QjA = Qi + 9216;                     // 128*72 (buf 0)
    __half* QjB = QjA + 9216;                    // 128*72 (buf 1)
    float* vb = (float*)(QjB + 9216);            // 2 x 128 (log2 units)

    const int bh = blockIdx.y;
    const int i0 = blockIdx.x * 128;
    const int tid = threadIdx.x, lane = tid & 31, w = tid >> 5;
    const int wm = w * 16;
    const __half* Qb = g_Qh16 + (size_t)bh * (NSEQ * DHEAD);
    const float* Qf32 = g_Qh + (size_t)bh * (NSEQ * DHEAD);
    __half* Qbuf[2] = { QjA, QjB };
    const int bb = bh & 7, hh2 = bh >> 3;        // batch, head

#pragma unroll
    for (int r = 0; r < 4; r++) {
        int idx = tid + r * 256;
        int row = idx >> 3, q = (idx & 7) * 8;
        *(float4*)(Qi + row * 72 + q) =
            *(const float4*)(Qb + (size_t)(i0 + row) * DHEAD + q);
    }
#pragma unroll
    for (int r = 0; r < 4; r++) {
        int idx = tid + r * 256;
        int row = idx >> 3, q = (idx & 7) * 8;
        cpa16(smaddr(QjA + row * 72 + q), Qb + (size_t)row * DHEAD + q);
    }
    if (tid < 128) {
        float s = 0.f;
#pragma unroll
        for (int k = 0; k < 8; k++)
            s += g_part2[((size_t)bh * 8 + k) * NSEQ + tid];
        vb[tid] = (LOGMU - __logf(s)) * LOG2E;
    }
    cpa_commit();

    float r0s = 0.f, r1s = 0.f;
#pragma unroll
    for (int k = 0; k < 8; k++) {
        r0s += g_part[((size_t)bh * 8 + k) * NSEQ + i0 + wm + (lane >> 2)];
        r1s += g_part[((size_t)bh * 8 + k) * NSEQ + i0 + wm + (lane >> 2) + 8];
    }
    const float u0 = (LOGMU - __logf(r0s)) * LOG2E + 10.f;
    const float u1 = (LOGMU - __logf(r1s)) * LOG2E + 10.f;
    __syncthreads();

    unsigned af[4][4];
#pragma unroll
    for (int kk = 0; kk < 4; kk++)
        ldm_x4(af[kk], smaddr(Qi + (wm + (lane & 15)) * 72 + kk * 16 + (lane >> 4) * 8));

    float oa[8][4];
#pragma unroll
    for (int y = 0; y < 8; y++)
#pragma unroll
        for (int z = 0; z < 4; z++) oa[y][z] = 0.f;

    for (int jt = 0; jt < 8; jt++) {
        __syncthreads();
        if (jt < 7) {
            int j0 = (jt + 1) * 128, buf = (jt + 1) & 1;
#pragma unroll
            for (int r = 0; r < 4; r++) {
                int idx = tid + r * 256;
                int row = idx >> 3, q = (idx & 7) * 8;
                cpa16(smaddr(Qbuf[buf] + row * 72 + q),
                      Qb + (size_t)(j0 + row) * DHEAD + q);
            }
            if (tid < 128) {
                float s = 0.f;
#pragma unroll
                for (int k = 0; k < 8; k++)
                    s += g_part2[((size_t)bh * 8 + k) * NSEQ + j0 + tid];
                vb[buf * 128 + tid] = (LOGMU - __logf(s)) * LOG2E;
            }
            cpa_commit();
            cpa_wait<1>();
        } else {
            cpa_wait<0>();
        }
        __syncthreads();

        const __half* Qc = Qbuf[jt & 1];
        const float* vv = vb + (jt & 1) * 128;

#pragma unroll
        for (int h = 0; h < 2; h++) {
            const int jb = h * 64;
            float sa[8][4];
#pragma unroll
            for (int y = 0; y < 8; y++)
#pragma unroll
                for (int z = 0; z < 4; z++) sa[y][z] = 0.f;

#pragma unroll
            for (int kk = 0; kk < 4; kk++) {
#pragma unroll
                for (int nb = 0; nb < 4; nb++) {
                    unsigned bq[4];
                    ldm_x4(bq, smaddr(Qc + (jb + nb * 16 + ((lane >> 4) & 1) * 8 + (lane & 7)) * 72 +
                                      kk * 16 + ((lane >> 3) & 1) * 8));
                    mma16h(sa[2 * nb], af[kk], bq);
                    mma16h(sa[2 * nb + 1], af[kk], bq + 2);
                }
            }

            unsigned ak[4][4];
#pragma unroll
            for (int s2 = 0; s2 < 4; s2++) {
                const float* s0 = sa[2 * s2];
                const float* s1 = sa[2 * s2 + 1];
                int c0 = jb + s2 * 16 + 2 * (lane & 3);
                int c8 = c0 + 8;
                float2 v0p = *(const float2*)(vv + c0);
                float2 v8p = *(const float2*)(vv + c8);
                unsigned vh0 = fh2(v0p.x, v0p.y);
                unsigned vh8 = fh2(v8p.x, v8p.y);
                unsigned p00 = fh2(s0[0] * SS2 + u0, s0[1] * SS2 + u0);
                unsigned p01 = fh2(s0[2] * SS2 + u1, s0[3] * SS2 + u1);
                unsigned p80 = fh2(s1[0] * SS2 + u0, s1[1] * SS2 + u0);
                unsigned p81 = fh2(s1[2] * SS2 + u1, s1[3] * SS2 + u1);
                ak[s2][0] = h2ex2(hadd2u(p00, vh0));
                ak[s2][1] = h2ex2(hadd2u(p01, vh0));
                ak[s2][2] = h2ex2(hadd2u(p80, vh8));
                ak[s2][3] = h2ex2(hadd2u(p81, vh8));
            }

#pragma unroll
            for (int s2 = 0; s2 < 4; s2++) {
#pragma unroll
                for (int nb = 0; nb < 4; nb++) {
                    unsigned bq[4];
                    ldm_x4t(bq, smaddr(Qc + (jb + s2 * 16 + (lane & 15)) * 72 +
                                       nb * 16 + ((lane >> 4) & 1) * 8));
                    mma16h(oa[2 * nb], ak[s2], bq);
                    mma16h(oa[2 * nb + 1], ak[s2], bq + 2);
                }
            }
        }
    }

    // epilogue: O_ = Q_ + accum, merged (b,i,512) layout, float2 vectorized
#pragma unroll
    for (int nt = 0; nt < 8; nt++) {
        int ri = i0 + wm + (lane >> 2);
        int col = nt * 8 + 2 * (lane & 3);
        int gcol = hh2 * 64 + col;
        float2 q0 = *(const float2*)(Qf32 + (size_t)ri * DHEAD + col);
        float2 o0 = { oa[nt][0] + q0.x, oa[nt][1] + q0.y };
        *(float2*)(g_Oh + ((size_t)(bb * NSEQ + ri) * DVTOT) + gcol) = o0;
        int ri8 = ri + 8;
        float2 q1 = *(const float2*)(Qf32 + (size_t)ri8 * DHEAD + col);
        float2 o1 = { oa[nt][2] + q1.x, oa[nt][3] + q1.y };
        *(float2*)(g_Oh + ((size_t)(bb * NSEQ + ri8) * DVTOT) + gcol) = o1;
    }
}

// ---------------------------------------------------------------------------
// fp16 GEMM, cp.async double-buffered, BK=64: C[8192,512] = A * W^T (+bias)
// MODE 0: A = g_A16; scatter head-major into g_Qh + g_Qh16 (vectorized)
// MODE 1: A = g_X16; g_T = g_X + relu(C + bias) (vectorized)
// ---------------------------------------------------------------------------
template <int MODE>
__global__ void __launch_bounds__(256, 2) gemm512h(const float* __restrict__ bias) {
    __shared__ __align__(16) __half As[2][128 * 72];
    __shared__ __align__(16) __half Bs[2][128 * 72];
    const __half* A16 = MODE ? g_X16 : g_A16;
    const __half* W16 = MODE ? g_W16o : g_W16q;

    const int m0 = blockIdx.y * 128, n0 = blockIdx.x * 128;
    const int tid = threadIdx.x, lane = tid & 31, w = tid >> 5;
    const int wm = (w & 3) * 32, wn = (w >> 2) * 64;

    float acc[2][8][4];
#pragma unroll
    for (int x = 0; x < 2; x++)
#pragma unroll
        for (int y = 0; y < 8; y++)
#pragma unroll
            for (int z = 0; z < 4; z++) acc[x][y][z] = 0.f;

#pragma unroll
    for (int c = 0; c < 4; c++) {
        int idx = tid + c * 256;
        int row = idx >> 3, ch = (idx & 7) * 8;
        cpa16(smaddr(&As[0][row * 72 + ch]), A16 + (size_t)(m0 + row) * 512 + ch);
        cpa16(smaddr(&Bs[0][row * 72 + ch]), W16 + (size_t)(n0 + row) * 512 + ch);
    }
    cpa_commit();

    for (int kt = 0; kt < 8; kt++) {
        __syncthreads();
        if (kt < 7) {
            int s = (kt + 1) & 1, k0 = (kt + 1) * 64;
#pragma unroll
            for (int c = 0; c < 4; c++) {
                int idx = tid + c * 256;
                int row = idx >> 3, ch = (idx & 7) * 8;
                cpa16(smaddr(&As[s][row * 72 + ch]), A16 + (size_t)(m0 + row) * 512 + k0 + ch);
                cpa16(smaddr(&Bs[s][row * 72 + ch]), W16 + (size_t)(n0 + row) * 512 + k0 + ch);
            }
            cpa_commit();
            cpa_wait<1>();
        } else {
            cpa_wait<0>();
        }
        __syncthreads();

        const __half* as = As[kt & 1];
        const __half* bs = Bs[kt & 1];
#pragma unroll
        for (int kk = 0; kk < 4; kk++) {
            unsigned af[2][4];
#pragma unroll
            for (int mt = 0; mt < 2; mt++)
                ldm_x4(af[mt], smaddr(as + (wm + mt * 16 + (lane & 15)) * 72 +
                                      kk * 16 + (lane >> 4) * 8));
#pragma unroll
            for (int nb = 0; nb < 4; nb++) {
                unsigned bq[4];
                ldm_x4(bq, smaddr(bs + (wn + nb * 16 + ((lane >> 4) & 1) * 8 + (lane & 7)) * 72 +
                                  kk * 16 + ((lane >> 3) & 1) * 8));
                mma16h(acc[0][2 * nb], af[0], bq);
                mma16h(acc[1][2 * nb], af[1], bq);
                mma16h(acc[0][2 * nb + 1], af[0], bq + 2);
                mma16h(acc[1][2 * nb + 1], af[1], bq + 2);
            }
        }
    }

#pragma unroll
    for (int mt = 0; mt < 2; mt++)
#pragma unroll
        for (int nt = 0; nt < 8; nt++) {
            int row = m0 + wm + mt * 16 + (lane >> 2);
            int col = n0 + wn + nt * 8 + 2 * (lane & 3);
            float b0 = bias[col], b1 = bias[col + 1];
#pragma unroll
            for (int hh = 0; hh < 2; hh++) {
                int rr = row + hh * 8;
                float v0 = acc[mt][nt][2 * hh] + b0;
                float v1 = acc[mt][nt][2 * hh + 1] + b1;
                if (MODE == 0) {
                    int b = rr >> 10, i = rr & 1023;
                    int h = col >> 6, dc = col & 63;
                    size_t idx = ((size_t)((h << 3) + b) * NSEQ + i) * DHEAD + dc;
                    *(float2*)(g_Qh + idx) = make_float2(v0, v1);
                    *(unsigned*)((__half*)g_Qh16 + idx) = fh2(v0, v1);
                } else {
                    float2 x = *(const float2*)(g_X + (size_t)rr * 512 + col);
                    float2 t = { fmaxf(v0, 0.f) + x.x, fmaxf(v1, 0.f) + x.y };
                    *(float2*)(g_T + (size_t)rr * 512 + col) = t;
                }
            }
        }
}

// ---------------------------------------------------------------------------
// LayerNorm, vectorized: 128 threads x float4, one row per block.
// mode 0: g_Oh (merged) -> LN -> g_X (+ g_X16) ; mode 1: g_T -> LN -> out
// ---------------------------------------------------------------------------
__global__ void __launch_bounds__(128) ln_kernel(const float* __restrict__ gg,
                                                 const float* __restrict__ bb,
                                                 float* __restrict__ out, int mode) {
    const int m = blockIdx.x, t = threadIdx.x;
    const float* src = (mode == 0) ? g_Oh : g_T;
    float4 v = *(const float4*)(src + (size_t)m * 512 + t * 4);
    float s = v.x + v.y + v.z + v.w;
    float q = v.x * v.x + v.y * v.y + v.z * v.z + v.w * v.w;
#pragma unroll
    for (int off = 16; off; off >>= 1) {
        s += __shfl_xor_sync(0xffffffffu, s, off);
        q += __shfl_xor_sync(0xffffffffu, q, off);
    }
    __shared__ float ss[4], sq[4];
    int wr = t >> 5, lane = t & 31;
    if (!lane) { ss[wr] = s; sq[wr] = q; }
    __syncthreads();
    float S = ss[0] + ss[1] + ss[2] + ss[3];
    float Q2 = sq[0] + sq[1] + sq[2] + sq[3];
    float mean = S * (1.f / 512.f);
    float var = Q2 * (1.f / 512.f) - mean * mean;
    float rstd = rsqrtf(var + 1e-5f);
    float4 G = *(const float4*)(gg + t * 4);
    float4 Bv = *(const float4*)(bb + t * 4);
    float4 y;
    y.x = (v.x - mean) * rstd * G.x + Bv.x;
    y.y = (v.y - mean) * rstd * G.y + Bv.y;
    y.z = (v.z - mean) * rstd * G.z + Bv.z;
    y.w = (v.w - mean) * rstd * G.w + Bv.w;
    if (mode == 0) {
        *(float4*)(g_X + (size_t)m * 512 + t * 4) = y;
        uint2 hp;
        hp.x = fh2(y.x, y.y);
        hp.y = fh2(y.z, y.w);
        *(uint2*)(g_X16 + (size_t)m * 512 + t * 4) = hp;
    } else {
        *(float4*)(out + (size_t)m * 512 + t * 4) = y;
    }
}

// ---------------------------------------------------------------------------
extern "C" void kernel_launch(void* const* d_in, const int* in_sizes, int n_in,
                              void* d_out, int out_size) {
    (void)in_sizes; (void)n_in; (void)out_size;
    const float* Q  = (const float*)d_in[0];
    // d_in[1] = K, unused by the reference forward
    const float* Wq = (const float*)d_in[2];
    const float* bq = (const float*)d_in[3];
    const float* Wo = (const float*)d_in[4];
    const float* bo = (const float*)d_in[5];
    const float* g0 = (const float*)d_in[6];
    const float* b0 = (const float*)d_in[7];
    const float* g1 = (const float*)d_in[8];
    const float* b1 = (const float*)d_in[9];
    float* out = (float*)d_out;

    const int SMEM_AV = 9216 * 3 * 2 + 256 * 4;  // 56320 B
    cudaFuncSetAttribute(sink_av_kernel,
                         cudaFuncAttributeMaxDynamicSharedMemorySize, SMEM_AV);

    dim3 ggrid(4, 64);    // N/128, M/128
    dim3 sgrid(36, 64);   // triangular tile pairs, bh
    dim3 agrid(8, 64);    // row-blocks, bh

    cvt_kernel<<<2304, 256>>>(Q, Wq, Wo);
    gemm512h<0><<<ggrid, 256>>>(bq);
    sym_lse<0><<<sgrid, 256>>>();
    sym_lse<1><<<sgrid, 256>>>();
    sink_av_kernel<<<agrid, 256, SMEM_AV>>>();
    ln_kernel<<<8192, 128>>>(g0, b0, nullptr, 0);
    gemm512h<1><<<ggrid, 256>>>(bo);
    ln_kernel<<<8192, 128>>>(g1, b1, out, 1);
}